// round 10
// baseline (speedup 1.0000x reference)
#include <cuda_runtime.h>
#include <cstdint>

#define BATCH 2
#define SEQ 2048
#define DMODEL 1024
#define NH 16
#define HD 64
#define FEAT 16
#define FDIM 153           // 1 + 16 + 136
#define FPAD 160
#define NCHUNK 16
#define CHUNKSZ 128
#define ROWS (BATCH*SEQ)          // 4096
#define HROWS (BATCH*SEQ*NH)      // 131072

// ------------------------- scratch (static device memory) -------------------
__device__ float g_h[ROWS*DMODEL];
__device__ float g_q[ROWS*DMODEL];
__device__ float g_k[ROWS*DMODEL];
__device__ float g_v[ROWS*DMODEL];
__device__ float g_ckv2[(size_t)BATCH*NH*NCHUNK*2*FPAD*72];  // partial per half-chunk
__device__ float g_ckv[(size_t)BATCH*NH*NCHUNK*FPAD*72];     // exclusive prefix (col64=ksum)
__device__ float g_cat[(size_t)ROWS*2*DMODEL];

__device__ __forceinline__ void mma8(float acc[4], uint32_t a0, uint32_t a1,
                                     uint32_t a2, uint32_t a3,
                                     uint32_t b0, uint32_t b1) {
    asm volatile(
        "mma.sync.aligned.m16n8k8.row.col.f32.tf32.tf32.f32 "
        "{%0,%1,%2,%3}, {%4,%5,%6,%7}, {%8,%9}, {%0,%1,%2,%3};"
        : "+f"(acc[0]), "+f"(acc[1]), "+f"(acc[2]), "+f"(acc[3])
        : "r"(a0), "r"(a1), "r"(a2), "r"(a3), "r"(b0), "r"(b1));
}

__device__ __forceinline__ void cp16(uint32_t sdst, const float* gsrc) {
    asm volatile("cp.async.cg.shared.global [%0], [%1], 16;" :: "r"(sdst), "l"(gsrc));
}

// phi expansion: x[16] -> 160 features written dst[f*132 + tok] (raw fp32 bits)
__device__ __forceinline__ void write_phi_colmajor(uint32_t* dst, int tok, const float* xf) {
    float x[16];
    #pragma unroll
    for (int i = 0; i < 16; i++) x[i] = xf[i];
    dst[tok] = 0x3f800000u;
    #pragma unroll
    for (int i = 0; i < 16; i++) dst[(1 + i) * 132 + tok] = __float_as_uint(x[i]);
    const float inv = 0.70710678118654752440f;
    int idx = 17;
    #pragma unroll
    for (int i = 0; i < 16; i++) {
        dst[idx * 132 + tok] = __float_as_uint(0.5f * x[i] * x[i]); idx++;
        #pragma unroll
        for (int j = i + 1; j < 16; j++) {
            dst[idx * 132 + tok] = __float_as_uint(inv * x[i] * x[j]); idx++;
        }
    }
    #pragma unroll
    for (int f = FDIM; f < FPAD; f++) dst[f * 132 + tok] = 0u;
}

// half-split row-major phi write: h=0 does [1]+even quad rows+padding, h=1 linear+odd rows
__device__ __forceinline__ void write_phi_rowmajor_half(uint32_t* dst, const float* xf, int h) {
    float x[16];
    #pragma unroll
    for (int i = 0; i < 16; i++) x[i] = xf[i];
    const float inv = 0.70710678118654752440f;
    if (h == 0) {
        dst[0] = 0x3f800000u;
        #pragma unroll
        for (int i = 0; i < 16; i += 2) {
            int idx = 17 + i * 16 - (i * (i - 1)) / 2;
            dst[idx++] = __float_as_uint(0.5f * x[i] * x[i]);
            #pragma unroll
            for (int j = i + 1; j < 16; j++)
                dst[idx++] = __float_as_uint(inv * x[i] * x[j]);
        }
        #pragma unroll
        for (int f = FDIM; f < FPAD; f++) dst[f] = 0u;
    } else {
        #pragma unroll
        for (int i = 0; i < 16; i++) dst[1 + i] = __float_as_uint(x[i]);
        #pragma unroll
        for (int i = 1; i < 16; i += 2) {
            int idx = 17 + i * 16 - (i * (i - 1)) / 2;
            dst[idx++] = __float_as_uint(0.5f * x[i] * x[i]);
            #pragma unroll
            for (int j = i + 1; j < 16; j++)
                dst[idx++] = __float_as_uint(inv * x[i] * x[j]);
        }
    }
}

// ------------------------------- RMSNorm (float4) -----------------------------
__global__ void rmsnorm_kernel(const float* __restrict__ x,
                               const float* __restrict__ w,
                               float* __restrict__ h) {
    int row = blockIdx.x;
    const float4* xr = (const float4*)(x + (size_t)row * DMODEL);
    float4 t = xr[threadIdx.x];
    float s = t.x * t.x + t.y * t.y + t.z * t.z + t.w * t.w;
    __shared__ float red[8];
    #pragma unroll
    for (int o = 16; o > 0; o >>= 1) s += __shfl_xor_sync(0xffffffffu, s, o);
    if ((threadIdx.x & 31) == 0) red[threadIdx.x >> 5] = s;
    __syncthreads();
    if (threadIdx.x < 8) {
        float v = red[threadIdx.x];
        #pragma unroll
        for (int o = 4; o > 0; o >>= 1) v += __shfl_xor_sync(0xffu, v, o);
        if (threadIdx.x == 0) red[0] = v;
    }
    __syncthreads();
    float rs = rsqrtf(red[0] / (float)DMODEL + 1e-6f);
    float4 wv = ((const float4*)w)[threadIdx.x];
    float4 o;
    o.x = t.x * rs * wv.x; o.y = t.y * rs * wv.y;
    o.z = t.z * rs * wv.z; o.w = t.w * rs * wv.w;
    ((float4*)(h + (size_t)row * DMODEL))[threadIdx.x] = o;
}

// -------------- TF32 GEMM: cp.async 3-stage, k-tile 32, raw-bit tf32 ----------
#define AS_ELE (128*36)
#define BS_ELE (32*136)
#define NSTAGE 3

__device__ __forceinline__ void gemm_issue(const float* A, const float* B,
        float* As, float* Bs, int bm, int bn, int k0, int K, int N, int tid) {
    #pragma unroll
    for (int j = 0; j < 4; j++) {
        int c = tid + j * 256;
        int m = c >> 3, seg = c & 7;
        cp16((uint32_t)__cvta_generic_to_shared(As + m * 36 + seg * 4),
             A + (size_t)(bm + m) * K + k0 + seg * 4);
    }
    #pragma unroll
    for (int j = 0; j < 4; j++) {
        int c = tid + j * 256;
        int kk = c >> 5, nc = c & 31;
        cp16((uint32_t)__cvta_generic_to_shared(Bs + kk * 136 + nc * 4),
             B + (size_t)(k0 + kk) * N + bn + nc * 4);
    }
}

__device__ __forceinline__ void gemm_core(const float* A, const float* B, float* C,
        const float* residual, float* As, float* Bs, int bm, int bn, int K, int N,
        int tid) {
    int warp = tid >> 5, lane = tid & 31;
    int wm = (warp >> 2) * 64, wn = (warp & 3) * 32;
    int r = lane >> 2, cq = lane & 3;

    float acc[4][4][4];
    #pragma unroll
    for (int mi = 0; mi < 4; mi++)
        #pragma unroll
        for (int ni = 0; ni < 4; ni++)
            #pragma unroll
            for (int e = 0; e < 4; e++) acc[mi][ni][e] = 0.f;

    int nk = K / 32;
    gemm_issue(A, B, As, Bs, bm, bn, 0, K, N, tid);
    asm volatile("cp.async.commit_group;");
    gemm_issue(A, B, As + AS_ELE, Bs + BS_ELE, bm, bn, 32, K, N, tid);
    asm volatile("cp.async.commit_group;");

    for (int kt = 0; kt < nk; kt++) {
        if (kt + 2 < nk) {
            int slot = (kt + 2) % 3;
            gemm_issue(A, B, As + slot * AS_ELE, Bs + slot * BS_ELE,
                       bm, bn, (kt + 2) * 32, K, N, tid);
        }
        asm volatile("cp.async.commit_group;");
        asm volatile("cp.async.wait_group 2;");
        __syncthreads();
        const uint32_t* Au = (const uint32_t*)(As + (kt % 3) * AS_ELE);
        const uint32_t* Bu = (const uint32_t*)(Bs + (kt % 3) * BS_ELE);
        #pragma unroll
        for (int ks = 0; ks < 32; ks += 8) {
            uint32_t af[4][4], bf[4][2];
            #pragma unroll
            for (int mi = 0; mi < 4; mi++) {
                int m = wm + mi * 16 + r;
                af[mi][0] = Au[m * 36 + ks + cq];
                af[mi][1] = Au[(m + 8) * 36 + ks + cq];
                af[mi][2] = Au[m * 36 + ks + cq + 4];
                af[mi][3] = Au[(m + 8) * 36 + ks + cq + 4];
            }
            #pragma unroll
            for (int ni = 0; ni < 4; ni++) {
                int n = wn + ni * 8 + r;
                bf[ni][0] = Bu[(ks + cq) * 136 + n];
                bf[ni][1] = Bu[(ks + cq + 4) * 136 + n];
            }
            #pragma unroll
            for (int mi = 0; mi < 4; mi++)
                #pragma unroll
                for (int ni = 0; ni < 4; ni++)
                    mma8(acc[mi][ni], af[mi][0], af[mi][1], af[mi][2], af[mi][3],
                         bf[ni][0], bf[ni][1]);
        }
        __syncthreads();
    }

    #pragma unroll
    for (int mi = 0; mi < 4; mi++) {
        int row0 = bm + wm + mi * 16 + r;
        #pragma unroll
        for (int ni = 0; ni < 4; ni++) {
            int col = bn + wn + ni * 8 + 2 * cq;
            float2 lo = make_float2(acc[mi][ni][0], acc[mi][ni][1]);
            float2 hi = make_float2(acc[mi][ni][2], acc[mi][ni][3]);
            if (residual) {
                float2 r0 = *(const float2*)(residual + (size_t)row0 * N + col);
                float2 r1 = *(const float2*)(residual + (size_t)(row0 + 8) * N + col);
                lo.x += r0.x; lo.y += r0.y; hi.x += r1.x; hi.y += r1.y;
            }
            *(float2*)(C + (size_t)row0 * N + col) = lo;
            *(float2*)(C + (size_t)(row0 + 8) * N + col) = hi;
        }
    }
}

__global__ __launch_bounds__(256) void gemm_v2(
        const float* __restrict__ A, const float* __restrict__ B,
        float* __restrict__ C, const float* __restrict__ residual,
        int M, int N, int K) {
    extern __shared__ float sg[];
    gemm_core(A, B, C, residual, sg, sg + NSTAGE * AS_ELE,
              blockIdx.y * 128, blockIdx.x * 128, K, N, threadIdx.x);
}

__global__ __launch_bounds__(256) void gemm_qkv(
        const float* __restrict__ A,
        const float* __restrict__ Bq, const float* __restrict__ Bk,
        const float* __restrict__ Bv,
        float* __restrict__ Cq, float* __restrict__ Ck, float* __restrict__ Cv) {
    extern __shared__ float sg[];
    const float* B = (blockIdx.z == 0) ? Bq : (blockIdx.z == 1) ? Bk : Bv;
    float* C = (blockIdx.z == 0) ? Cq : (blockIdx.z == 1) ? Ck : Cv;
    gemm_core(A, B, C, nullptr, sg, sg + NSTAGE * AS_ELE,
              blockIdx.y * 128, blockIdx.x * 128, DMODEL, DMODEL, threadIdx.x);
}

// --------- pass A: half-chunk fused feat-proj + phi + partial KV' -------------
// One block per (bhc, half): 64 tokens. smem ~63KB -> 2+ CTAs/SM.
__global__ __launch_bounds__(320) void chunk_kv_v5(const float* __restrict__ kk_,
        const float* __restrict__ vv, const float* __restrict__ Wkf,
        float* __restrict__ ckv2) {
    extern __shared__ uint32_t su[];
    uint32_t* Ks = su;             // [tok 64][feat 164]
    uint32_t* Vs = su + 64 * 164;  // [tok 64][88]
    float* Kf = (float*)Ks;        // overlay: raw k tile [64][68]
    float* Sf = (float*)Vs;        // overlay: W [1024] + kf [1024]
    int tid = threadIdx.x, warp = tid >> 5, lane = tid & 31;
    int r = lane >> 2, cq = lane & 3;
    int bid = blockIdx.x;
    int half = bid & 1, bhc = bid >> 1;
    int c = bhc & 15, bh = bhc >> 4, b = bh >> 4, hh = bh & 15;
    size_t row0 = (size_t)(b * SEQ + c * CHUNKSZ + half * 64) * DMODEL + hh * HD;

    for (int i = tid; i < 64 * 16; i += 320) {
        int tok = i >> 4, qd = (i & 15) * 4;
        float4 t = *(const float4*)(kk_ + row0 + (size_t)tok * DMODEL + qd);
        *(float4*)(Kf + tok * 68 + qd) = t;
    }
    for (int i = tid; i < 1024; i += 320) Sf[i] = Wkf[i];
    __syncthreads();

    if (tid < 256) {                 // 4 threads per token, 4 output cols each
        int tok = tid >> 2, qm = (tid & 3) * 4;
        float accf[4];
        #pragma unroll
        for (int cc = 0; cc < 4; cc++) accf[cc] = 0.f;
        for (int e = 0; e < 64; e++) {
            float rv = Kf[tok * 68 + e];
            #pragma unroll
            for (int cc = 0; cc < 4; cc++) accf[cc] += rv * Sf[e * 16 + qm + cc];
        }
        #pragma unroll
        for (int cc = 0; cc < 4; cc++) Sf[1024 + tok * 16 + qm + cc] = accf[cc];
    }
    __syncthreads();
    if (tid < 128) {
        int tok = tid >> 1, hm = tid & 1;
        write_phi_rowmajor_half(Ks + tok * 164, Sf + 1024 + tok * 16, hm);
    }
    __syncthreads();

    for (int i = tid; i < 64 * 18; i += 320) {
        int tok = i / 18, qd = (i % 18) * 4;
        uint4 u = make_uint4(0u, 0u, 0u, 0u);
        if (qd < 64) {
            float4 t = *(const float4*)(vv + row0 + (size_t)tok * DMODEL + qd);
            u = make_uint4(__float_as_uint(t.x), __float_as_uint(t.y),
                           __float_as_uint(t.z), __float_as_uint(t.w));
        } else if (qd == 64) u.x = 0x3f800000u;
        *(uint4*)(Vs + tok * 88 + qd) = u;
    }
    __syncthreads();

    float acc[9][4];
    #pragma unroll
    for (int ni = 0; ni < 9; ni++)
        #pragma unroll
        for (int e = 0; e < 4; e++) acc[ni][e] = 0.f;
    int m0 = warp * 16;
    for (int kk = 0; kk < 64; kk += 8) {
        uint32_t a0 = Ks[(kk + cq) * 164 + m0 + r];
        uint32_t a1 = Ks[(kk + cq) * 164 + m0 + r + 8];
        uint32_t a2 = Ks[(kk + cq + 4) * 164 + m0 + r];
        uint32_t a3 = Ks[(kk + cq + 4) * 164 + m0 + r + 8];
        #pragma unroll
        for (int ni = 0; ni < 9; ni++) {
            uint32_t b0 = Vs[(kk + cq) * 88 + ni * 8 + r];
            uint32_t b1 = Vs[(kk + cq + 4) * 88 + ni * 8 + r];
            mma8(acc[ni], a0, a1, a2, a3, b0, b1);
        }
    }
    float* outb = ckv2 + (size_t)bid * FPAD * 72;
    #pragma unroll
    for (int ni = 0; ni < 9; ni++) {
        int n = ni * 8 + 2 * cq;
        *(float2*)(outb + (m0 + r) * 72 + n)     = make_float2(acc[ni][0], acc[ni][1]);
        *(float2*)(outb + (m0 + r + 8) * 72 + n) = make_float2(acc[ni][2], acc[ni][3]);
    }
}

// --------- pass B: exclusive prefix over chunks, summing the two halves -------
__global__ void prefix_kv_v3(const float* __restrict__ ckv2, float* __restrict__ ckv) {
    const int FD = FPAD * 72;
    int idx = blockIdx.x * 256 + threadIdx.x;
    if (idx >= 32 * FD) return;
    int bh = idx / FD, e = idx % FD;
    float run = 0.f;
    for (int c = 0; c < NCHUNK; c++) {
        size_t bc = (size_t)(bh * NCHUNK + c);
        float cur = ckv2[(bc * 2) * FD + e] + ckv2[(bc * 2 + 1) * FD + e];
        ckv[bc * FD + e] = run;
        run += cur;
    }
}

// --------- pass C: fused feat-proj + phi + linear attention (tf32) ------------
__global__ __launch_bounds__(256) void lin_attn_v4(const float* __restrict__ qq_,
        const float* __restrict__ kk_, const float* __restrict__ vv,
        const float* __restrict__ Wqf, const float* __restrict__ Wkf,
        const float* __restrict__ ckv, float* __restrict__ cat) {
    extern __shared__ uint32_t su[];
    uint32_t* Qs  = su;                    // [k 160][m 132]
    uint32_t* Ks  = su + 160 * 132;        // [k 160][n 132]
    uint32_t* KVs = Ks + 160 * 132;        // [k 160][n 88]
    uint32_t* Am  = Ks;                    // overlay
    uint32_t* Vs  = Ks + 128 * 132;        // overlay
    float* Qraw = (float*)Qs;              // [128][68]
    float* Kraw = (float*)Ks;              // [128][68]
    float* Scr  = (float*)KVs;
    int tid = threadIdx.x, warp = tid >> 5, lane = tid & 31;
    int r = lane >> 2, cq = lane & 3;
    int bhc = blockIdx.x, c = bhc & 15, bh = bhc >> 4, b = bh >> 4, hh = bh & 15;
    size_t row0 = (size_t)(b * SEQ + c * CHUNKSZ) * DMODEL + hh * HD;

    for (int i = tid; i < 128 * 16; i += 256) {
        int tok = i >> 4, qd = (i & 15) * 4;
        *(float4*)(Qraw + tok * 68 + qd) =
            *(const float4*)(qq_ + row0 + (size_t)tok * DMODEL + qd);
        *(float4*)(Kraw + tok * 68 + qd) =
            *(const float4*)(kk_ + row0 + (size_t)tok * DMODEL + qd);
    }
    for (int i = tid; i < 1024; i += 256) { Scr[i] = Wqf[i]; Scr[1024 + i] = Wkf[i]; }
    __syncthreads();

    {
        int tok = tid & 127, which = tid >> 7;
        const float* raw = which ? Kraw : Qraw;
        const float* W   = Scr + which * 1024;
        float* of        = Scr + 2048 + which * 2048;
        float accf[16];
        #pragma unroll
        for (int cc = 0; cc < 16; cc++) accf[cc] = 0.f;
        for (int e = 0; e < 64; e++) {
            float rv = raw[tok * 68 + e];
            #pragma unroll
            for (int cc = 0; cc < 16; cc++) accf[cc] += rv * W[e * 16 + cc];
        }
        #pragma unroll
        for (int cc = 0; cc < 16; cc++) of[tok * 16 + cc] = accf[cc];
    }
    __syncthreads();
    {
        int tok = tid & 127, which = tid >> 7;
        uint32_t* dst = which ? Ks : Qs;
        write_phi_colmajor(dst, tok, Scr + 2048 + which * 2048 + tok * 16);
    }
    __syncthreads();

    const float* kvb = ckv + (size_t)bhc * FPAD * 72;
    for (int i = tid; i < 160 * 36; i += 256) {
        int f = i / 36, n = (i % 36) * 2;
        float2 t = *(const float2*)(kvb + f * 72 + n);
        KVs[f * 88 + n]     = __float_as_uint(t.x);
        KVs[f * 88 + n + 1] = __float_as_uint(t.y);
    }
    __syncthreads();

    float accy[9][4];
    #pragma unroll
    for (int ni = 0; ni < 9; ni++)
        #pragma unroll
        for (int e = 0; e < 4; e++) accy[ni][e] = 0.f;
    int m0 = warp * 16;
    for (int kk = 0; kk < 160; kk += 8) {
        uint32_t a0 = Qs[(kk + cq) * 132 + m0 + r];
        uint32_t a1 = Qs[(kk + cq) * 132 + m0 + r + 8];
        uint32_t a2 = Qs[(kk + cq + 4) * 132 + m0 + r];
        uint32_t a3 = Qs[(kk + cq + 4) * 132 + m0 + r + 8];
        #pragma unroll
        for (int ni = 0; ni < 9; ni++) {
            uint32_t b0 = KVs[(kk + cq) * 88 + ni * 8 + r];
            uint32_t b1 = KVs[(kk + cq + 4) * 88 + ni * 8 + r];
            mma8(accy[ni], a0, a1, a2, a3, b0, b1);
        }
    }

    float acc1[4][4][4];
    #pragma unroll
    for (int mi = 0; mi < 4; mi++)
        #pragma unroll
        for (int ni = 0; ni < 4; ni++)
            #pragma unroll
            for (int e = 0; e < 4; e++) acc1[mi][ni][e] = 0.f;
    int wm = (warp >> 2) * 64, wn = (warp & 3) * 32;
    for (int kk = 0; kk < 160; kk += 8) {
        uint32_t af[4][4];
        #pragma unroll
        for (int mi = 0; mi < 4; mi++) {
            int m = wm + mi * 16;
            af[mi][0] = Qs[(kk + cq) * 132 + m + r];
            af[mi][1] = Qs[(kk + cq) * 132 + m + r + 8];
            af[mi][2] = Qs[(kk + cq + 4) * 132 + m + r];
            af[mi][3] = Qs[(kk + cq + 4) * 132 + m + r + 8];
        }
        #pragma unroll
        for (int ni = 0; ni < 4; ni++) {
            uint32_t b0 = Ks[(kk + cq) * 132 + wn + ni * 8 + r];
            uint32_t b1 = Ks[(kk + cq + 4) * 132 + wn + ni * 8 + r];
            #pragma unroll
            for (int mi = 0; mi < 4; mi++)
                mma8(acc1[mi][ni], af[mi][0], af[mi][1], af[mi][2], af[mi][3], b0, b1);
        }
    }
    __syncthreads();

    #pragma unroll
    for (int mi = 0; mi < 4; mi++) {
        int row = wm + mi * 16 + r;
        #pragma unroll
        for (int ni = 0; ni < 4; ni++) {
            int col = wn + ni * 8 + 2 * cq;
            Am[col * 132 + row]           = (col     <= row)     ? __float_as_uint(acc1[mi][ni][0]) : 0u;
            Am[(col + 1) * 132 + row]     = (col + 1 <= row)     ? __float_as_uint(acc1[mi][ni][1]) : 0u;
            Am[col * 132 + row + 8]       = (col     <= row + 8) ? __float_as_uint(acc1[mi][ni][2]) : 0u;
            Am[(col + 1) * 132 + row + 8] = (col + 1 <= row + 8) ? __float_as_uint(acc1[mi][ni][3]) : 0u;
        }
    }
    for (int i = tid; i < 128 * 18; i += 256) {
        int tok = i / 18, qd = (i % 18) * 4;
        uint4 u = make_uint4(0u, 0u, 0u, 0u);
        if (qd < 64) {
            float4 t = *(const float4*)(vv + row0 + (size_t)tok * DMODEL + qd);
            u = make_uint4(__float_as_uint(t.x), __float_as_uint(t.y),
                           __float_as_uint(t.z), __float_as_uint(t.w));
        } else if (qd == 64) u.x = 0x3f800000u;
        *(uint4*)(Vs + tok * 88 + qd) = u;
    }
    __syncthreads();

    for (int kk = 0; kk < 128; kk += 8) {
        uint32_t a0 = Am[(kk + cq) * 132 + m0 + r];
        uint32_t a1 = Am[(kk + cq) * 132 + m0 + r + 8];
        uint32_t a2 = Am[(kk + cq + 4) * 132 + m0 + r];
        uint32_t a3 = Am[(kk + cq + 4) * 132 + m0 + r + 8];
        #pragma unroll
        for (int ni = 0; ni < 9; ni++) {
            uint32_t b0 = Vs[(kk + cq) * 88 + ni * 8 + r];
            uint32_t b1 = Vs[(kk + cq + 4) * 88 + ni * 8 + r];
            mma8(accy[ni], a0, a1, a2, a3, b0, b1);
        }
    }

    float zlo = __shfl_sync(0xffffffffu, accy[8][0], lane & 28) + 1e-6f;
    float zhi = __shfl_sync(0xffffffffu, accy[8][2], lane & 28) + 1e-6f;
    float izlo = 1.f / zlo, izhi = 1.f / zhi;
    size_t rowg = (size_t)(b * SEQ + c * CHUNKSZ + m0 + r);
    #pragma unroll
    for (int ni = 0; ni < 8; ni++) {
        int colg = hh * HD + ni * 8 + 2 * cq;
        *(float2*)(cat + rowg * (2 * DMODEL) + colg) =
            make_float2(accy[ni][0] * izlo, accy[ni][1] * izlo);
        *(float2*)(cat + (rowg + 8) * (2 * DMODEL) + colg) =
            make_float2(accy[ni][2] * izhi, accy[ni][3] * izhi);
    }
}

// ---------------- sliding-window attention (256 thr, warp-pair) --------------
__global__ __launch_bounds__(256) void swa_v4(const float* __restrict__ q,
        const float* __restrict__ k, const float* __restrict__ v,
        float* __restrict__ cat) {
    extern __shared__ uint32_t su[];
    uint32_t* Qs = su;               // [e 64][tok 68]
    uint32_t* Ks = Qs + 64 * 68;     // [e 64][key 132]
    uint32_t* Ps = Ks + 64 * 132;    // [key 128][tok 68]
    uint32_t* Vs = Ps + 128 * 68;    // [key 128][d 68]
    float* red   = (float*)(Vs + 128 * 68);
    float* Osm   = (float*)Qs;       // overlay after S phase
    int tid = threadIdx.x, warp = tid >> 5, lane = tid & 31;
    int r = lane >> 2, cq = lane & 3;
    int g = warp & 3, half = warp >> 2;
    int m0 = g * 16;
    int q0 = blockIdx.x * 64, hh = blockIdx.y, b = blockIdx.z;

    for (int i = tid; i < 64 * 16; i += 256) {
        int tok = i >> 4, qd = (i & 15) * 4;
        float4 t = *(const float4*)(q + (size_t)(b * SEQ + q0 + tok) * DMODEL + hh * HD + qd);
        Qs[(qd + 0) * 68 + tok] = __float_as_uint(t.x);
        Qs[(qd + 1) * 68 + tok] = __float_as_uint(t.y);
        Qs[(qd + 2) * 68 + tok] = __float_as_uint(t.z);
        Qs[(qd + 3) * 68 + tok] = __float_as_uint(t.w);
    }
    for (int i = tid; i < 128 * 16; i += 256) {
        int key = i >> 4, qd = (i & 15) * 4;
        int kg = q0 - 64 + key;
        float4 tk = make_float4(0.f, 0.f, 0.f, 0.f);
        float4 tv = make_float4(0.f, 0.f, 0.f, 0.f);
        if (kg >= 0) {
            tk = *(const float4*)(k + (size_t)(b * SEQ + kg) * DMODEL + hh * HD + qd);
            tv = *(const float4*)(v + (size_t)(b * SEQ + kg) * DMODEL + hh * HD + qd);
        }
        Ks[(qd + 0) * 132 + key] = __float_as_uint(tk.x);
        Ks[(qd + 1) * 132 + key] = __float_as_uint(tk.y);
        Ks[(qd + 2) * 132 + key] = __float_as_uint(tk.z);
        Ks[(qd + 3) * 132 + key] = __float_as_uint(tk.w);
        *(uint4*)(Vs + key * 68 + qd) =
            make_uint4(__float_as_uint(tv.x), __float_as_uint(tv.y),
                       __float_as_uint(tv.z), __float_as_uint(tv.w));
    }
    __syncthreads();

    float acc[8][4];
    #pragma unroll
    for (int ni = 0; ni < 8; ni++)
        #pragma unroll
        for (int e = 0; e < 4; e++) acc[ni][e] = 0.f;
    for (int kk = 0; kk < 64; kk += 8) {
        uint32_t a0 = Qs[(kk + cq) * 68 + m0 + r];
        uint32_t a1 = Qs[(kk + cq) * 68 + m0 + r + 8];
        uint32_t a2 = Qs[(kk + cq + 4) * 68 + m0 + r];
        uint32_t a3 = Qs[(kk + cq + 4) * 68 + m0 + r + 8];
        #pragma unroll
        for (int ni = 0; ni < 8; ni++) {
            int gn = half * 8 + ni;
            uint32_t b0 = Ks[(kk + cq) * 132 + gn * 8 + r];
            uint32_t b1 = Ks[(kk + cq + 4) * 132 + gn * 8 + r];
            mma8(acc[ni], a0, a1, a2, a3, b0, b1);
        }
    }

    int rowlo = m0 + r, rowhi = rowlo + 8;
    float mlo = -1e30f, mhi = -1e30f;
    #pragma unroll
    for (int ni = 0; ni < 8; ni++) {
        int n = (half * 8 + ni) * 8 + 2 * cq;
        bool ok0l = (n     >= rowlo) && (n     <= rowlo + 64) && (q0 - 64 + n     >= 0);
        bool ok1l = (n + 1 >= rowlo) && (n + 1 <= rowlo + 64) && (q0 - 64 + n + 1 >= 0);
        bool ok0h = (n     >= rowhi) && (n     <= rowhi + 64) && (q0 - 64 + n     >= 0);
        bool ok1h = (n + 1 >= rowhi) && (n + 1 <= rowhi + 64) && (q0 - 64 + n + 1 >= 0);
        acc[ni][0] = ok0l ? acc[ni][0] * 0.125f : -1e30f;
        acc[ni][1] = ok1l ? acc[ni][1] * 0.125f : -1e30f;
        acc[ni][2] = ok0h ? acc[ni][2] * 0.125f : -1e30f;
        acc[ni][3] = ok1h ? acc[ni][3] * 0.125f : -1e30f;
        mlo = fmaxf(mlo, fmaxf(acc[ni][0], acc[ni][1]));
        mhi = fmaxf(mhi, fmaxf(acc[ni][2], acc[ni][3]));
    }
    mlo = fmaxf(mlo, __shfl_xor_sync(0xffffffffu, mlo, 1));
    mlo = fmaxf(mlo, __shfl_xor_sync(0xffffffffu, mlo, 2));
    mhi = fmaxf(mhi, __shfl_xor_sync(0xffffffffu, mhi, 1));
    mhi = fmaxf(mhi, __shfl_xor_sync(0xffffffffu, mhi, 2));
    if (cq == 0) {
        red[rowlo * 2 + half] = mlo;
        red[rowhi * 2 + half] = mhi;
    }
    __syncthreads();
    float Mlo = fmaxf(red[rowlo * 2], red[rowlo * 2 + 1]);
    float Mhi = fmaxf(red[rowhi * 2], red[rowhi * 2 + 1]);

    float slo = 0.f, shi = 0.f;
    #pragma unroll
    for (int ni = 0; ni < 8; ni++) {
        acc[ni][0] = __expf(acc[ni][0] - Mlo);
        acc[ni][1] = __expf(acc[ni][1] - Mlo);
        acc[ni][2] = __expf(acc[ni][2] - Mhi);
        acc[ni][3] = __expf(acc[ni][3] - Mhi);
        slo += acc[ni][0] + acc[ni][1];
        shi += acc[ni][2] + acc[ni][3];
    }
    slo += __shfl_xor_sync(0xffffffffu, slo, 1);
    slo += __shfl_xor_sync(0xffffffffu, slo, 2);
    shi += __shfl_xor_sync(0xffffffffu, shi, 1);
    shi += __shfl_xor_sync(0xffffffffu, shi, 2);
    if (cq == 0) {
        red[128 + rowlo * 2 + half] = slo;
        red[128 + rowhi * 2 + half] = shi;
    }

    #pragma unroll
    for (int ni = 0; ni < 8; ni++) {
        int n = (half * 8 + ni) * 8 + 2 * cq;
        Ps[n * 68 + rowlo]       = __float_as_uint(acc[ni][0]);
        Ps[(n + 1) * 68 + rowlo] = __float_as_uint(acc[ni][1]);
        Ps[n * 68 + rowhi]       = __float_as_uint(acc[ni][2]);
        Ps[(n + 1) * 68 + rowhi] = __float_as_uint(acc[ni][3]);
    }
    __syncthreads();
    float sumlo = red[128 + rowlo * 2] + red[128 + rowlo * 2 + 1];
    float sumhi = red[128 + rowhi * 2] + red[128 + rowhi * 2 + 1];

    float accO[8][4];
    #pragma unroll
    for (int ni = 0; ni < 8; ni++)
        #pragma unroll
        for (int e = 0; e < 4; e++) accO[ni][e] = 0.f;
    for (int ks = 0; ks < 64; ks += 8) {
        int kk = half * 64 + ks;
        uint32_t a0 = Ps[(kk + cq) * 68 + m0 + r];
        uint32_t a1 = Ps[(kk + cq) * 68 + m0 + r + 8];
        uint32_t a2 = Ps[(kk + cq + 4) * 68 + m0 + r];
        uint32_t a3 = Ps[(kk + cq + 4) * 68 + m0 + r + 8];
        #pragma unroll
        for (int ni = 0; ni < 8; ni++) {
            uint32_t b0 = Vs[(kk + cq) * 68 + ni * 8 + r];
            uint32_t b1 = Vs[(kk + cq + 4) * 68 + ni * 8 + r];
            mma8(accO[ni], a0, a1, a2, a3, b0, b1);
        }
    }
    if (half == 1) {
        #pragma unroll
        for (int ni = 0; ni < 8; ni++) {
            int n = ni * 8 + 2 * cq;
            Osm[rowlo * 68 + n]     = accO[ni][0];
            Osm[rowlo * 68 + n + 1] = accO[ni][1];
            Osm[rowhi * 68 + n]     = accO[ni][2];
            Osm[rowhi * 68 + n + 1] = accO[ni][3];
        }
    }
    __syncthreads();
    if (half == 0) {
        float izlo = 1.f / sumlo, izhi = 1.f / sumhi;
        #pragma unroll
        for (int ni = 0; ni < 8; ni++) {
            int n = ni * 8 + 2 * cq;
            int colg = DMODEL + hh * HD + n;
            *(float2*)(cat + (size_t)(b * SEQ + q0 + rowlo) * (2 * DMODEL) + colg) =
                make_float2((accO[ni][0] + Osm[rowlo * 68 + n]) * izlo,
                            (accO[ni][1] + Osm[rowlo * 68 + n + 1]) * izlo);
            *(float2*)(cat + (size_t)(b * SEQ + q0 + rowhi) * (2 * DMODEL) + colg) =
                make_float2((accO[ni][2] + Osm[rowhi * 68 + n]) * izhi,
                            (accO[ni][3] + Osm[rowhi * 68 + n + 1]) * izhi);
        }
    }
}

// ---------------------------------- launch -----------------------------------
extern "C" void kernel_launch(void* const* d_in, const int* in_sizes, int n_in,
                              void* d_out, int out_size) {
    const float* x      = (const float*)d_in[0];
    const float* norm_w = (const float*)d_in[1];
    const float* Wq     = (const float*)d_in[2];
    const float* Wk     = (const float*)d_in[3];
    const float* Wv     = (const float*)d_in[4];
    const float* Wqf    = (const float*)d_in[5];
    const float* Wkf    = (const float*)d_in[6];
    const float* Wout   = (const float*)d_in[7];
    float* out = (float*)d_out;

    float *h, *q, *k, *v, *ckv2, *ckv, *cat;
    cudaGetSymbolAddress((void**)&h,    g_h);
    cudaGetSymbolAddress((void**)&q,    g_q);
    cudaGetSymbolAddress((void**)&k,    g_k);
    cudaGetSymbolAddress((void**)&v,    g_v);
    cudaGetSymbolAddress((void**)&ckv2, g_ckv2);
    cudaGetSymbolAddress((void**)&ckv,  g_ckv);
    cudaGetSymbolAddress((void**)&cat,  g_cat);

    const int smemG   = NSTAGE * (AS_ELE + BS_ELE) * 4;                 // 107520
    const int smemKV  = (64 * 164 + 64 * 88) * 4;                       // 64512
    const int smemLin = (160 * 132 + 160 * 132 + 160 * 88) * 4;         // 225280
    const int smemSWA = (64 * 68 + 64 * 132 + 128 * 68 + 128 * 68) * 4 + 256 * 4;

    static cudaStream_t s2 = nullptr;
    static cudaEvent_t ev_fork = nullptr, ev_join = nullptr;
    static bool attrs_set = false;
    if (!attrs_set) {
        cudaFuncSetAttribute(gemm_v2,     cudaFuncAttributeMaxDynamicSharedMemorySize, smemG);
        cudaFuncSetAttribute(gemm_qkv,    cudaFuncAttributeMaxDynamicSharedMemorySize, smemG);
        cudaFuncSetAttribute(chunk_kv_v5, cudaFuncAttributeMaxDynamicSharedMemorySize, smemKV);
        cudaFuncSetAttribute(lin_attn_v4, cudaFuncAttributeMaxDynamicSharedMemorySize, smemLin);
        cudaFuncSetAttribute(swa_v4,      cudaFuncAttributeMaxDynamicSharedMemorySize, smemSWA);
        cudaStreamCreateWithFlags(&s2, cudaStreamNonBlocking);
        cudaEventCreateWithFlags(&ev_fork, cudaEventDisableTiming);
        cudaEventCreateWithFlags(&ev_join, cudaEventDisableTiming);
        attrs_set = true;
    }

    rmsnorm_kernel<<<ROWS, 256>>>(x, norm_w, h);

    gemm_qkv<<<dim3(DMODEL / 128, ROWS / 128, 3), 256, smemG>>>(h, Wq, Wk, Wv, q, k, v);

    // fork: SWA runs concurrently with the linear-attention chain
    cudaEventRecord(ev_fork, 0);
    cudaStreamWaitEvent(s2, ev_fork, 0);
    swa_v4<<<dim3(SEQ / 64, NH, BATCH), 256, smemSWA, s2>>>(q, k, v, cat);
    cudaEventRecord(ev_join, s2);

    chunk_kv_v5<<<BATCH * NH * NCHUNK * 2, 320, smemKV>>>(k, v, Wkf, ckv2);
    prefix_kv_v3<<<(32 * FPAD * 72 + 255) / 256, 256>>>(ckv2, ckv);
    lin_attn_v4<<<BATCH * NH * NCHUNK, 256, smemLin>>>(q, k, v, Wqf, Wkf, ckv, cat);

    // join before the output GEMM consumes cat
    cudaStreamWaitEvent(0, ev_join, 0);

    gemm_v2<<<dim3(DMODEL / 128, ROWS / 128), 256, smemG>>>(cat, Wout, out, x, ROWS, DMODEL, 2 * DMODEL);
}

// round 13
// speedup vs baseline: 1.2520x; 1.2520x over previous
#include <cuda_runtime.h>
#include <cuda_bf16.h>
#include <cstdint>

#define BATCH 2
#define SEQ 2048
#define DMODEL 1024
#define NH 16
#define HD 64
#define FEAT 16
#define FDIM 153           // 1 + 16 + 136
#define FPAD 160
#define NCHUNK 16
#define CHUNKSZ 128
#define ROWS (BATCH*SEQ)          // 4096
#define HROWS (BATCH*SEQ*NH)      // 131072

// ------------------------- scratch (static device memory) -------------------
__device__ __nv_bfloat16 g_hb[ROWS*DMODEL];
__device__ __nv_bfloat16 g_wqt[DMODEL*DMODEL];
__device__ __nv_bfloat16 g_wkt[DMODEL*DMODEL];
__device__ __nv_bfloat16 g_wvt[DMODEL*DMODEL];
__device__ __nv_bfloat16 g_woutt[DMODEL*2*DMODEL];
__device__ __nv_bfloat16 g_catb[(size_t)ROWS*2*DMODEL];
__device__ float g_q[ROWS*DMODEL];
__device__ float g_k[ROWS*DMODEL];
__device__ float g_v[ROWS*DMODEL];
__device__ float g_ckv2[(size_t)BATCH*NH*NCHUNK*2*FPAD*72];
__device__ float g_ckv[(size_t)BATCH*NH*NCHUNK*FPAD*72];

__device__ __forceinline__ void mma8(float acc[4], uint32_t a0, uint32_t a1,
                                     uint32_t a2, uint32_t a3,
                                     uint32_t b0, uint32_t b1) {
    asm volatile(
        "mma.sync.aligned.m16n8k8.row.col.f32.tf32.tf32.f32 "
        "{%0,%1,%2,%3}, {%4,%5,%6,%7}, {%8,%9}, {%0,%1,%2,%3};"
        : "+f"(acc[0]), "+f"(acc[1]), "+f"(acc[2]), "+f"(acc[3])
        : "r"(a0), "r"(a1), "r"(a2), "r"(a3), "r"(b0), "r"(b1));
}

__device__ __forceinline__ void mma16bf(float acc[4], uint32_t a0, uint32_t a1,
                                        uint32_t a2, uint32_t a3,
                                        uint32_t b0, uint32_t b1) {
    asm volatile(
        "mma.sync.aligned.m16n8k16.row.col.f32.bf16.bf16.f32 "
        "{%0,%1,%2,%3}, {%4,%5,%6,%7}, {%8,%9}, {%0,%1,%2,%3};"
        : "+f"(acc[0]), "+f"(acc[1]), "+f"(acc[2]), "+f"(acc[3])
        : "r"(a0), "r"(a1), "r"(a2), "r"(a3), "r"(b0), "r"(b1));
}

__device__ __forceinline__ void cp16(uint32_t sdst, const void* gsrc) {
    asm volatile("cp.async.cg.shared.global [%0], [%1], 16;" :: "r"(sdst), "l"(gsrc));
}

__device__ __forceinline__ uint32_t bf16pack(float lo, float hi) {
    uint32_t u;
    asm("cvt.rn.bf16x2.f32 %0, %1, %2;" : "=r"(u) : "f"(hi), "f"(lo));
    return u;
}

// phi expansion: x[16] -> 160 features written dst[f*132 + tok] (raw fp32 bits)
__device__ __forceinline__ void write_phi_colmajor(uint32_t* dst, int tok, const float* xf) {
    float x[16];
    #pragma unroll
    for (int i = 0; i < 16; i++) x[i] = xf[i];
    dst[tok] = 0x3f800000u;
    #pragma unroll
    for (int i = 0; i < 16; i++) dst[(1 + i) * 132 + tok] = __float_as_uint(x[i]);
    const float inv = 0.70710678118654752440f;
    int idx = 17;
    #pragma unroll
    for (int i = 0; i < 16; i++) {
        dst[idx * 132 + tok] = __float_as_uint(0.5f * x[i] * x[i]); idx++;
        #pragma unroll
        for (int j = i + 1; j < 16; j++) {
            dst[idx * 132 + tok] = __float_as_uint(inv * x[i] * x[j]); idx++;
        }
    }
    #pragma unroll
    for (int f = FDIM; f < FPAD; f++) dst[f * 132 + tok] = 0u;
}

__device__ __forceinline__ void write_phi_rowmajor_half(uint32_t* dst, const float* xf, int h) {
    float x[16];
    #pragma unroll
    for (int i = 0; i < 16; i++) x[i] = xf[i];
    const float inv = 0.70710678118654752440f;
    if (h == 0) {
        dst[0] = 0x3f800000u;
        #pragma unroll
        for (int i = 0; i < 16; i += 2) {
            int idx = 17 + i * 16 - (i * (i - 1)) / 2;
            dst[idx++] = __float_as_uint(0.5f * x[i] * x[i]);
            #pragma unroll
            for (int j = i + 1; j < 16; j++)
                dst[idx++] = __float_as_uint(inv * x[i] * x[j]);
        }
        #pragma unroll
        for (int f = FDIM; f < FPAD; f++) dst[f] = 0u;
    } else {
        #pragma unroll
        for (int i = 0; i < 16; i++) dst[1 + i] = __float_as_uint(x[i]);
        #pragma unroll
        for (int i = 1; i < 16; i += 2) {
            int idx = 17 + i * 16 - (i * (i - 1)) / 2;
            dst[idx++] = __float_as_uint(0.5f * x[i] * x[i]);
            #pragma unroll
            for (int j = i + 1; j < 16; j++)
                dst[idx++] = __float_as_uint(inv * x[i] * x[j]);
        }
    }
}

// ---------------- weight transpose + fp32->bf16 convert ----------------------
__global__ void transpose_bf16(const float* __restrict__ W, __nv_bfloat16* __restrict__ Wt,
                               int K, int N) {
    __shared__ float tile[32][33];
    int n0 = blockIdx.x * 32, k0 = blockIdx.y * 32;
    int tx = threadIdx.x & 31, ty = threadIdx.x >> 5;
    #pragma unroll
    for (int j = 0; j < 32; j += 8)
        tile[ty + j][tx] = W[(size_t)(k0 + ty + j) * N + n0 + tx];
    __syncthreads();
    #pragma unroll
    for (int j = 0; j < 32; j += 8)
        Wt[(size_t)(n0 + ty + j) * K + k0 + tx] = __float2bfloat16(tile[tx][ty + j]);
}

// ------------------------- RMSNorm (float4 in, bf16 out) ---------------------
__global__ void rmsnorm_kernel(const float* __restrict__ x,
                               const float* __restrict__ w,
                               __nv_bfloat16* __restrict__ hb) {
    int row = blockIdx.x;
    const float4* xr = (const float4*)(x + (size_t)row * DMODEL);
    float4 t = xr[threadIdx.x];
    float s = t.x * t.x + t.y * t.y + t.z * t.z + t.w * t.w;
    __shared__ float red[8];
    #pragma unroll
    for (int o = 16; o > 0; o >>= 1) s += __shfl_xor_sync(0xffffffffu, s, o);
    if ((threadIdx.x & 31) == 0) red[threadIdx.x >> 5] = s;
    __syncthreads();
    if (threadIdx.x < 8) {
        float v = red[threadIdx.x];
        #pragma unroll
        for (int o = 4; o > 0; o >>= 1) v += __shfl_xor_sync(0xffu, v, o);
        if (threadIdx.x == 0) red[0] = v;
    }
    __syncthreads();
    float rs = rsqrtf(red[0] / (float)DMODEL + 1e-6f);
    float4 wv = ((const float4*)w)[threadIdx.x];
    uint32_t p0 = bf16pack(t.x * rs * wv.x, t.y * rs * wv.y);
    uint32_t p1 = bf16pack(t.z * rs * wv.z, t.w * rs * wv.w);
    ((uint2*)(hb + (size_t)row * DMODEL))[threadIdx.x] = make_uint2(p0, p1);
}

// ---------------- BF16 GEMM: cp.async 4-stage, k-tile 32, m16n8k16 ------------
#define ASB_ELE (128*20)
#define BSB_ELE (128*20)
#define NSTAGEB 4

__device__ __forceinline__ void gemmb_issue(const __nv_bfloat16* A, const __nv_bfloat16* Bt,
        uint32_t* As, uint32_t* Bs, int bm, int bn, int k0, int K, int tid) {
    #pragma unroll
    for (int j = 0; j < 2; j++) {
        int c = tid + j * 256;            // 512 chunks: A tile 128 rows x 64B
        int m = c >> 2, seg = c & 3;
        cp16((uint32_t)__cvta_generic_to_shared(As + m * 20 + seg * 4),
             A + (size_t)(bm + m) * K + k0 + seg * 8);
    }
    #pragma unroll
    for (int j = 0; j < 2; j++) {
        int c = tid + j * 256;            // 512 chunks: Bt tile 128 rows x 64B
        int n = c >> 2, seg = c & 3;
        cp16((uint32_t)__cvta_generic_to_shared(Bs + n * 20 + seg * 4),
             Bt + (size_t)(bn + n) * K + k0 + seg * 8);
    }
}

__device__ __forceinline__ void gemmb_core(const __nv_bfloat16* A, const __nv_bfloat16* Bt,
        float* C, const float* residual, uint32_t* As, uint32_t* Bs,
        int bm, int bn, int K, int N, int tid) {
    int warp = tid >> 5, lane = tid & 31;
    int wm = (warp >> 2) * 64, wn = (warp & 3) * 32;
    int r = lane >> 2, cq = lane & 3;

    float acc[4][4][4];
    #pragma unroll
    for (int mi = 0; mi < 4; mi++)
        #pragma unroll
        for (int ni = 0; ni < 4; ni++)
            #pragma unroll
            for (int e = 0; e < 4; e++) acc[mi][ni][e] = 0.f;

    int nk = K / 32;
    gemmb_issue(A, Bt, As, Bs, bm, bn, 0, K, tid);
    asm volatile("cp.async.commit_group;");
    gemmb_issue(A, Bt, As + ASB_ELE, Bs + BSB_ELE, bm, bn, 32, K, tid);
    asm volatile("cp.async.commit_group;");
    gemmb_issue(A, Bt, As + 2 * ASB_ELE, Bs + 2 * BSB_ELE, bm, bn, 64, K, tid);
    asm volatile("cp.async.commit_group;");

    for (int kt = 0; kt < nk; kt++) {
        if (kt + 3 < nk) {
            int slot = (kt + 3) & 3;
            gemmb_issue(A, Bt, As + slot * ASB_ELE, Bs + slot * BSB_ELE,
                        bm, bn, (kt + 3) * 32, K, tid);
        }
        asm volatile("cp.async.commit_group;");
        asm volatile("cp.async.wait_group 3;");
        __syncthreads();
        const uint32_t* Au = As + (kt & 3) * ASB_ELE;
        const uint32_t* Bu = Bs + (kt & 3) * BSB_ELE;
        #pragma unroll
        for (int ks = 0; ks < 16; ks += 8) {   // two k16 steps
            uint32_t af[4][4], bf[4][2];
            #pragma unroll
            for (int mi = 0; mi < 4; mi++) {
                int m = wm + mi * 16 + r;
                af[mi][0] = Au[m * 20 + ks + cq];
                af[mi][1] = Au[(m + 8) * 20 + ks + cq];
                af[mi][2] = Au[m * 20 + ks + cq + 4];
                af[mi][3] = Au[(m + 8) * 20 + ks + cq + 4];
            }
            #pragma unroll
            for (int ni = 0; ni < 4; ni++) {
                int n = wn + ni * 8 + r;
                bf[ni][0] = Bu[n * 20 + ks + cq];
                bf[ni][1] = Bu[n * 20 + ks + cq + 4];
            }
            #pragma unroll
            for (int mi = 0; mi < 4; mi++)
                #pragma unroll
                for (int ni = 0; ni < 4; ni++)
                    mma16bf(acc[mi][ni], af[mi][0], af[mi][1], af[mi][2], af[mi][3],
                            bf[ni][0], bf[ni][1]);
        }
        __syncthreads();
    }

    #pragma unroll
    for (int mi = 0; mi < 4; mi++) {
        int row0 = bm + wm + mi * 16 + r;
        #pragma unroll
        for (int ni = 0; ni < 4; ni++) {
            int col = bn + wn + ni * 8 + 2 * cq;
            float2 lo = make_float2(acc[mi][ni][0], acc[mi][ni][1]);
            float2 hi = make_float2(acc[mi][ni][2], acc[mi][ni][3]);
            if (residual) {
                float2 r0 = *(const float2*)(residual + (size_t)row0 * N + col);
                float2 r1 = *(const float2*)(residual + (size_t)(row0 + 8) * N + col);
                lo.x += r0.x; lo.y += r0.y; hi.x += r1.x; hi.y += r1.y;
            }
            *(float2*)(C + (size_t)row0 * N + col) = lo;
            *(float2*)(C + (size_t)(row0 + 8) * N + col) = hi;
        }
    }
}

__global__ __launch_bounds__(256) void gemmb(
        const __nv_bfloat16* __restrict__ A, const __nv_bfloat16* __restrict__ Bt,
        float* __restrict__ C, const float* __restrict__ residual, int K, int N) {
    extern __shared__ uint32_t sgb[];
    gemmb_core(A, Bt, C, residual, sgb, sgb + NSTAGEB * ASB_ELE,
               blockIdx.y * 128, blockIdx.x * 128, K, N, threadIdx.x);
}

__global__ __launch_bounds__(256) void gemmb_qkv(
        const __nv_bfloat16* __restrict__ A,
        const __nv_bfloat16* __restrict__ Bq, const __nv_bfloat16* __restrict__ Bk,
        const __nv_bfloat16* __restrict__ Bv,
        float* __restrict__ Cq, float* __restrict__ Ck, float* __restrict__ Cv) {
    extern __shared__ uint32_t sgb[];
    const __nv_bfloat16* Bt = (blockIdx.z == 0) ? Bq : (blockIdx.z == 1) ? Bk : Bv;
    float* C = (blockIdx.z == 0) ? Cq : (blockIdx.z == 1) ? Ck : Cv;
    gemmb_core(A, Bt, C, nullptr, sgb, sgb + NSTAGEB * ASB_ELE,
               blockIdx.y * 128, blockIdx.x * 128, DMODEL, DMODEL, threadIdx.x);
}

// --------- pass A: half-chunk fused feat-proj + phi + partial KV' -------------
__global__ __launch_bounds__(320) void chunk_kv_v5(const float* __restrict__ kk_,
        const float* __restrict__ vv, const float* __restrict__ Wkf,
        float* __restrict__ ckv2) {
    extern __shared__ uint32_t su[];
    uint32_t* Ks = su;             // [tok 64][feat 164]
    uint32_t* Vs = su + 64 * 164;  // [tok 64][88]
    float* Kf = (float*)Ks;
    float* Sf = (float*)Vs;
    int tid = threadIdx.x, warp = tid >> 5, lane = tid & 31;
    int r = lane >> 2, cq = lane & 3;
    int bid = blockIdx.x;
    int half = bid & 1, bhc = bid >> 1;
    int c = bhc & 15, bh = bhc >> 4, b = bh >> 4, hh = bh & 15;
    size_t row0 = (size_t)(b * SEQ + c * CHUNKSZ + half * 64) * DMODEL + hh * HD;

    for (int i = tid; i < 64 * 16; i += 320) {
        int tok = i >> 4, qd = (i & 15) * 4;
        float4 t = *(const float4*)(kk_ + row0 + (size_t)tok * DMODEL + qd);
        *(float4*)(Kf + tok * 68 + qd) = t;
    }
    for (int i = tid; i < 1024; i += 320) Sf[i] = Wkf[i];
    __syncthreads();

    if (tid < 256) {
        int tok = tid >> 2, qm = (tid & 3) * 4;
        float accf[4];
        #pragma unroll
        for (int cc = 0; cc < 4; cc++) accf[cc] = 0.f;
        for (int e = 0; e < 64; e++) {
            float rv = Kf[tok * 68 + e];
            #pragma unroll
            for (int cc = 0; cc < 4; cc++) accf[cc] += rv * Sf[e * 16 + qm + cc];
        }
        #pragma unroll
        for (int cc = 0; cc < 4; cc++) Sf[1024 + tok * 16 + qm + cc] = accf[cc];
    }
    __syncthreads();
    if (tid < 128) {
        int tok = tid >> 1, hm = tid & 1;
        write_phi_rowmajor_half(Ks + tok * 164, Sf + 1024 + tok * 16, hm);
    }
    __syncthreads();

    for (int i = tid; i < 64 * 18; i += 320) {
        int tok = i / 18, qd = (i % 18) * 4;
        uint4 u = make_uint4(0u, 0u, 0u, 0u);
        if (qd < 64) {
            float4 t = *(const float4*)(vv + row0 + (size_t)tok * DMODEL + qd);
            u = make_uint4(__float_as_uint(t.x), __float_as_uint(t.y),
                           __float_as_uint(t.z), __float_as_uint(t.w));
        } else if (qd == 64) u.x = 0x3f800000u;
        *(uint4*)(Vs + tok * 88 + qd) = u;
    }
    __syncthreads();

    float acc[9][4];
    #pragma unroll
    for (int ni = 0; ni < 9; ni++)
        #pragma unroll
        for (int e = 0; e < 4; e++) acc[ni][e] = 0.f;
    int m0 = warp * 16;
    for (int kk = 0; kk < 64; kk += 8) {
        uint32_t a0 = Ks[(kk + cq) * 164 + m0 + r];
        uint32_t a1 = Ks[(kk + cq) * 164 + m0 + r + 8];
        uint32_t a2 = Ks[(kk + cq + 4) * 164 + m0 + r];
        uint32_t a3 = Ks[(kk + cq + 4) * 164 + m0 + r + 8];
        #pragma unroll
        for (int ni = 0; ni < 9; ni++) {
            uint32_t b0 = Vs[(kk + cq) * 88 + ni * 8 + r];
            uint32_t b1 = Vs[(kk + cq + 4) * 88 + ni * 8 + r];
            mma8(acc[ni], a0, a1, a2, a3, b0, b1);
        }
    }
    float* outb = ckv2 + (size_t)bid * FPAD * 72;
    #pragma unroll
    for (int ni = 0; ni < 9; ni++) {
        int n = ni * 8 + 2 * cq;
        *(float2*)(outb + (m0 + r) * 72 + n)     = make_float2(acc[ni][0], acc[ni][1]);
        *(float2*)(outb + (m0 + r + 8) * 72 + n) = make_float2(acc[ni][2], acc[ni][3]);
    }
}

// --------- pass B: exclusive prefix over chunks, summing the two halves -------
__global__ void prefix_kv_v3(const float* __restrict__ ckv2, float* __restrict__ ckv) {
    const int FD = FPAD * 72;
    int idx = blockIdx.x * 256 + threadIdx.x;
    if (idx >= 32 * FD) return;
    int bh = idx / FD, e = idx % FD;
    float run = 0.f;
    for (int c = 0; c < NCHUNK; c++) {
        size_t bc = (size_t)(bh * NCHUNK + c);
        float cur = ckv2[(bc * 2) * FD + e] + ckv2[(bc * 2 + 1) * FD + e];
        ckv[bc * FD + e] = run;
        run += cur;
    }
}

// --------- pass C: fused feat-proj + phi + linear attention (tf32) ------------
__global__ __launch_bounds__(256) void lin_attn_v5(const float* __restrict__ qq_,
        const float* __restrict__ kk_, const float* __restrict__ vv,
        const float* __restrict__ Wqf, const float* __restrict__ Wkf,
        const float* __restrict__ ckv, __nv_bfloat16* __restrict__ catb) {
    extern __shared__ uint32_t su[];
    uint32_t* Qs  = su;
    uint32_t* Ks  = su + 160 * 132;
    uint32_t* KVs = Ks + 160 * 132;
    uint32_t* Am  = Ks;
    uint32_t* Vs  = Ks + 128 * 132;
    float* Qraw = (float*)Qs;
    float* Kraw = (float*)Ks;
    float* Scr  = (float*)KVs;
    int tid = threadIdx.x, warp = tid >> 5, lane = tid & 31;
    int r = lane >> 2, cq = lane & 3;
    int bhc = blockIdx.x, c = bhc & 15, bh = bhc >> 4, b = bh >> 4, hh = bh & 15;
    size_t row0 = (size_t)(b * SEQ + c * CHUNKSZ) * DMODEL + hh * HD;

    for (int i = tid; i < 128 * 16; i += 256) {
        int tok = i >> 4, qd = (i & 15) * 4;
        *(float4*)(Qraw + tok * 68 + qd) =
            *(const float4*)(qq_ + row0 + (size_t)tok * DMODEL + qd);
        *(float4*)(Kraw + tok * 68 + qd) =
            *(const float4*)(kk_ + row0 + (size_t)tok * DMODEL + qd);
    }
    for (int i = tid; i < 1024; i += 256) { Scr[i] = Wqf[i]; Scr[1024 + i] = Wkf[i]; }
    __syncthreads();

    {
        int tok = tid & 127, which = tid >> 7;
        const float* raw = which ? Kraw : Qraw;
        const float* W   = Scr + which * 1024;
        float* of        = Scr + 2048 + which * 2048;
        float accf[16];
        #pragma unroll
        for (int cc = 0; cc < 16; cc++) accf[cc] = 0.f;
        for (int e = 0; e < 64; e++) {
            float rv = raw[tok * 68 + e];
            #pragma unroll
            for (int cc = 0; cc < 16; cc++) accf[cc] += rv * W[e * 16 + cc];
        }
        #pragma unroll
        for (int cc = 0; cc < 16; cc++) of[tok * 16 + cc] = accf[cc];
    }
    __syncthreads();
    {
        int tok = tid & 127, which = tid >> 7;
        uint32_t* dst = which ? Ks : Qs;
        write_phi_colmajor(dst, tok, Scr + 2048 + which * 2048 + tok * 16);
    }
    __syncthreads();

    const float* kvb = ckv + (size_t)bhc * FPAD * 72;
    for (int i = tid; i < 160 * 36; i += 256) {
        int f = i / 36, n = (i % 36) * 2;
        float2 t = *(const float2*)(kvb + f * 72 + n);
        KVs[f * 88 + n]     = __float_as_uint(t.x);
        KVs[f * 88 + n + 1] = __float_as_uint(t.y);
    }
    __syncthreads();

    float accy[9][4];
    #pragma unroll
    for (int ni = 0; ni < 9; ni++)
        #pragma unroll
        for (int e = 0; e < 4; e++) accy[ni][e] = 0.f;
    int m0 = warp * 16;
    for (int kk = 0; kk < 160; kk += 8) {
        uint32_t a0 = Qs[(kk + cq) * 132 + m0 + r];
        uint32_t a1 = Qs[(kk + cq) * 132 + m0 + r + 8];
        uint32_t a2 = Qs[(kk + cq + 4) * 132 + m0 + r];
        uint32_t a3 = Qs[(kk + cq + 4) * 132 + m0 + r + 8];
        #pragma unroll
        for (int ni = 0; ni < 9; ni++) {
            uint32_t b0 = KVs[(kk + cq) * 88 + ni * 8 + r];
            uint32_t b1 = KVs[(kk + cq + 4) * 88 + ni * 8 + r];
            mma8(accy[ni], a0, a1, a2, a3, b0, b1);
        }
    }

    float acc1[4][4][4];
    #pragma unroll
    for (int mi = 0; mi < 4; mi++)
        #pragma unroll
        for (int ni = 0; ni < 4; ni++)
            #pragma unroll
            for (int e = 0; e < 4; e++) acc1[mi][ni][e] = 0.f;
    int wm = (warp >> 2) * 64, wn = (warp & 3) * 32;
    for (int kk = 0; kk < 160; kk += 8) {
        uint32_t af[4][4];
        #pragma unroll
        for (int mi = 0; mi < 4; mi++) {
            int m = wm + mi * 16;
            af[mi][0] = Qs[(kk + cq) * 132 + m + r];
            af[mi][1] = Qs[(kk + cq) * 132 + m + r + 8];
            af[mi][2] = Qs[(kk + cq + 4) * 132 + m + r];
            af[mi][3] = Qs[(kk + cq + 4) * 132 + m + r + 8];
        }
        #pragma unroll
        for (int ni = 0; ni < 4; ni++) {
            uint32_t b0 = Ks[(kk + cq) * 132 + wn + ni * 8 + r];
            uint32_t b1 = Ks[(kk + cq + 4) * 132 + wn + ni * 8 + r];
            #pragma unroll
            for (int mi = 0; mi < 4; mi++)
                mma8(acc1[mi][ni], af[mi][0], af[mi][1], af[mi][2], af[mi][3], b0, b1);
        }
    }
    __syncthreads();

    #pragma unroll
    for (int mi = 0; mi < 4; mi++) {
        int row = wm + mi * 16 + r;
        #pragma unroll
        for (int ni = 0; ni < 4; ni++) {
            int col = wn + ni * 8 + 2 * cq;
            Am[col * 132 + row]           = (col     <= row)     ? __float_as_uint(acc1[mi][ni][0]) : 0u;
            Am[(col + 1) * 132 + row]     = (col + 1 <= row)     ? __float_as_uint(acc1[mi][ni][1]) : 0u;
            Am[col * 132 + row + 8]       = (col     <= row + 8) ? __float_as_uint(acc1[mi][ni][2]) : 0u;
            Am[(col + 1) * 132 + row + 8] = (col + 1 <= row + 8) ? __float_as_uint(acc1[mi][ni][3]) : 0u;
        }
    }
    for (int i = tid; i < 128 * 18; i += 256) {
        int tok = i / 18, qd = (i % 18) * 4;
        uint4 u = make_uint4(0u, 0u, 0u, 0u);
        if (qd < 64) {
            float4 t = *(const float4*)(vv + row0 + (size_t)tok * DMODEL + qd);
            u = make_uint4(__float_as_uint(t.x), __float_as_uint(t.y),
                           __float_as_uint(t.z), __float_as_uint(t.w));
        } else if (qd == 64) u.x = 0x3f800000u;
        *(uint4*)(Vs + tok * 88 + qd) = u;
    }
    __syncthreads();

    for (int kk = 0; kk < 128; kk += 8) {
        uint32_t a0 = Am[(kk + cq) * 132 + m0 + r];
        uint32_t a1 = Am[(kk + cq) * 132 + m0 + r + 8];
        uint32_t a2 = Am[(kk + cq + 4) * 132 + m0 + r];
        uint32_t a3 = Am[(kk + cq + 4) * 132 + m0 + r + 8];
        #pragma unroll
        for (int ni = 0; ni < 9; ni++) {
            uint32_t b0 = Vs[(kk + cq) * 88 + ni * 8 + r];
            uint32_t b1 = Vs[(kk + cq + 4) * 88 + ni * 8 + r];
            mma8(accy[ni], a0, a1, a2, a3, b0, b1);
        }
    }

    float zlo = __shfl_sync(0xffffffffu, accy[8][0], lane & 28) + 1e-6f;
    float zhi = __shfl_sync(0xffffffffu, accy[8][2], lane & 28) + 1e-6f;
    float izlo = 1.f / zlo, izhi = 1.f / zhi;
    size_t rowg = (size_t)(b * SEQ + c * CHUNKSZ + m0 + r);
    #pragma unroll
    for (int ni = 0; ni < 8; ni++) {
        int colg = hh * HD + ni * 8 + 2 * cq;
        *(uint32_t*)(catb + rowg * (2 * DMODEL) + colg) =
            bf16pack(accy[ni][0] * izlo, accy[ni][1] * izlo);
        *(uint32_t*)(catb + (rowg + 8) * (2 * DMODEL) + colg) =
            bf16pack(accy[ni][2] * izhi, accy[ni][3] * izhi);
    }
}

// ---------------- sliding-window attention (256 thr, warp-pair) --------------
__global__ __launch_bounds__(256) void swa_v5(const float* __restrict__ q,
        const float* __restrict__ k, const float* __restrict__ v,
        __nv_bfloat16* __restrict__ catb) {
    extern __shared__ uint32_t su[];
    uint32_t* Qs = su;
    uint32_t* Ks = Qs + 64 * 68;
    uint32_t* Ps = Ks + 64 * 132;
    uint32_t* Vs = Ps + 128 * 68;
    float* red   = (float*)(Vs + 128 * 68);
    float* Osm   = (float*)Qs;
    int tid = threadIdx.x, warp = tid >> 5, lane = tid & 31;
    int r = lane >> 2, cq = lane & 3;
    int g = warp & 3, half = warp >> 2;
    int m0 = g * 16;
    int q0 = blockIdx.x * 64, hh = blockIdx.y, b = blockIdx.z;

    for (int i = tid; i < 64 * 16; i += 256) {
        int tok = i >> 4, qd = (i & 15) * 4;
        float4 t = *(const float4*)(q + (size_t)(b * SEQ + q0 + tok) * DMODEL + hh * HD + qd);
        Qs[(qd + 0) * 68 + tok] = __float_as_uint(t.x);
        Qs[(qd + 1) * 68 + tok] = __float_as_uint(t.y);
        Qs[(qd + 2) * 68 + tok] = __float_as_uint(t.z);
        Qs[(qd + 3) * 68 + tok] = __float_as_uint(t.w);
    }
    for (int i = tid; i < 128 * 16; i += 256) {
        int key = i >> 4, qd = (i & 15) * 4;
        int kg = q0 - 64 + key;
        float4 tk = make_float4(0.f, 0.f, 0.f, 0.f);
        float4 tv = make_float4(0.f, 0.f, 0.f, 0.f);
        if (kg >= 0) {
            tk = *(const float4*)(k + (size_t)(b * SEQ + kg) * DMODEL + hh * HD + qd);
            tv = *(const float4*)(v + (size_t)(b * SEQ + kg) * DMODEL + hh * HD + qd);
        }
        Ks[(qd + 0) * 132 + key] = __float_as_uint(tk.x);
        Ks[(qd + 1) * 132 + key] = __float_as_uint(tk.y);
        Ks[(qd + 2) * 132 + key] = __float_as_uint(tk.z);
        Ks[(qd + 3) * 132 + key] = __float_as_uint(tk.w);
        *(uint4*)(Vs + key * 68 + qd) =
            make_uint4(__float_as_uint(tv.x), __float_as_uint(tv.y),
                       __float_as_uint(tv.z), __float_as_uint(tv.w));
    }
    __syncthreads();

    float acc[8][4];
    #pragma unroll
    for (int ni = 0; ni < 8; ni++)
        #pragma unroll
        for (int e = 0; e < 4; e++) acc[ni][e] = 0.f;
    for (int kk = 0; kk < 64; kk += 8) {
        uint32_t a0 = Qs[(kk + cq) * 68 + m0 + r];
        uint32_t a1 = Qs[(kk + cq) * 68 + m0 + r + 8];
        uint32_t a2 = Qs[(kk + cq + 4) * 68 + m0 + r];
        uint32_t a3 = Qs[(kk + cq + 4) * 68 + m0 + r + 8];
        #pragma unroll
        for (int ni = 0; ni < 8; ni++) {
            int gn = half * 8 + ni;
            uint32_t b0 = Ks[(kk + cq) * 132 + gn * 8 + r];
            uint32_t b1 = Ks[(kk + cq + 4) * 132 + gn * 8 + r];
            mma8(acc[ni], a0, a1, a2, a3, b0, b1);
        }
    }

    int rowlo = m0 + r, rowhi = rowlo + 8;
    float mlo = -1e30f, mhi = -1e30f;
    #pragma unroll
    for (int ni = 0; ni < 8; ni++) {
        int n = (half * 8 + ni) * 8 + 2 * cq;
        bool ok0l = (n     >= rowlo) && (n     <= rowlo + 64) && (q0 - 64 + n     >= 0);
        bool ok1l = (n + 1 >= rowlo) && (n + 1 <= rowlo + 64) && (q0 - 64 + n + 1 >= 0);
        bool ok0h = (n     >= rowhi) && (n     <= rowhi + 64) && (q0 - 64 + n     >= 0);
        bool ok1h = (n + 1 >= rowhi) && (n + 1 <= rowhi + 64) && (q0 - 64 + n + 1 >= 0);
        acc[ni][0] = ok0l ? acc[ni][0] * 0.125f : -1e30f;
        acc[ni][1] = ok1l ? acc[ni][1] * 0.125f : -1e30f;
        acc[ni][2] = ok0h ? acc[ni][2] * 0.125f : -1e30f;
        acc[ni][3] = ok1h ? acc[ni][3] * 0.125f : -1e30f;
        mlo = fmaxf(mlo, fmaxf(acc[ni][0], acc[ni][1]));
        mhi = fmaxf(mhi, fmaxf(acc[ni][2], acc[ni][3]));
    }
    mlo = fmaxf(mlo, __shfl_xor_sync(0xffffffffu, mlo, 1));
    mlo = fmaxf(mlo, __shfl_xor_sync(0xffffffffu, mlo, 2));
    mhi = fmaxf(mhi, __shfl_xor_sync(0xffffffffu, mhi, 1));
    mhi = fmaxf(mhi, __shfl_xor_sync(0xffffffffu, mhi, 2));
    if (cq == 0) {
        red[rowlo * 2 + half] = mlo;
        red[rowhi * 2 + half] = mhi;
    }
    __syncthreads();
    float Mlo = fmaxf(red[rowlo * 2], red[rowlo * 2 + 1]);
    float Mhi = fmaxf(red[rowhi * 2], red[rowhi * 2 + 1]);

    float slo = 0.f, shi = 0.f;
    #pragma unroll
    for (int ni = 0; ni < 8; ni++) {
        acc[ni][0] = __expf(acc[ni][0] - Mlo);
        acc[ni][1] = __expf(acc[ni][1] - Mlo);
        acc[ni][2] = __expf(acc[ni][2] - Mhi);
        acc[ni][3] = __expf(acc[ni][3] - Mhi);
        slo += acc[ni][0] + acc[ni][1];
        shi += acc[ni][2] + acc[ni][3];
    }
    slo += __shfl_xor_sync(0xffffffffu, slo, 1);
    slo += __shfl_xor_sync(0xffffffffu, slo, 2);
    shi += __shfl_xor_sync(0xffffffffu, shi, 1);
    shi += __shfl_xor_sync(0xffffffffu, shi, 2);
    if (cq == 0) {
        red[128 + rowlo * 2 + half] = slo;
        red[128 + rowhi * 2 + half] = shi;
    }

    #pragma unroll
    for (int ni = 0; ni < 8; ni++) {
        int n = (half * 8 + ni) * 8 + 2 * cq;
        Ps[n * 68 + rowlo]       = __float_as_uint(acc[ni][0]);
        Ps[(n + 1) * 68 + rowlo] = __float_as_uint(acc[ni][1]);
        Ps[n * 68 + rowhi]       = __float_as_uint(acc[ni][2]);
        Ps[(n + 1) * 68 + rowhi] = __float_as_uint(acc[ni][3]);
    }
    __syncthreads();
    float sumlo = red[128 + rowlo * 2] + red[128 + rowlo * 2 + 1];
    float sumhi = red[128 + rowhi * 2] + red[128 + rowhi * 2 + 1];

    float accO[8][4];
    #pragma unroll
    for (int ni = 0; ni < 8; ni++)
        #pragma unroll
        for (int e = 0; e < 4; e++) accO[ni][e] = 0.f;
    for (int ks = 0; ks < 64; ks += 8) {
        int kk = half * 64 + ks;
        uint32_t a0 = Ps[(kk + cq) * 68 + m0 + r];
        uint32_t a1 = Ps[(kk + cq) * 68 + m0 + r + 8];
        uint32_t a2 = Ps[(kk + cq + 4) * 68 + m0 + r];
        uint32_t a3 = Ps[(kk + cq + 4) * 68 + m0 + r + 8];
        #pragma unroll
        for (int ni = 0; ni < 8; ni++) {
            uint32_t b0 = Vs[(kk + cq) * 68 + ni * 8 + r];
            uint32_t b1 = Vs[(kk + cq + 4) * 68 + ni * 8 + r];
            mma8(accO[ni], a0, a1, a2, a3, b0, b1);
        }
    }
    if (half == 1) {
        #pragma unroll
        for (int ni = 0; ni < 8; ni++) {
            int n = ni * 8 + 2 * cq;
            Osm[rowlo * 68 + n]     = accO[ni][0];
            Osm[rowlo * 68 + n + 1] = accO[ni][1];
            Osm[rowhi * 68 + n]     = accO[ni][2];
            Osm[rowhi * 68 + n + 1] = accO[ni][3];
        }
    }
    __syncthreads();
    if (half == 0) {
        float izlo = 1.f / sumlo, izhi = 1.f / sumhi;
        #pragma unroll
        for (int ni = 0; ni < 8; ni++) {
            int n = ni * 8 + 2 * cq;
            int colg = DMODEL + hh * HD + n;
            *(uint32_t*)(catb + (size_t)(b * SEQ + q0 + rowlo) * (2 * DMODEL) + colg) =
                bf16pack((accO[ni][0] + Osm[rowlo * 68 + n]) * izlo,
                         (accO[ni][1] + Osm[rowlo * 68 + n + 1]) * izlo);
            *(uint32_t*)(catb + (size_t)(b * SEQ + q0 + rowhi) * (2 * DMODEL) + colg) =
                bf16pack((accO[ni][2] + Osm[rowhi * 68 + n]) * izhi,
                         (accO[ni][3] + Osm[rowhi * 68 + n + 1]) * izhi);
        }
    }
}

// ---------------------------------- launch -----------------------------------
extern "C" void kernel_launch(void* const* d_in, const int* in_sizes, int n_in,
                              void* d_out, int out_size) {
    const float* x      = (const float*)d_in[0];
    const float* norm_w = (const float*)d_in[1];
    const float* Wq     = (const float*)d_in[2];
    const float* Wk     = (const float*)d_in[3];
    const float* Wv     = (const float*)d_in[4];
    const float* Wqf    = (const float*)d_in[5];
    const float* Wkf    = (const float*)d_in[6];
    const float* Wout   = (const float*)d_in[7];
    float* out = (float*)d_out;

    __nv_bfloat16 *hb, *wqt, *wkt, *wvt, *woutt, *catb;
    float *q, *k, *v, *ckv2, *ckv;
    cudaGetSymbolAddress((void**)&hb,    g_hb);
    cudaGetSymbolAddress((void**)&wqt,   g_wqt);
    cudaGetSymbolAddress((void**)&wkt,   g_wkt);
    cudaGetSymbolAddress((void**)&wvt,   g_wvt);
    cudaGetSymbolAddress((void**)&woutt, g_woutt);
    cudaGetSymbolAddress((void**)&catb,  g_catb);
    cudaGetSymbolAddress((void**)&q,     g_q);
    cudaGetSymbolAddress((void**)&k,     g_k);
    cudaGetSymbolAddress((void**)&v,     g_v);
    cudaGetSymbolAddress((void**)&ckv2,  g_ckv2);
    cudaGetSymbolAddress((void**)&ckv,   g_ckv);

    const int smemG   = NSTAGEB * (ASB_ELE + BSB_ELE) * 4;              // 81920
    const int smemKV  = (64 * 164 + 64 * 88) * 4;                       // 64512
    const int smemLin = (160 * 132 + 160 * 132 + 160 * 88) * 4;         // 225280
    const int smemSWA = (64 * 68 + 64 * 132 + 128 * 68 + 128 * 68) * 4 + 256 * 4;

    static cudaStream_t s2 = nullptr;
    static cudaEvent_t ev_root = nullptr, ev_w = nullptr, ev_fork = nullptr, ev_join = nullptr;
    static bool attrs_set = false;
    if (!attrs_set) {
        cudaFuncSetAttribute(gemmb,       cudaFuncAttributeMaxDynamicSharedMemorySize, smemG);
        cudaFuncSetAttribute(gemmb_qkv,   cudaFuncAttributeMaxDynamicSharedMemorySize, smemG);
        cudaFuncSetAttribute(chunk_kv_v5, cudaFuncAttributeMaxDynamicSharedMemorySize, smemKV);
        cudaFuncSetAttribute(lin_attn_v5, cudaFuncAttributeMaxDynamicSharedMemorySize, smemLin);
        cudaFuncSetAttribute(swa_v5,      cudaFuncAttributeMaxDynamicSharedMemorySize, smemSWA);
        cudaStreamCreateWithFlags(&s2, cudaStreamNonBlocking);
        cudaEventCreateWithFlags(&ev_root, cudaEventDisableTiming);
        cudaEventCreateWithFlags(&ev_w,    cudaEventDisableTiming);
        cudaEventCreateWithFlags(&ev_fork, cudaEventDisableTiming);
        cudaEventCreateWithFlags(&ev_join, cudaEventDisableTiming);
        attrs_set = true;
    }

    // fork s2 from the capture-origin stream BEFORE any s2 work (capture-legal)
    cudaEventRecord(ev_root, 0);
    cudaStreamWaitEvent(s2, ev_root, 0);

    // weight transposes (s2) overlap rmsnorm (s0)
    transpose_bf16<<<dim3(32, 32), 256, 0, s2>>>(Wq, wqt, DMODEL, DMODEL);
    transpose_bf16<<<dim3(32, 32), 256, 0, s2>>>(Wk, wkt, DMODEL, DMODEL);
    transpose_bf16<<<dim3(32, 32), 256, 0, s2>>>(Wv, wvt, DMODEL, DMODEL);
    transpose_bf16<<<dim3(32, 64), 256, 0, s2>>>(Wout, woutt, 2 * DMODEL, DMODEL);
    cudaEventRecord(ev_w, s2);

    rmsnorm_kernel<<<ROWS, 256>>>(x, norm_w, hb);
    cudaStreamWaitEvent(0, ev_w, 0);

    gemmb_qkv<<<dim3(DMODEL / 128, ROWS / 128, 3), 256, smemG>>>(hb, wqt, wkt, wvt, q, k, v);

    // fork: SWA runs concurrently with the linear-attention chain
    cudaEventRecord(ev_fork, 0);
    cudaStreamWaitEvent(s2, ev_fork, 0);
    swa_v5<<<dim3(SEQ / 64, NH, BATCH), 256, smemSWA, s2>>>(q, k, v, catb);
    cudaEventRecord(ev_join, s2);

    chunk_kv_v5<<<BATCH * NH * NCHUNK * 2, 320, smemKV>>>(k, v, Wkf, ckv2);
    prefix_kv_v3<<<(32 * FPAD * 72 + 255) / 256, 256>>>(ckv2, ckv);
    lin_attn_v5<<<BATCH * NH * NCHUNK, 256, smemLin>>>(q, k, v, Wqf, Wkf, ckv, catb);

    cudaStreamWaitEvent(0, ev_join, 0);

    gemmb<<<dim3(DMODEL / 128, ROWS / 128), 256, smemG>>>(catb, woutt, out, x, 2 * DMODEL, DMODEL);
}

// round 14
// speedup vs baseline: 1.4195x; 1.1338x over previous
#include <cuda_runtime.h>
#include <cuda_bf16.h>
#include <cstdint>

#define BATCH 2
#define SEQ 2048
#define DMODEL 1024
#define NH 16
#define HD 64
#define FEAT 16
#define FDIM 153           // 1 + 16 + 136
#define FPAD 160
#define NCHUNK 16
#define CHUNKSZ 128
#define ROWS (BATCH*SEQ)          // 4096
#define HROWS (BATCH*SEQ*NH)      // 131072

// ------------------------- scratch (static device memory) -------------------
__device__ __nv_bfloat16 g_hb[ROWS*DMODEL];
__device__ __nv_bfloat16 g_wqt[DMODEL*DMODEL];
__device__ __nv_bfloat16 g_wkt[DMODEL*DMODEL];
__device__ __nv_bfloat16 g_wvt[DMODEL*DMODEL];
__device__ __nv_bfloat16 g_woutt[DMODEL*2*DMODEL];
__device__ __nv_bfloat16 g_catb[(size_t)ROWS*2*DMODEL];
__device__ float g_q[ROWS*DMODEL];
__device__ float g_k[ROWS*DMODEL];
__device__ float g_v[ROWS*DMODEL];
__device__ float g_ckv2[(size_t)BATCH*NH*NCHUNK*2*FPAD*72];
__device__ float g_ckv[(size_t)BATCH*NH*NCHUNK*FPAD*72];

__device__ __forceinline__ void mma8(float acc[4], uint32_t a0, uint32_t a1,
                                     uint32_t a2, uint32_t a3,
                                     uint32_t b0, uint32_t b1) {
    asm volatile(
        "mma.sync.aligned.m16n8k8.row.col.f32.tf32.tf32.f32 "
        "{%0,%1,%2,%3}, {%4,%5,%6,%7}, {%8,%9}, {%0,%1,%2,%3};"
        : "+f"(acc[0]), "+f"(acc[1]), "+f"(acc[2]), "+f"(acc[3])
        : "r"(a0), "r"(a1), "r"(a2), "r"(a3), "r"(b0), "r"(b1));
}

__device__ __forceinline__ void mma16bf(float acc[4], uint32_t a0, uint32_t a1,
                                        uint32_t a2, uint32_t a3,
                                        uint32_t b0, uint32_t b1) {
    asm volatile(
        "mma.sync.aligned.m16n8k16.row.col.f32.bf16.bf16.f32 "
        "{%0,%1,%2,%3}, {%4,%5,%6,%7}, {%8,%9}, {%0,%1,%2,%3};"
        : "+f"(acc[0]), "+f"(acc[1]), "+f"(acc[2]), "+f"(acc[3])
        : "r"(a0), "r"(a1), "r"(a2), "r"(a3), "r"(b0), "r"(b1));
}

__device__ __forceinline__ void cp16(uint32_t sdst, const void* gsrc) {
    asm volatile("cp.async.cg.shared.global [%0], [%1], 16;" :: "r"(sdst), "l"(gsrc));
}

__device__ __forceinline__ uint32_t bf16pack(float lo, float hi) {
    uint32_t u;
    asm("cvt.rn.bf16x2.f32 %0, %1, %2;" : "=r"(u) : "f"(hi), "f"(lo));
    return u;
}

// phi expansion -> bf16x2-packed col-major: uint dst[(f>>1)*132 + tok] holds
// (feature f even -> low half, f+1 -> high half). Emits features in order.
__device__ __forceinline__ void write_phi_colmajor_bf(uint32_t* dst, int tok,
                                                      const float* xf) {
    float x[16];
    #pragma unroll
    for (int i = 0; i < 16; i++) x[i] = xf[i];
    const float inv = 0.70710678118654752440f;
    float pend = 0.f;
    #define PHI_EMIT(IDX, V) { if ((IDX) & 1) dst[((IDX) >> 1) * 132 + tok] = bf16pack(pend, (V)); else pend = (V); }
    PHI_EMIT(0, 1.f);
    #pragma unroll
    for (int i = 0; i < 16; i++) PHI_EMIT(1 + i, x[i]);
    int idx = 17;
    #pragma unroll
    for (int i = 0; i < 16; i++) {
        PHI_EMIT(idx, 0.5f * x[i] * x[i]); idx++;
        #pragma unroll
        for (int j = i + 1; j < 16; j++) { PHI_EMIT(idx, inv * x[i] * x[j]); idx++; }
    }
    #pragma unroll
    for (int f = FDIM; f < FPAD; f++) PHI_EMIT(f, 0.f);
    #undef PHI_EMIT
}

// fp32 row-major phi (used by chunk_kv, unchanged semantics)
__device__ __forceinline__ void write_phi_rowmajor_half(uint32_t* dst, const float* xf, int h) {
    float x[16];
    #pragma unroll
    for (int i = 0; i < 16; i++) x[i] = xf[i];
    const float inv = 0.70710678118654752440f;
    if (h == 0) {
        dst[0] = 0x3f800000u;
        #pragma unroll
        for (int i = 0; i < 16; i += 2) {
            int idx = 17 + i * 16 - (i * (i - 1)) / 2;
            dst[idx++] = __float_as_uint(0.5f * x[i] * x[i]);
            #pragma unroll
            for (int j = i + 1; j < 16; j++)
                dst[idx++] = __float_as_uint(inv * x[i] * x[j]);
        }
        #pragma unroll
        for (int f = FDIM; f < FPAD; f++) dst[f] = 0u;
    } else {
        #pragma unroll
        for (int i = 0; i < 16; i++) dst[1 + i] = __float_as_uint(x[i]);
        #pragma unroll
        for (int i = 1; i < 16; i += 2) {
            int idx = 17 + i * 16 - (i * (i - 1)) / 2;
            dst[idx++] = __float_as_uint(0.5f * x[i] * x[i]);
            #pragma unroll
            for (int j = i + 1; j < 16; j++)
                dst[idx++] = __float_as_uint(inv * x[i] * x[j]);
        }
    }
}

// ---------------- weight transpose + fp32->bf16 convert ----------------------
__global__ void transpose_bf16(const float* __restrict__ W, __nv_bfloat16* __restrict__ Wt,
                               int K, int N) {
    __shared__ float tile[32][33];
    int n0 = blockIdx.x * 32, k0 = blockIdx.y * 32;
    int tx = threadIdx.x & 31, ty = threadIdx.x >> 5;
    #pragma unroll
    for (int j = 0; j < 32; j += 8)
        tile[ty + j][tx] = W[(size_t)(k0 + ty + j) * N + n0 + tx];
    __syncthreads();
    #pragma unroll
    for (int j = 0; j < 32; j += 8)
        Wt[(size_t)(n0 + ty + j) * K + k0 + tx] = __float2bfloat16(tile[tx][ty + j]);
}

// ------------------------- RMSNorm (float4 in, bf16 out) ---------------------
__global__ void rmsnorm_kernel(const float* __restrict__ x,
                               const float* __restrict__ w,
                               __nv_bfloat16* __restrict__ hb) {
    int row = blockIdx.x;
    const float4* xr = (const float4*)(x + (size_t)row * DMODEL);
    float4 t = xr[threadIdx.x];
    float s = t.x * t.x + t.y * t.y + t.z * t.z + t.w * t.w;
    __shared__ float red[8];
    #pragma unroll
    for (int o = 16; o > 0; o >>= 1) s += __shfl_xor_sync(0xffffffffu, s, o);
    if ((threadIdx.x & 31) == 0) red[threadIdx.x >> 5] = s;
    __syncthreads();
    if (threadIdx.x < 8) {
        float v = red[threadIdx.x];
        #pragma unroll
        for (int o = 4; o > 0; o >>= 1) v += __shfl_xor_sync(0xffu, v, o);
        if (threadIdx.x == 0) red[0] = v;
    }
    __syncthreads();
    float rs = rsqrtf(red[0] / (float)DMODEL + 1e-6f);
    float4 wv = ((const float4*)w)[threadIdx.x];
    uint32_t p0 = bf16pack(t.x * rs * wv.x, t.y * rs * wv.y);
    uint32_t p1 = bf16pack(t.z * rs * wv.z, t.w * rs * wv.w);
    ((uint2*)(hb + (size_t)row * DMODEL))[threadIdx.x] = make_uint2(p0, p1);
}

// ---------------- BF16 GEMM: cp.async 4-stage, k-tile 32, m16n8k16 ------------
#define ASB_ELE (128*20)
#define BSB_ELE (128*20)
#define NSTAGEB 4

__device__ __forceinline__ void gemmb_issue(const __nv_bfloat16* A, const __nv_bfloat16* Bt,
        uint32_t* As, uint32_t* Bs, int bm, int bn, int k0, int K, int tid) {
    #pragma unroll
    for (int j = 0; j < 2; j++) {
        int c = tid + j * 256;
        int m = c >> 2, seg = c & 3;
        cp16((uint32_t)__cvta_generic_to_shared(As + m * 20 + seg * 4),
             A + (size_t)(bm + m) * K + k0 + seg * 8);
    }
    #pragma unroll
    for (int j = 0; j < 2; j++) {
        int c = tid + j * 256;
        int n = c >> 2, seg = c & 3;
        cp16((uint32_t)__cvta_generic_to_shared(Bs + n * 20 + seg * 4),
             Bt + (size_t)(bn + n) * K + k0 + seg * 8);
    }
}

__device__ __forceinline__ void gemmb_core(const __nv_bfloat16* A, const __nv_bfloat16* Bt,
        float* C, const float* residual, uint32_t* As, uint32_t* Bs,
        int bm, int bn, int K, int N, int tid) {
    int warp = tid >> 5, lane = tid & 31;
    int wm = (warp >> 2) * 64, wn = (warp & 3) * 32;
    int r = lane >> 2, cq = lane & 3;

    float acc[4][4][4];
    #pragma unroll
    for (int mi = 0; mi < 4; mi++)
        #pragma unroll
        for (int ni = 0; ni < 4; ni++)
            #pragma unroll
            for (int e = 0; e < 4; e++) acc[mi][ni][e] = 0.f;

    int nk = K / 32;
    gemmb_issue(A, Bt, As, Bs, bm, bn, 0, K, tid);
    asm volatile("cp.async.commit_group;");
    gemmb_issue(A, Bt, As + ASB_ELE, Bs + BSB_ELE, bm, bn, 32, K, tid);
    asm volatile("cp.async.commit_group;");
    gemmb_issue(A, Bt, As + 2 * ASB_ELE, Bs + 2 * BSB_ELE, bm, bn, 64, K, tid);
    asm volatile("cp.async.commit_group;");

    for (int kt = 0; kt < nk; kt++) {
        if (kt + 3 < nk) {
            int slot = (kt + 3) & 3;
            gemmb_issue(A, Bt, As + slot * ASB_ELE, Bs + slot * BSB_ELE,
                        bm, bn, (kt + 3) * 32, K, tid);
        }
        asm volatile("cp.async.commit_group;");
        asm volatile("cp.async.wait_group 3;");
        __syncthreads();
        const uint32_t* Au = As + (kt & 3) * ASB_ELE;
        const uint32_t* Bu = Bs + (kt & 3) * BSB_ELE;
        #pragma unroll
        for (int ks = 0; ks < 16; ks += 8) {
            uint32_t af[4][4], bf[4][2];
            #pragma unroll
            for (int mi = 0; mi < 4; mi++) {
                int m = wm + mi * 16 + r;
                af[mi][0] = Au[m * 20 + ks + cq];
                af[mi][1] = Au[(m + 8) * 20 + ks + cq];
                af[mi][2] = Au[m * 20 + ks + cq + 4];
                af[mi][3] = Au[(m + 8) * 20 + ks + cq + 4];
            }
            #pragma unroll
            for (int ni = 0; ni < 4; ni++) {
                int n = wn + ni * 8 + r;
                bf[ni][0] = Bu[n * 20 + ks + cq];
                bf[ni][1] = Bu[n * 20 + ks + cq + 4];
            }
            #pragma unroll
            for (int mi = 0; mi < 4; mi++)
                #pragma unroll
                for (int ni = 0; ni < 4; ni++)
                    mma16bf(acc[mi][ni], af[mi][0], af[mi][1], af[mi][2], af[mi][3],
                            bf[ni][0], bf[ni][1]);
        }
        __syncthreads();
    }

    #pragma unroll
    for (int mi = 0; mi < 4; mi++) {
        int row0 = bm + wm + mi * 16 + r;
        #pragma unroll
        for (int ni = 0; ni < 4; ni++) {
            int col = bn + wn + ni * 8 + 2 * cq;
            float2 lo = make_float2(acc[mi][ni][0], acc[mi][ni][1]);
            float2 hi = make_float2(acc[mi][ni][2], acc[mi][ni][3]);
            if (residual) {
                float2 r0 = *(const float2*)(residual + (size_t)row0 * N + col);
                float2 r1 = *(const float2*)(residual + (size_t)(row0 + 8) * N + col);
                lo.x += r0.x; lo.y += r0.y; hi.x += r1.x; hi.y += r1.y;
            }
            *(float2*)(C + (size_t)row0 * N + col) = lo;
            *(float2*)(C + (size_t)(row0 + 8) * N + col) = hi;
        }
    }
}

__global__ __launch_bounds__(256) void gemmb(
        const __nv_bfloat16* __restrict__ A, const __nv_bfloat16* __restrict__ Bt,
        float* __restrict__ C, const float* __restrict__ residual, int K, int N) {
    extern __shared__ uint32_t sgb[];
    gemmb_core(A, Bt, C, residual, sgb, sgb + NSTAGEB * ASB_ELE,
               blockIdx.y * 128, blockIdx.x * 128, K, N, threadIdx.x);
}

__global__ __launch_bounds__(256) void gemmb_qkv(
        const __nv_bfloat16* __restrict__ A,
        const __nv_bfloat16* __restrict__ Bq, const __nv_bfloat16* __restrict__ Bk,
        const __nv_bfloat16* __restrict__ Bv,
        float* __restrict__ Cq, float* __restrict__ Ck, float* __restrict__ Cv) {
    extern __shared__ uint32_t sgb[];
    const __nv_bfloat16* Bt = (blockIdx.z == 0) ? Bq : (blockIdx.z == 1) ? Bk : Bv;
    float* C = (blockIdx.z == 0) ? Cq : (blockIdx.z == 1) ? Ck : Cv;
    gemmb_core(A, Bt, C, nullptr, sgb, sgb + NSTAGEB * ASB_ELE,
               blockIdx.y * 128, blockIdx.x * 128, DMODEL, DMODEL, threadIdx.x);
}

// --------- pass A: half-chunk fused feat-proj + phi + partial KV' -------------
__global__ __launch_bounds__(320) void chunk_kv_v5(const float* __restrict__ kk_,
        const float* __restrict__ vv, const float* __restrict__ Wkf,
        float* __restrict__ ckv2) {
    extern __shared__ uint32_t su[];
    uint32_t* Ks = su;             // [tok 64][feat 164]
    uint32_t* Vs = su + 64 * 164;  // [tok 64][88]
    float* Kf = (float*)Ks;
    float* Sf = (float*)Vs;
    int tid = threadIdx.x, warp = tid >> 5, lane = tid & 31;
    int r = lane >> 2, cq = lane & 3;
    int bid = blockIdx.x;
    int half = bid & 1, bhc = bid >> 1;
    int c = bhc & 15, bh = bhc >> 4, b = bh >> 4, hh = bh & 15;
    size_t row0 = (size_t)(b * SEQ + c * CHUNKSZ + half * 64) * DMODEL + hh * HD;

    for (int i = tid; i < 64 * 16; i += 320) {
        int tok = i >> 4, qd = (i & 15) * 4;
        float4 t = *(const float4*)(kk_ + row0 + (size_t)tok * DMODEL + qd);
        *(float4*)(Kf + tok * 68 + qd) = t;
    }
    for (int i = tid; i < 1024; i += 320) Sf[i] = Wkf[i];
    __syncthreads();

    if (tid < 256) {
        int tok = tid >> 2, qm = (tid & 3) * 4;
        float accf[4];
        #pragma unroll
        for (int cc = 0; cc < 4; cc++) accf[cc] = 0.f;
        for (int e = 0; e < 64; e++) {
            float rv = Kf[tok * 68 + e];
            #pragma unroll
            for (int cc = 0; cc < 4; cc++) accf[cc] += rv * Sf[e * 16 + qm + cc];
        }
        #pragma unroll
        for (int cc = 0; cc < 4; cc++) Sf[1024 + tok * 16 + qm + cc] = accf[cc];
    }
    __syncthreads();
    if (tid < 128) {
        int tok = tid >> 1, hm = tid & 1;
        write_phi_rowmajor_half(Ks + tok * 164, Sf + 1024 + tok * 16, hm);
    }
    __syncthreads();

    for (int i = tid; i < 64 * 18; i += 320) {
        int tok = i / 18, qd = (i % 18) * 4;
        uint4 u = make_uint4(0u, 0u, 0u, 0u);
        if (qd < 64) {
            float4 t = *(const float4*)(vv + row0 + (size_t)tok * DMODEL + qd);
            u = make_uint4(__float_as_uint(t.x), __float_as_uint(t.y),
                           __float_as_uint(t.z), __float_as_uint(t.w));
        } else if (qd == 64) u.x = 0x3f800000u;
        *(uint4*)(Vs + tok * 88 + qd) = u;
    }
    __syncthreads();

    float acc[9][4];
    #pragma unroll
    for (int ni = 0; ni < 9; ni++)
        #pragma unroll
        for (int e = 0; e < 4; e++) acc[ni][e] = 0.f;
    int m0 = warp * 16;
    for (int kk = 0; kk < 64; kk += 8) {
        uint32_t a0 = Ks[(kk + cq) * 164 + m0 + r];
        uint32_t a1 = Ks[(kk + cq) * 164 + m0 + r + 8];
        uint32_t a2 = Ks[(kk + cq + 4) * 164 + m0 + r];
        uint32_t a3 = Ks[(kk + cq + 4) * 164 + m0 + r + 8];
        #pragma unroll
        for (int ni = 0; ni < 9; ni++) {
            uint32_t b0 = Vs[(kk + cq) * 88 + ni * 8 + r];
            uint32_t b1 = Vs[(kk + cq + 4) * 88 + ni * 8 + r];
            mma8(acc[ni], a0, a1, a2, a3, b0, b1);
        }
    }
    float* outb = ckv2 + (size_t)bid * FPAD * 72;
    #pragma unroll
    for (int ni = 0; ni < 9; ni++) {
        int n = ni * 8 + 2 * cq;
        *(float2*)(outb + (m0 + r) * 72 + n)     = make_float2(acc[ni][0], acc[ni][1]);
        *(float2*)(outb + (m0 + r + 8) * 72 + n) = make_float2(acc[ni][2], acc[ni][3]);
    }
}

// --------- pass B: exclusive prefix over chunks, summing the two halves -------
__global__ void prefix_kv_v3(const float* __restrict__ ckv2, float* __restrict__ ckv) {
    const int FD = FPAD * 72;
    int idx = blockIdx.x * 256 + threadIdx.x;
    if (idx >= 32 * FD) return;
    int bh = idx / FD, e = idx % FD;
    float run = 0.f;
    for (int c = 0; c < NCHUNK; c++) {
        size_t bc = (size_t)(bh * NCHUNK + c);
        float cur = ckv2[(bc * 2) * FD + e] + ckv2[(bc * 2 + 1) * FD + e];
        ckv[bc * FD + e] = run;
        run += cur;
    }
}

// --------- pass C: fused feat-proj + phi + linear attention (bf16 mma) --------
// Qs/Ks: [kpair 80][132] bf16x2 (feature pairs); KVs: [kpair 80][88].
// Overlays after GEMM1: Am [spair 64][132] (score token-pairs), Vs [spair 64][88].
__global__ __launch_bounds__(256) void lin_attn_v6(const float* __restrict__ qq_,
        const float* __restrict__ kk_, const float* __restrict__ vv,
        const float* __restrict__ Wqf, const float* __restrict__ Wkf,
        const float* __restrict__ ckv, __nv_bfloat16* __restrict__ catb) {
    extern __shared__ uint32_t su[];
    uint32_t* Qs  = su;                  // [kp 80][132]
    uint32_t* Ks  = su + 80 * 132;       // [kp 80][132]
    uint32_t* KVs = Ks + 80 * 132;       // [kp 80][88]
    uint32_t* Am  = Ks;                  // overlay [sp 64][132]
    uint32_t* Vs  = Ks + 64 * 132;       // overlay [sp 64][88]
    float* Qraw = (float*)Qs;            // [128][68]
    float* Kraw = (float*)Ks;
    float* Scr  = (float*)KVs;           // 6144 floats
    int tid = threadIdx.x, warp = tid >> 5, lane = tid & 31;
    int r = lane >> 2, cq = lane & 3;
    int bhc = blockIdx.x, c = bhc & 15, bh = bhc >> 4, b = bh >> 4, hh = bh & 15;
    size_t row0 = (size_t)(b * SEQ + c * CHUNKSZ) * DMODEL + hh * HD;

    for (int i = tid; i < 128 * 16; i += 256) {
        int tok = i >> 4, qd = (i & 15) * 4;
        *(float4*)(Qraw + tok * 68 + qd) =
            *(const float4*)(qq_ + row0 + (size_t)tok * DMODEL + qd);
        *(float4*)(Kraw + tok * 68 + qd) =
            *(const float4*)(kk_ + row0 + (size_t)tok * DMODEL + qd);
    }
    for (int i = tid; i < 1024; i += 256) { Scr[i] = Wqf[i]; Scr[1024 + i] = Wkf[i]; }
    __syncthreads();

    {
        int tok = tid & 127, which = tid >> 7;
        const float* raw = which ? Kraw : Qraw;
        const float* W   = Scr + which * 1024;
        float* of        = Scr + 2048 + which * 2048;
        float accf[16];
        #pragma unroll
        for (int cc = 0; cc < 16; cc++) accf[cc] = 0.f;
        for (int e = 0; e < 64; e++) {
            float rv = raw[tok * 68 + e];
            #pragma unroll
            for (int cc = 0; cc < 16; cc++) accf[cc] += rv * W[e * 16 + cc];
        }
        #pragma unroll
        for (int cc = 0; cc < 16; cc++) of[tok * 16 + cc] = accf[cc];
    }
    __syncthreads();
    {
        int tok = tid & 127, which = tid >> 7;
        uint32_t* dst = which ? Ks : Qs;
        write_phi_colmajor_bf(dst, tok, Scr + 2048 + which * 2048 + tok * 16);
    }
    __syncthreads();

    // KV' pack: pairs of feature rows -> one bf16x2 uint
    const float* kvb = ckv + (size_t)bhc * FPAD * 72;
    for (int i = tid; i < 80 * 72; i += 256) {
        int kp = i / 72, n = i % 72;
        KVs[kp * 88 + n] = bf16pack(kvb[(size_t)(2 * kp) * 72 + n],
                                    kvb[(size_t)(2 * kp + 1) * 72 + n]);
    }
    __syncthreads();

    // GEMM2: Y1z = Qphi @ KV'  (k = 160 features = 80 kpairs, 10 k16 steps)
    float accy[9][4];
    #pragma unroll
    for (int ni = 0; ni < 9; ni++)
        #pragma unroll
        for (int e = 0; e < 4; e++) accy[ni][e] = 0.f;
    int m0 = warp * 16;
    for (int kp = 0; kp < 80; kp += 8) {
        uint32_t a0 = Qs[(kp + cq) * 132 + m0 + r];
        uint32_t a1 = Qs[(kp + cq) * 132 + m0 + r + 8];
        uint32_t a2 = Qs[(kp + cq + 4) * 132 + m0 + r];
        uint32_t a3 = Qs[(kp + cq + 4) * 132 + m0 + r + 8];
        #pragma unroll
        for (int ni = 0; ni < 9; ni++) {
            uint32_t b0 = KVs[(kp + cq) * 88 + ni * 8 + r];
            uint32_t b1 = KVs[(kp + cq + 4) * 88 + ni * 8 + r];
            mma16bf(accy[ni], a0, a1, a2, a3, b0, b1);
        }
    }

    // GEMM1: S = Qphi @ Kphi^T (128x128)
    float acc1[4][4][4];
    #pragma unroll
    for (int mi = 0; mi < 4; mi++)
        #pragma unroll
        for (int ni = 0; ni < 4; ni++)
            #pragma unroll
            for (int e = 0; e < 4; e++) acc1[mi][ni][e] = 0.f;
    int wm = (warp >> 2) * 64, wn = (warp & 3) * 32;
    for (int kp = 0; kp < 80; kp += 8) {
        uint32_t af[4][4];
        #pragma unroll
        for (int mi = 0; mi < 4; mi++) {
            int m = wm + mi * 16;
            af[mi][0] = Qs[(kp + cq) * 132 + m + r];
            af[mi][1] = Qs[(kp + cq) * 132 + m + r + 8];
            af[mi][2] = Qs[(kp + cq + 4) * 132 + m + r];
            af[mi][3] = Qs[(kp + cq + 4) * 132 + m + r + 8];
        }
        #pragma unroll
        for (int ni = 0; ni < 4; ni++) {
            uint32_t b0 = Ks[(kp + cq) * 132 + wn + ni * 8 + r];
            uint32_t b1 = Ks[(kp + cq + 4) * 132 + wn + ni * 8 + r];
            #pragma unroll
            for (int mi = 0; mi < 4; mi++)
                mma16bf(acc1[mi][ni], af[mi][0], af[mi][1], af[mi][2], af[mi][3], b0, b1);
        }
    }
    __syncthreads();

    // masked A -> bf16x2 token-pairs (col always even, pair = col,col+1)
    #pragma unroll
    for (int mi = 0; mi < 4; mi++) {
        int row = wm + mi * 16 + r;
        #pragma unroll
        for (int ni = 0; ni < 4; ni++) {
            int col = wn + ni * 8 + 2 * cq;
            float v0 = (col     <= row)     ? acc1[mi][ni][0] : 0.f;
            float v1 = (col + 1 <= row)     ? acc1[mi][ni][1] : 0.f;
            float v2 = (col     <= row + 8) ? acc1[mi][ni][2] : 0.f;
            float v3 = (col + 1 <= row + 8) ? acc1[mi][ni][3] : 0.f;
            Am[(col >> 1) * 132 + row]     = bf16pack(v0, v1);
            Am[(col >> 1) * 132 + row + 8] = bf16pack(v2, v3);
        }
    }
    // V' packed along token pairs via scalar bf16 stores
    {
        __nv_bfloat16* Vb = (__nv_bfloat16*)Vs;
        for (int i = tid; i < 128 * 18; i += 256) {
            int tok = i / 18, qd = (i % 18) * 4;
            float vals[4];
            if (qd < 64) {
                float4 t = *(const float4*)(vv + row0 + (size_t)tok * DMODEL + qd);
                vals[0] = t.x; vals[1] = t.y; vals[2] = t.z; vals[3] = t.w;
            } else {
                #pragma unroll
                for (int e = 0; e < 4; e++) vals[e] = (qd + e == 64) ? 1.f : 0.f;
            }
            #pragma unroll
            for (int e = 0; e < 4; e++)
                Vb[((size_t)(tok >> 1) * 88 + qd + e) * 2 + (tok & 1)] =
                    __float2bfloat16(vals[e]);
        }
    }
    __syncthreads();

    // GEMM3: accy += A @ V'  (k = 128 tokens = 64 spairs, 8 k16 steps)
    for (int sp = 0; sp < 64; sp += 8) {
        uint32_t a0 = Am[(sp + cq) * 132 + m0 + r];
        uint32_t a1 = Am[(sp + cq) * 132 + m0 + r + 8];
        uint32_t a2 = Am[(sp + cq + 4) * 132 + m0 + r];
        uint32_t a3 = Am[(sp + cq + 4) * 132 + m0 + r + 8];
        #pragma unroll
        for (int ni = 0; ni < 9; ni++) {
            uint32_t b0 = Vs[(sp + cq) * 88 + ni * 8 + r];
            uint32_t b1 = Vs[(sp + cq + 4) * 88 + ni * 8 + r];
            mma16bf(accy[ni], a0, a1, a2, a3, b0, b1);
        }
    }

    float zlo = __shfl_sync(0xffffffffu, accy[8][0], lane & 28) + 1e-6f;
    float zhi = __shfl_sync(0xffffffffu, accy[8][2], lane & 28) + 1e-6f;
    float izlo = 1.f / zlo, izhi = 1.f / zhi;
    size_t rowg = (size_t)(b * SEQ + c * CHUNKSZ + m0 + r);
    #pragma unroll
    for (int ni = 0; ni < 8; ni++) {
        int colg = hh * HD + ni * 8 + 2 * cq;
        *(uint32_t*)(catb + rowg * (2 * DMODEL) + colg) =
            bf16pack(accy[ni][0] * izlo, accy[ni][1] * izlo);
        *(uint32_t*)(catb + (rowg + 8) * (2 * DMODEL) + colg) =
            bf16pack(accy[ni][2] * izhi, accy[ni][3] * izhi);
    }
}

// ---------------- sliding-window attention (256 thr, warp-pair) --------------
__global__ __launch_bounds__(256) void swa_v5(const float* __restrict__ q,
        const float* __restrict__ k, const float* __restrict__ v,
        __nv_bfloat16* __restrict__ catb) {
    extern __shared__ uint32_t su[];
    uint32_t* Qs = su;
    uint32_t* Ks = Qs + 64 * 68;
    uint32_t* Ps = Ks + 64 * 132;
    uint32_t* Vs = Ps + 128 * 68;
    float* red   = (float*)(Vs + 128 * 68);
    float* Osm   = (float*)Qs;
    int tid = threadIdx.x, warp = tid >> 5, lane = tid & 31;
    int r = lane >> 2, cq = lane & 3;
    int g = warp & 3, half = warp >> 2;
    int m0 = g * 16;
    int q0 = blockIdx.x * 64, hh = blockIdx.y, b = blockIdx.z;

    for (int i = tid; i < 64 * 16; i += 256) {
        int tok = i >> 4, qd = (i & 15) * 4;
        float4 t = *(const float4*)(q + (size_t)(b * SEQ + q0 + tok) * DMODEL + hh * HD + qd);
        Qs[(qd + 0) * 68 + tok] = __float_as_uint(t.x);
        Qs[(qd + 1) * 68 + tok] = __float_as_uint(t.y);
        Qs[(qd + 2) * 68 + tok] = __float_as_uint(t.z);
        Qs[(qd + 3) * 68 + tok] = __float_as_uint(t.w);
    }
    for (int i = tid; i < 128 * 16; i += 256) {
        int key = i >> 4, qd = (i & 15) * 4;
        int kg = q0 - 64 + key;
        float4 tk = make_float4(0.f, 0.f, 0.f, 0.f);
        float4 tv = make_float4(0.f, 0.f, 0.f, 0.f);
        if (kg >= 0) {
            tk = *(const float4*)(k + (size_t)(b * SEQ + kg) * DMODEL + hh * HD + qd);
            tv = *(const float4*)(v + (size_t)(b * SEQ + kg) * DMODEL + hh * HD + qd);
        }
        Ks[(qd + 0) * 132 + key] = __float_as_uint(tk.x);
        Ks[(qd + 1) * 132 + key] = __float_as_uint(tk.y);
        Ks[(qd + 2) * 132 + key] = __float_as_uint(tk.z);
        Ks[(qd + 3) * 132 + key] = __float_as_uint(tk.w);
        *(uint4*)(Vs + key * 68 + qd) =
            make_uint4(__float_as_uint(tv.x), __float_as_uint(tv.y),
                       __float_as_uint(tv.z), __float_as_uint(tv.w));
    }
    __syncthreads();

    float acc[8][4];
    #pragma unroll
    for (int ni = 0; ni < 8; ni++)
        #pragma unroll
        for (int e = 0; e < 4; e++) acc[ni][e] = 0.f;
    for (int kk = 0; kk < 64; kk += 8) {
        uint32_t a0 = Qs[(kk + cq) * 68 + m0 + r];
        uint32_t a1 = Qs[(kk + cq) * 68 + m0 + r + 8];
        uint32_t a2 = Qs[(kk + cq + 4) * 68 + m0 + r];
        uint32_t a3 = Qs[(kk + cq + 4) * 68 + m0 + r + 8];
        #pragma unroll
        for (int ni = 0; ni < 8; ni++) {
            int gn = half * 8 + ni;
            uint32_t b0 = Ks[(kk + cq) * 132 + gn * 8 + r];
            uint32_t b1 = Ks[(kk + cq + 4) * 132 + gn * 8 + r];
            mma8(acc[ni], a0, a1, a2, a3, b0, b1);
        }
    }

    int rowlo = m0 + r, rowhi = rowlo + 8;
    float mlo = -1e30f, mhi = -1e30f;
    #pragma unroll
    for (int ni = 0; ni < 8; ni++) {
        int n = (half * 8 + ni) * 8 + 2 * cq;
        bool ok0l = (n     >= rowlo) && (n     <= rowlo + 64) && (q0 - 64 + n     >= 0);
        bool ok1l = (n + 1 >= rowlo) && (n + 1 <= rowlo + 64) && (q0 - 64 + n + 1 >= 0);
        bool ok0h = (n     >= rowhi) && (n     <= rowhi + 64) && (q0 - 64 + n     >= 0);
        bool ok1h = (n + 1 >= rowhi) && (n + 1 <= rowhi + 64) && (q0 - 64 + n + 1 >= 0);
        acc[ni][0] = ok0l ? acc[ni][0] * 0.125f : -1e30f;
        acc[ni][1] = ok1l ? acc[ni][1] * 0.125f : -1e30f;
        acc[ni][2] = ok0h ? acc[ni][2] * 0.125f : -1e30f;
        acc[ni][3] = ok1h ? acc[ni][3] * 0.125f : -1e30f;
        mlo = fmaxf(mlo, fmaxf(acc[ni][0], acc[ni][1]));
        mhi = fmaxf(mhi, fmaxf(acc[ni][2], acc[ni][3]));
    }
    mlo = fmaxf(mlo, __shfl_xor_sync(0xffffffffu, mlo, 1));
    mlo = fmaxf(mlo, __shfl_xor_sync(0xffffffffu, mlo, 2));
    mhi = fmaxf(mhi, __shfl_xor_sync(0xffffffffu, mhi, 1));
    mhi = fmaxf(mhi, __shfl_xor_sync(0xffffffffu, mhi, 2));
    if (cq == 0) {
        red[rowlo * 2 + half] = mlo;
        red[rowhi * 2 + half] = mhi;
    }
    __syncthreads();
    float Mlo = fmaxf(red[rowlo * 2], red[rowlo * 2 + 1]);
    float Mhi = fmaxf(red[rowhi * 2], red[rowhi * 2 + 1]);

    float slo = 0.f, shi = 0.f;
    #pragma unroll
    for (int ni = 0; ni < 8; ni++) {
        acc[ni][0] = __expf(acc[ni][0] - Mlo);
        acc[ni][1] = __expf(acc[ni][1] - Mlo);
        acc[ni][2] = __expf(acc[ni][2] - Mhi);
        acc[ni][3] = __expf(acc[ni][3] - Mhi);
        slo += acc[ni][0] + acc[ni][1];
        shi += acc[ni][2] + acc[ni][3];
    }
    slo += __shfl_xor_sync(0xffffffffu, slo, 1);
    slo += __shfl_xor_sync(0xffffffffu, slo, 2);
    shi += __shfl_xor_sync(0xffffffffu, shi, 1);
    shi += __shfl_xor_sync(0xffffffffu, shi, 2);
    if (cq == 0) {
        red[128 + rowlo * 2 + half] = slo;
        red[128 + rowhi * 2 + half] = shi;
    }

    #pragma unroll
    for (int ni = 0; ni < 8; ni++) {
        int n = (half * 8 + ni) * 8 + 2 * cq;
        Ps[n * 68 + rowlo]       = __float_as_uint(acc[ni][0]);
        Ps[(n + 1) * 68 + rowlo] = __float_as_uint(acc[ni][1]);
        Ps[n * 68 + rowhi]       = __float_as_uint(acc[ni][2]);
        Ps[(n + 1) * 68 + rowhi] = __float_as_uint(acc[ni][3]);
    }
    __syncthreads();
    float sumlo = red[128 + rowlo * 2] + red[128 + rowlo * 2 + 1];
    float sumhi = red[128 + rowhi * 2] + red[128 + rowhi * 2 + 1];

    float accO[8][4];
    #pragma unroll
    for (int ni = 0; ni < 8; ni++)
        #pragma unroll
        for (int e = 0; e < 4; e++) accO[ni][e] = 0.f;
    for (int ks = 0; ks < 64; ks += 8) {
        int kk = half * 64 + ks;
        uint32_t a0 = Ps[(kk + cq) * 68 + m0 + r];
        uint32_t a1 = Ps[(kk + cq) * 68 + m0 + r + 8];
        uint32_t a2 = Ps[(kk + cq + 4) * 68 + m0 + r];
        uint32_t a3 = Ps[(kk + cq + 4) * 68 + m0 + r + 8];
        #pragma unroll
        for (int ni = 0; ni < 8; ni++) {
            uint32_t b0 = Vs[(kk + cq) * 68 + ni * 8 + r];
            uint32_t b1 = Vs[(kk + cq + 4) * 68 + ni * 8 + r];
            mma8(accO[ni], a0, a1, a2, a3, b0, b1);
        }
    }
    if (half == 1) {
        #pragma unroll
        for (int ni = 0; ni < 8; ni++) {
            int n = ni * 8 + 2 * cq;
            Osm[rowlo * 68 + n]     = accO[ni][0];
            Osm[rowlo * 68 + n + 1] = accO[ni][1];
            Osm[rowhi * 68 + n]     = accO[ni][2];
            Osm[rowhi * 68 + n + 1] = accO[ni][3];
        }
    }
    __syncthreads();
    if (half == 0) {
        float izlo = 1.f / sumlo, izhi = 1.f / sumhi;
        #pragma unroll
        for (int ni = 0; ni < 8; ni++) {
            int n = ni * 8 + 2 * cq;
            int colg = DMODEL + hh * HD + n;
            *(uint32_t*)(catb + (size_t)(b * SEQ + q0 + rowlo) * (2 * DMODEL) + colg) =
                bf16pack((accO[ni][0] + Osm[rowlo * 68 + n]) * izlo,
                         (accO[ni][1] + Osm[rowlo * 68 + n + 1]) * izlo);
            *(uint32_t*)(catb + (size_t)(b * SEQ + q0 + rowhi) * (2 * DMODEL) + colg) =
                bf16pack((accO[ni][2] + Osm[rowhi * 68 + n]) * izhi,
                         (accO[ni][3] + Osm[rowhi * 68 + n + 1]) * izhi);
        }
    }
}

// ---------------------------------- launch -----------------------------------
extern "C" void kernel_launch(void* const* d_in, const int* in_sizes, int n_in,
                              void* d_out, int out_size) {
    const float* x      = (const float*)d_in[0];
    const float* norm_w = (const float*)d_in[1];
    const float* Wq     = (const float*)d_in[2];
    const float* Wk     = (const float*)d_in[3];
    const float* Wv     = (const float*)d_in[4];
    const float* Wqf    = (const float*)d_in[5];
    const float* Wkf    = (const float*)d_in[6];
    const float* Wout   = (const float*)d_in[7];
    float* out = (float*)d_out;

    __nv_bfloat16 *hb, *wqt, *wkt, *wvt, *woutt, *catb;
    float *q, *k, *v, *ckv2, *ckv;
    cudaGetSymbolAddress((void**)&hb,    g_hb);
    cudaGetSymbolAddress((void**)&wqt,   g_wqt);
    cudaGetSymbolAddress((void**)&wkt,   g_wkt);
    cudaGetSymbolAddress((void**)&wvt,   g_wvt);
    cudaGetSymbolAddress((void**)&woutt, g_woutt);
    cudaGetSymbolAddress((void**)&catb,  g_catb);
    cudaGetSymbolAddress((void**)&q,     g_q);
    cudaGetSymbolAddress((void**)&k,     g_k);
    cudaGetSymbolAddress((void**)&v,     g_v);
    cudaGetSymbolAddress((void**)&ckv2,  g_ckv2);
    cudaGetSymbolAddress((void**)&ckv,   g_ckv);

    const int smemG   = NSTAGEB * (ASB_ELE + BSB_ELE) * 4;              // 81920
    const int smemKV  = (64 * 164 + 64 * 88) * 4;                       // 64512
    const int smemLin = (80 * 132 * 2 + 80 * 88) * 4;                   // 112640
    const int smemSWA = (64 * 68 + 64 * 132 + 128 * 68 + 128 * 68) * 4 + 256 * 4;

    static cudaStream_t s2 = nullptr;
    static cudaEvent_t ev_root = nullptr, ev_w = nullptr, ev_fork = nullptr, ev_join = nullptr;
    static bool attrs_set = false;
    if (!attrs_set) {
        cudaFuncSetAttribute(gemmb,       cudaFuncAttributeMaxDynamicSharedMemorySize, smemG);
        cudaFuncSetAttribute(gemmb_qkv,   cudaFuncAttributeMaxDynamicSharedMemorySize, smemG);
        cudaFuncSetAttribute(chunk_kv_v5, cudaFuncAttributeMaxDynamicSharedMemorySize, smemKV);
        cudaFuncSetAttribute(lin_attn_v6, cudaFuncAttributeMaxDynamicSharedMemorySize, smemLin);
        cudaFuncSetAttribute(swa_v5,      cudaFuncAttributeMaxDynamicSharedMemorySize, smemSWA);
        cudaStreamCreateWithFlags(&s2, cudaStreamNonBlocking);
        cudaEventCreateWithFlags(&ev_root, cudaEventDisableTiming);
        cudaEventCreateWithFlags(&ev_w,    cudaEventDisableTiming);
        cudaEventCreateWithFlags(&ev_fork, cudaEventDisableTiming);
        cudaEventCreateWithFlags(&ev_join, cudaEventDisableTiming);
        attrs_set = true;
    }

    // fork s2 from the capture-origin stream BEFORE any s2 work (capture-legal)
    cudaEventRecord(ev_root, 0);
    cudaStreamWaitEvent(s2, ev_root, 0);

    // weight transposes (s2) overlap rmsnorm (s0)
    transpose_bf16<<<dim3(32, 32), 256, 0, s2>>>(Wq, wqt, DMODEL, DMODEL);
    transpose_bf16<<<dim3(32, 32), 256, 0, s2>>>(Wk, wkt, DMODEL, DMODEL);
    transpose_bf16<<<dim3(32, 32), 256, 0, s2>>>(Wv, wvt, DMODEL, DMODEL);
    transpose_bf16<<<dim3(32, 64), 256, 0, s2>>>(Wout, woutt, 2 * DMODEL, DMODEL);
    cudaEventRecord(ev_w, s2);

    rmsnorm_kernel<<<ROWS, 256>>>(x, norm_w, hb);
    cudaStreamWaitEvent(0, ev_w, 0);

    gemmb_qkv<<<dim3(DMODEL / 128, ROWS / 128, 3), 256, smemG>>>(hb, wqt, wkt, wvt, q, k, v);

    // fork: SWA runs concurrently with the linear-attention chain
    cudaEventRecord(ev_fork, 0);
    cudaStreamWaitEvent(s2, ev_fork, 0);
    swa_v5<<<dim3(SEQ / 64, NH, BATCH), 256, smemSWA, s2>>>(q, k, v, catb);
    cudaEventRecord(ev_join, s2);

    chunk_kv_v5<<<BATCH * NH * NCHUNK * 2, 320, smemKV>>>(k, v, Wkf, ckv2);
    prefix_kv_v3<<<(32 * FPAD * 72 + 255) / 256, 256>>>(ckv2, ckv);
    lin_attn_v6<<<BATCH * NH * NCHUNK, 256, smemLin>>>(q, k, v, Wqf, Wkf, ckv, catb);

    cudaStreamWaitEvent(0, ev_join, 0);

    gemmb<<<dim3(DMODEL / 128, ROWS / 128), 256, smemG>>>(catb, woutt, out, x, 2 * DMODEL, DMODEL);
}

// round 15
// speedup vs baseline: 1.4278x; 1.0058x over previous
#include <cuda_runtime.h>
#include <cuda_bf16.h>
#include <cstdint>

#define BATCH 2
#define SEQ 2048
#define DMODEL 1024
#define NH 16
#define HD 64
#define FEAT 16
#define FDIM 153           // 1 + 16 + 136
#define FPAD 160
#define NCHUNK 16
#define CHUNKSZ 128
#define ROWS (BATCH*SEQ)          // 4096
#define HROWS (BATCH*SEQ*NH)      // 131072
#define FPH (FPAD/2)              // 80 feature pairs

// ------------------------- scratch (static device memory) -------------------
__device__ __nv_bfloat16 g_hb[ROWS*DMODEL];
__device__ __nv_bfloat16 g_wqt[DMODEL*DMODEL];
__device__ __nv_bfloat16 g_wkt[DMODEL*DMODEL];
__device__ __nv_bfloat16 g_wvt[DMODEL*DMODEL];
__device__ __nv_bfloat16 g_woutt[DMODEL*2*DMODEL];
__device__ __nv_bfloat16 g_catb[(size_t)ROWS*2*DMODEL];
__device__ float g_q[ROWS*DMODEL];
__device__ float g_k[ROWS*DMODEL];
__device__ float g_v[ROWS*DMODEL];
__device__ float g_ckv2[(size_t)BATCH*NH*NCHUNK*2*FPAD*72];
__device__ uint32_t g_ckvb[(size_t)BATCH*NH*NCHUNK*FPH*72];   // bf16x2 feature pairs

__device__ __forceinline__ void mma16bf(float acc[4], uint32_t a0, uint32_t a1,
                                        uint32_t a2, uint32_t a3,
                                        uint32_t b0, uint32_t b1) {
    asm volatile(
        "mma.sync.aligned.m16n8k16.row.col.f32.bf16.bf16.f32 "
        "{%0,%1,%2,%3}, {%4,%5,%6,%7}, {%8,%9}, {%0,%1,%2,%3};"
        : "+f"(acc[0]), "+f"(acc[1]), "+f"(acc[2]), "+f"(acc[3])
        : "r"(a0), "r"(a1), "r"(a2), "r"(a3), "r"(b0), "r"(b1));
}

__device__ __forceinline__ void mma8(float acc[4], uint32_t a0, uint32_t a1,
                                     uint32_t a2, uint32_t a3,
                                     uint32_t b0, uint32_t b1) {
    asm volatile(
        "mma.sync.aligned.m16n8k8.row.col.f32.tf32.tf32.f32 "
        "{%0,%1,%2,%3}, {%4,%5,%6,%7}, {%8,%9}, {%0,%1,%2,%3};"
        : "+f"(acc[0]), "+f"(acc[1]), "+f"(acc[2]), "+f"(acc[3])
        : "r"(a0), "r"(a1), "r"(a2), "r"(a3), "r"(b0), "r"(b1));
}

__device__ __forceinline__ void cp16(uint32_t sdst, const void* gsrc) {
    asm volatile("cp.async.cg.shared.global [%0], [%1], 16;" :: "r"(sdst), "l"(gsrc));
}

__device__ __forceinline__ uint32_t bf16pack(float lo, float hi) {
    uint32_t u;
    asm("cvt.rn.bf16x2.f32 %0, %1, %2;" : "=r"(u) : "f"(hi), "f"(lo));
    return u;
}

// phi expansion -> bf16x2-packed col-major (feature pairs): dst[(f>>1)*132 + tok]
__device__ __forceinline__ void write_phi_colmajor_bf(uint32_t* dst, int tok,
                                                      const float* xf) {
    float x[16];
    #pragma unroll
    for (int i = 0; i < 16; i++) x[i] = xf[i];
    const float inv = 0.70710678118654752440f;
    float pend = 0.f;
    #define PHI_EMIT(IDX, V) { if ((IDX) & 1) dst[((IDX) >> 1) * 132 + tok] = bf16pack(pend, (V)); else pend = (V); }
    PHI_EMIT(0, 1.f);
    #pragma unroll
    for (int i = 0; i < 16; i++) PHI_EMIT(1 + i, x[i]);
    int idx = 17;
    #pragma unroll
    for (int i = 0; i < 16; i++) {
        PHI_EMIT(idx, 0.5f * x[i] * x[i]); idx++;
        #pragma unroll
        for (int j = i + 1; j < 16; j++) { PHI_EMIT(idx, inv * x[i] * x[j]); idx++; }
    }
    #pragma unroll
    for (int f = FDIM; f < FPAD; f++) PHI_EMIT(f, 0.f);
    #undef PHI_EMIT
}

// phi expansion -> bf16 [feature][token] layout (stride 72 bf16), half-split
__device__ __forceinline__ void write_phi_ftok_half(__nv_bfloat16* dstb, int tok,
                                                    const float* xf, int h) {
    float x[16];
    #pragma unroll
    for (int i = 0; i < 16; i++) x[i] = xf[i];
    const float inv = 0.70710678118654752440f;
    #define EMITF(F, V) dstb[(F) * 72 + tok] = __float2bfloat16(V)
    if (h == 0) {
        EMITF(0, 1.f);
        #pragma unroll
        for (int i = 0; i < 16; i += 2) {
            int idx = 17 + i * 16 - (i * (i - 1)) / 2;
            EMITF(idx, 0.5f * x[i] * x[i]); idx++;
            #pragma unroll
            for (int j = i + 1; j < 16; j++) { EMITF(idx, inv * x[i] * x[j]); idx++; }
        }
        #pragma unroll
        for (int f = FDIM; f < FPAD; f++) EMITF(f, 0.f);
    } else {
        #pragma unroll
        for (int i = 0; i < 16; i++) EMITF(1 + i, x[i]);
        #pragma unroll
        for (int i = 1; i < 16; i += 2) {
            int idx = 17 + i * 16 - (i * (i - 1)) / 2;
            EMITF(idx, 0.5f * x[i] * x[i]); idx++;
            #pragma unroll
            for (int j = i + 1; j < 16; j++) { EMITF(idx, inv * x[i] * x[j]); idx++; }
        }
    }
    #undef EMITF
}

// ---------------- weight transpose + fp32->bf16 convert ----------------------
__global__ void transpose_bf16(const float* __restrict__ W, __nv_bfloat16* __restrict__ Wt,
                               int K, int N) {
    __shared__ float tile[32][33];
    int n0 = blockIdx.x * 32, k0 = blockIdx.y * 32;
    int tx = threadIdx.x & 31, ty = threadIdx.x >> 5;
    #pragma unroll
    for (int j = 0; j < 32; j += 8)
        tile[ty + j][tx] = W[(size_t)(k0 + ty + j) * N + n0 + tx];
    __syncthreads();
    #pragma unroll
    for (int j = 0; j < 32; j += 8)
        Wt[(size_t)(n0 + ty + j) * K + k0 + tx] = __float2bfloat16(tile[tx][ty + j]);
}

// ------------------------- RMSNorm (float4 in, bf16 out) ---------------------
__global__ void rmsnorm_kernel(const float* __restrict__ x,
                               const float* __restrict__ w,
                               __nv_bfloat16* __restrict__ hb) {
    int row = blockIdx.x;
    const float4* xr = (const float4*)(x + (size_t)row * DMODEL);
    float4 t = xr[threadIdx.x];
    float s = t.x * t.x + t.y * t.y + t.z * t.z + t.w * t.w;
    __shared__ float red[8];
    #pragma unroll
    for (int o = 16; o > 0; o >>= 1) s += __shfl_xor_sync(0xffffffffu, s, o);
    if ((threadIdx.x & 31) == 0) red[threadIdx.x >> 5] = s;
    __syncthreads();
    if (threadIdx.x < 8) {
        float v = red[threadIdx.x];
        #pragma unroll
        for (int o = 4; o > 0; o >>= 1) v += __shfl_xor_sync(0xffu, v, o);
        if (threadIdx.x == 0) red[0] = v;
    }
    __syncthreads();
    float rs = rsqrtf(red[0] / (float)DMODEL + 1e-6f);
    float4 wv = ((const float4*)w)[threadIdx.x];
    uint32_t p0 = bf16pack(t.x * rs * wv.x, t.y * rs * wv.y);
    uint32_t p1 = bf16pack(t.z * rs * wv.z, t.w * rs * wv.w);
    ((uint2*)(hb + (size_t)row * DMODEL))[threadIdx.x] = make_uint2(p0, p1);
}

// ---------------- BF16 GEMM: cp.async 4-stage, k-tile 32, m16n8k16 ------------
#define ASB_ELE (128*20)
#define BSB_ELE (128*20)
#define NSTAGEB 4

__device__ __forceinline__ void gemmb_issue(const __nv_bfloat16* A, const __nv_bfloat16* Bt,
        uint32_t* As, uint32_t* Bs, int bm, int bn, int k0, int K, int tid) {
    #pragma unroll
    for (int j = 0; j < 2; j++) {
        int c = tid + j * 256;
        int m = c >> 2, seg = c & 3;
        cp16((uint32_t)__cvta_generic_to_shared(As + m * 20 + seg * 4),
             A + (size_t)(bm + m) * K + k0 + seg * 8);
    }
    #pragma unroll
    for (int j = 0; j < 2; j++) {
        int c = tid + j * 256;
        int n = c >> 2, seg = c & 3;
        cp16((uint32_t)__cvta_generic_to_shared(Bs + n * 20 + seg * 4),
             Bt + (size_t)(bn + n) * K + k0 + seg * 8);
    }
}

__device__ __forceinline__ void gemmb_core(const __nv_bfloat16* A, const __nv_bfloat16* Bt,
        float* C, const float* residual, uint32_t* As, uint32_t* Bs,
        int bm, int bn, int K, int N, int tid) {
    int warp = tid >> 5, lane = tid & 31;
    int wm = (warp >> 2) * 64, wn = (warp & 3) * 32;
    int r = lane >> 2, cq = lane & 3;

    float acc[4][4][4];
    #pragma unroll
    for (int mi = 0; mi < 4; mi++)
        #pragma unroll
        for (int ni = 0; ni < 4; ni++)
            #pragma unroll
            for (int e = 0; e < 4; e++) acc[mi][ni][e] = 0.f;

    int nk = K / 32;
    gemmb_issue(A, Bt, As, Bs, bm, bn, 0, K, tid);
    asm volatile("cp.async.commit_group;");
    gemmb_issue(A, Bt, As + ASB_ELE, Bs + BSB_ELE, bm, bn, 32, K, tid);
    asm volatile("cp.async.commit_group;");
    gemmb_issue(A, Bt, As + 2 * ASB_ELE, Bs + 2 * BSB_ELE, bm, bn, 64, K, tid);
    asm volatile("cp.async.commit_group;");

    for (int kt = 0; kt < nk; kt++) {
        if (kt + 3 < nk) {
            int slot = (kt + 3) & 3;
            gemmb_issue(A, Bt, As + slot * ASB_ELE, Bs + slot * BSB_ELE,
                        bm, bn, (kt + 3) * 32, K, tid);
        }
        asm volatile("cp.async.commit_group;");
        asm volatile("cp.async.wait_group 3;");
        __syncthreads();
        const uint32_t* Au = As + (kt & 3) * ASB_ELE;
        const uint32_t* Bu = Bs + (kt & 3) * BSB_ELE;
        #pragma unroll
        for (int ks = 0; ks < 16; ks += 8) {
            uint32_t af[4][4], bf[4][2];
            #pragma unroll
            for (int mi = 0; mi < 4; mi++) {
                int m = wm + mi * 16 + r;
                af[mi][0] = Au[m * 20 + ks + cq];
                af[mi][1] = Au[(m + 8) * 20 + ks + cq];
                af[mi][2] = Au[m * 20 + ks + cq + 4];
                af[mi][3] = Au[(m + 8) * 20 + ks + cq + 4];
            }
            #pragma unroll
            for (int ni = 0; ni < 4; ni++) {
                int n = wn + ni * 8 + r;
                bf[ni][0] = Bu[n * 20 + ks + cq];
                bf[ni][1] = Bu[n * 20 + ks + cq + 4];
            }
            #pragma unroll
            for (int mi = 0; mi < 4; mi++)
                #pragma unroll
                for (int ni = 0; ni < 4; ni++)
                    mma16bf(acc[mi][ni], af[mi][0], af[mi][1], af[mi][2], af[mi][3],
                            bf[ni][0], bf[ni][1]);
        }
        __syncthreads();
    }

    #pragma unroll
    for (int mi = 0; mi < 4; mi++) {
        int row0 = bm + wm + mi * 16 + r;
        #pragma unroll
        for (int ni = 0; ni < 4; ni++) {
            int col = bn + wn + ni * 8 + 2 * cq;
            float2 lo = make_float2(acc[mi][ni][0], acc[mi][ni][1]);
            float2 hi = make_float2(acc[mi][ni][2], acc[mi][ni][3]);
            if (residual) {
                float2 r0 = *(const float2*)(residual + (size_t)row0 * N + col);
                float2 r1 = *(const float2*)(residual + (size_t)(row0 + 8) * N + col);
                lo.x += r0.x; lo.y += r0.y; hi.x += r1.x; hi.y += r1.y;
            }
            *(float2*)(C + (size_t)row0 * N + col) = lo;
            *(float2*)(C + (size_t)(row0 + 8) * N + col) = hi;
        }
    }
}

__global__ __launch_bounds__(256) void gemmb(
        const __nv_bfloat16* __restrict__ A, const __nv_bfloat16* __restrict__ Bt,
        float* __restrict__ C, const float* __restrict__ residual, int K, int N) {
    extern __shared__ uint32_t sgb[];
    gemmb_core(A, Bt, C, residual, sgb, sgb + NSTAGEB * ASB_ELE,
               blockIdx.y * 128, blockIdx.x * 128, K, N, threadIdx.x);
}

__global__ __launch_bounds__(256) void gemmb_qkv(
        const __nv_bfloat16* __restrict__ A,
        const __nv_bfloat16* __restrict__ Bq, const __nv_bfloat16* __restrict__ Bk,
        const __nv_bfloat16* __restrict__ Bv,
        float* __restrict__ Cq, float* __restrict__ Ck, float* __restrict__ Cv) {
    extern __shared__ uint32_t sgb[];
    const __nv_bfloat16* Bt = (blockIdx.z == 0) ? Bq : (blockIdx.z == 1) ? Bk : Bv;
    float* C = (blockIdx.z == 0) ? Cq : (blockIdx.z == 1) ? Ck : Cv;
    gemmb_core(A, Bt, C, nullptr, sgb, sgb + NSTAGEB * ASB_ELE,
               blockIdx.y * 128, blockIdx.x * 128, DMODEL, DMODEL, threadIdx.x);
}

// --------- pass A: half-chunk fused feat-proj + phi + partial KV' (bf16) ------
// Ks2: bf16 [feat 160][tok 72-stride] (=36 uints/row). Vs2: bf16 [d 72][tok].
__global__ __launch_bounds__(320) void chunk_kv_v6(const float* __restrict__ kk_,
        const float* __restrict__ vv, const float* __restrict__ Wkf,
        float* __restrict__ ckv2) {
    extern __shared__ uint32_t su[];
    uint32_t* Ks2 = su;             // [160][36] uints
    uint32_t* Vs2 = su + 160 * 36;  // [72][36] uints
    float* Kf = (float*)Ks2;        // overlay: raw k tile [64][68] floats (17KB <= 23KB)
    float* Sf = (float*)Vs2;        // overlay: W [1024] + kf [1024] floats (8KB <= 10.3KB)
    int tid = threadIdx.x, warp = tid >> 5, lane = tid & 31;
    int r = lane >> 2, cq = lane & 3;
    int bid = blockIdx.x;
    int half = bid & 1, bhc = bid >> 1;
    int c = bhc & 15, bh = bhc >> 4, b = bh >> 4, hh = bh & 15;
    size_t row0 = (size_t)(b * SEQ + c * CHUNKSZ + half * 64) * DMODEL + hh * HD;

    for (int i = tid; i < 64 * 16; i += 320) {
        int tok = i >> 4, qd = (i & 15) * 4;
        float4 t = *(const float4*)(kk_ + row0 + (size_t)tok * DMODEL + qd);
        *(float4*)(Kf + tok * 68 + qd) = t;
    }
    for (int i = tid; i < 1024; i += 320) Sf[i] = Wkf[i];
    __syncthreads();

    if (tid < 256) {                 // feat-proj: 4 threads/token, 4 cols each
        int tok = tid >> 2, qm = (tid & 3) * 4;
        float accf[4];
        #pragma unroll
        for (int cc = 0; cc < 4; cc++) accf[cc] = 0.f;
        for (int e = 0; e < 64; e++) {
            float rv = Kf[tok * 68 + e];
            #pragma unroll
            for (int cc = 0; cc < 4; cc++) accf[cc] += rv * Sf[e * 16 + qm + cc];
        }
        #pragma unroll
        for (int cc = 0; cc < 4; cc++) Sf[1024 + tok * 16 + qm + cc] = accf[cc];
    }
    __syncthreads();
    if (tid < 128) {
        int tok = tid >> 1, hm = tid & 1;
        write_phi_ftok_half((__nv_bfloat16*)Ks2, tok, Sf + 1024 + tok * 16, hm);
    }
    __syncthreads();

    // V' bf16 [d][tok] (d 0..71: 64 V dims + ones col 64 + zeros)
    {
        __nv_bfloat16* Vb = (__nv_bfloat16*)Vs2;
        for (int i = tid; i < 64 * 18; i += 320) {
            int tok = i / 18, qd = (i % 18) * 4;
            float vals[4];
            if (qd < 64) {
                float4 t = *(const float4*)(vv + row0 + (size_t)tok * DMODEL + qd);
                vals[0] = t.x; vals[1] = t.y; vals[2] = t.z; vals[3] = t.w;
            } else {
                #pragma unroll
                for (int e = 0; e < 4; e++) vals[e] = (qd + e == 64) ? 1.f : 0.f;
            }
            #pragma unroll
            for (int e = 0; e < 4; e++)
                Vb[(qd + e) * 72 + tok] = __float2bfloat16(vals[e]);
        }
    }
    __syncthreads();

    // KV' = Kphi^T @ [V|1]: m = 160 feats (10 warps x 16), n = 72, k = 64 tokens
    float acc[9][4];
    #pragma unroll
    for (int ni = 0; ni < 9; ni++)
        #pragma unroll
        for (int e = 0; e < 4; e++) acc[ni][e] = 0.f;
    int m0 = warp * 16;
    for (int kp = 0; kp < 32; kp += 8) {     // 32 token-pairs, 4 k16 steps
        uint32_t a0 = Ks2[(m0 + r) * 36 + kp + cq];
        uint32_t a1 = Ks2[(m0 + r + 8) * 36 + kp + cq];
        uint32_t a2 = Ks2[(m0 + r) * 36 + kp + cq + 4];
        uint32_t a3 = Ks2[(m0 + r + 8) * 36 + kp + cq + 4];
        #pragma unroll
        for (int ni = 0; ni < 9; ni++) {
            uint32_t b0 = Vs2[(ni * 8 + r) * 36 + kp + cq];
            uint32_t b1 = Vs2[(ni * 8 + r) * 36 + kp + cq + 4];
            mma16bf(acc[ni], a0, a1, a2, a3, b0, b1);
        }
    }
    float* outb = ckv2 + (size_t)bid * FPAD * 72;
    #pragma unroll
    for (int ni = 0; ni < 9; ni++) {
        int n = ni * 8 + 2 * cq;
        *(float2*)(outb + (m0 + r) * 72 + n)     = make_float2(acc[ni][0], acc[ni][1]);
        *(float2*)(outb + (m0 + r + 8) * 72 + n) = make_float2(acc[ni][2], acc[ni][3]);
    }
}

// --------- pass B: exclusive prefix over chunks -> bf16x2 feature pairs -------
__global__ void prefix_kv_v4(const float* __restrict__ ckv2, uint32_t* __restrict__ ckvb) {
    const int FD = FPAD * 72;       // fp32 partial stride
    const int PD = FPH * 72;        // packed stride
    int idx = blockIdx.x * 256 + threadIdx.x;
    if (idx >= 32 * PD) return;
    int bh = idx / PD, e = idx % PD;
    int fp = e / 72, n = e % 72;
    size_t o0 = (size_t)(2 * fp) * 72 + n;
    size_t o1 = o0 + 72;
    float run0 = 0.f, run1 = 0.f;
    for (int c = 0; c < NCHUNK; c++) {
        size_t bc = (size_t)(bh * NCHUNK + c);
        ckvb[bc * PD + e] = bf16pack(run0, run1);
        run0 += ckv2[(bc * 2) * FD + o0] + ckv2[(bc * 2 + 1) * FD + o0];
        run1 += ckv2[(bc * 2) * FD + o1] + ckv2[(bc * 2 + 1) * FD + o1];
    }
}

// --------- pass C: fused feat-proj + phi + linear attention (bf16 mma) --------
__global__ __launch_bounds__(256) void lin_attn_v6(const float* __restrict__ qq_,
        const float* __restrict__ kk_, const float* __restrict__ vv,
        const float* __restrict__ Wqf, const float* __restrict__ Wkf,
        const uint32_t* __restrict__ ckvb, __nv_bfloat16* __restrict__ catb) {
    extern __shared__ uint32_t su[];
    uint32_t* Qs  = su;                  // [kp 80][132]
    uint32_t* Ks  = su + 80 * 132;       // [kp 80][132]
    uint32_t* KVs = Ks + 80 * 132;       // [kp 80][88]
    uint32_t* Am  = Ks;                  // overlay [sp 64][132]
    uint32_t* Vs  = Ks + 64 * 132;       // overlay [sp 64][88]
    float* Qraw = (float*)Qs;
    float* Kraw = (float*)Ks;
    float* Scr  = (float*)KVs;
    int tid = threadIdx.x, warp = tid >> 5, lane = tid & 31;
    int r = lane >> 2, cq = lane & 3;
    int bhc = blockIdx.x, c = bhc & 15, bh = bhc >> 4, b = bh >> 4, hh = bh & 15;
    size_t row0 = (size_t)(b * SEQ + c * CHUNKSZ) * DMODEL + hh * HD;

    for (int i = tid; i < 128 * 16; i += 256) {
        int tok = i >> 4, qd = (i & 15) * 4;
        *(float4*)(Qraw + tok * 68 + qd) =
            *(const float4*)(qq_ + row0 + (size_t)tok * DMODEL + qd);
        *(float4*)(Kraw + tok * 68 + qd) =
            *(const float4*)(kk_ + row0 + (size_t)tok * DMODEL + qd);
    }
    for (int i = tid; i < 1024; i += 256) { Scr[i] = Wqf[i]; Scr[1024 + i] = Wkf[i]; }
    __syncthreads();

    {
        int tok = tid & 127, which = tid >> 7;
        const float* raw = which ? Kraw : Qraw;
        const float* W   = Scr + which * 1024;
        float* of        = Scr + 2048 + which * 2048;
        float accf[16];
        #pragma unroll
        for (int cc = 0; cc < 16; cc++) accf[cc] = 0.f;
        for (int e = 0; e < 64; e++) {
            float rv = raw[tok * 68 + e];
            #pragma unroll
            for (int cc = 0; cc < 16; cc++) accf[cc] += rv * W[e * 16 + cc];
        }
        #pragma unroll
        for (int cc = 0; cc < 16; cc++) of[tok * 16 + cc] = accf[cc];
    }
    __syncthreads();
    {
        int tok = tid & 127, which = tid >> 7;
        uint32_t* dst = which ? Ks : Qs;
        write_phi_colmajor_bf(dst, tok, Scr + 2048 + which * 2048 + tok * 16);
    }
    __syncthreads();

    // KV' already bf16x2-packed: straight copy
    const uint32_t* kvb = ckvb + (size_t)bhc * FPH * 72;
    for (int i = tid; i < 80 * 72; i += 256) {
        int kp = i / 72, n = i % 72;
        KVs[kp * 88 + n] = kvb[kp * 72 + n];
    }
    __syncthreads();

    float accy[9][4];
    #pragma unroll
    for (int ni = 0; ni < 9; ni++)
        #pragma unroll
        for (int e = 0; e < 4; e++) accy[ni][e] = 0.f;
    int m0 = warp * 16;
    for (int kp = 0; kp < 80; kp += 8) {
        uint32_t a0 = Qs[(kp + cq) * 132 + m0 + r];
        uint32_t a1 = Qs[(kp + cq) * 132 + m0 + r + 8];
        uint32_t a2 = Qs[(kp + cq + 4) * 132 + m0 + r];
        uint32_t a3 = Qs[(kp + cq + 4) * 132 + m0 + r + 8];
        #pragma unroll
        for (int ni = 0; ni < 9; ni++) {
            uint32_t b0 = KVs[(kp + cq) * 88 + ni * 8 + r];
            uint32_t b1 = KVs[(kp + cq + 4) * 88 + ni * 8 + r];
            mma16bf(accy[ni], a0, a1, a2, a3, b0, b1);
        }
    }

    float acc1[4][4][4];
    #pragma unroll
    for (int mi = 0; mi < 4; mi++)
        #pragma unroll
        for (int ni = 0; ni < 4; ni++)
            #pragma unroll
            for (int e = 0; e < 4; e++) acc1[mi][ni][e] = 0.f;
    int wm = (warp >> 2) * 64, wn = (warp & 3) * 32;
    for (int kp = 0; kp < 80; kp += 8) {
        uint32_t af[4][4];
        #pragma unroll
        for (int mi = 0; mi < 4; mi++) {
            int m = wm + mi * 16;
            af[mi][0] = Qs[(kp + cq) * 132 + m + r];
            af[mi][1] = Qs[(kp + cq) * 132 + m + r + 8];
            af[mi][2] = Qs[(kp + cq + 4) * 132 + m + r];
            af[mi][3] = Qs[(kp + cq + 4) * 132 + m + r + 8];
        }
        #pragma unroll
        for (int ni = 0; ni < 4; ni++) {
            uint32_t b0 = Ks[(kp + cq) * 132 + wn + ni * 8 + r];
            uint32_t b1 = Ks[(kp + cq + 4) * 132 + wn + ni * 8 + r];
            #pragma unroll
            for (int mi = 0; mi < 4; mi++)
                mma16bf(acc1[mi][ni], af[mi][0], af[mi][1], af[mi][2], af[mi][3], b0, b1);
        }
    }
    __syncthreads();

    #pragma unroll
    for (int mi = 0; mi < 4; mi++) {
        int row = wm + mi * 16 + r;
        #pragma unroll
        for (int ni = 0; ni < 4; ni++) {
            int col = wn + ni * 8 + 2 * cq;
            float v0 = (col     <= row)     ? acc1[mi][ni][0] : 0.f;
            float v1 = (col + 1 <= row)     ? acc1[mi][ni][1] : 0.f;
            float v2 = (col     <= row + 8) ? acc1[mi][ni][2] : 0.f;
            float v3 = (col + 1 <= row + 8) ? acc1[mi][ni][3] : 0.f;
            Am[(col >> 1) * 132 + row]     = bf16pack(v0, v1);
            Am[(col >> 1) * 132 + row + 8] = bf16pack(v2, v3);
        }
    }
    {
        __nv_bfloat16* Vb = (__nv_bfloat16*)Vs;
        for (int i = tid; i < 128 * 18; i += 256) {
            int tok = i / 18, qd = (i % 18) * 4;
            float vals[4];
            if (qd < 64) {
                float4 t = *(const float4*)(vv + row0 + (size_t)tok * DMODEL + qd);
                vals[0] = t.x; vals[1] = t.y; vals[2] = t.z; vals[3] = t.w;
            } else {
                #pragma unroll
                for (int e = 0; e < 4; e++) vals[e] = (qd + e == 64) ? 1.f : 0.f;
            }
            #pragma unroll
            for (int e = 0; e < 4; e++)
                Vb[((size_t)(tok >> 1) * 88 + qd + e) * 2 + (tok & 1)] =
                    __float2bfloat16(vals[e]);
        }
    }
    __syncthreads();

    for (int sp = 0; sp < 64; sp += 8) {
        uint32_t a0 = Am[(sp + cq) * 132 + m0 + r];
        uint32_t a1 = Am[(sp + cq) * 132 + m0 + r + 8];
        uint32_t a2 = Am[(sp + cq + 4) * 132 + m0 + r];
        uint32_t a3 = Am[(sp + cq + 4) * 132 + m0 + r + 8];
        #pragma unroll
        for (int ni = 0; ni < 9; ni++) {
            uint32_t b0 = Vs[(sp + cq) * 88 + ni * 8 + r];
            uint32_t b1 = Vs[(sp + cq + 4) * 88 + ni * 8 + r];
            mma16bf(accy[ni], a0, a1, a2, a3, b0, b1);
        }
    }

    float zlo = __shfl_sync(0xffffffffu, accy[8][0], lane & 28) + 1e-6f;
    float zhi = __shfl_sync(0xffffffffu, accy[8][2], lane & 28) + 1e-6f;
    float izlo = 1.f / zlo, izhi = 1.f / zhi;
    size_t rowg = (size_t)(b * SEQ + c * CHUNKSZ + m0 + r);
    #pragma unroll
    for (int ni = 0; ni < 8; ni++) {
        int colg = hh * HD + ni * 8 + 2 * cq;
        *(uint32_t*)(catb + rowg * (2 * DMODEL) + colg) =
            bf16pack(accy[ni][0] * izlo, accy[ni][1] * izlo);
        *(uint32_t*)(catb + (rowg + 8) * (2 * DMODEL) + colg) =
            bf16pack(accy[ni][2] * izhi, accy[ni][3] * izhi);
    }
}

// ---------------- sliding-window attention (256 thr, warp-pair) --------------
__global__ __launch_bounds__(256) void swa_v5(const float* __restrict__ q,
        const float* __restrict__ k, const float* __restrict__ v,
        __nv_bfloat16* __restrict__ catb) {
    extern __shared__ uint32_t su[];
    uint32_t* Qs = su;
    uint32_t* Ks = Qs + 64 * 68;
    uint32_t* Ps = Ks + 64 * 132;
    uint32_t* Vs = Ps + 128 * 68;
    float* red   = (float*)(Vs + 128 * 68);
    float* Osm   = (float*)Qs;
    int tid = threadIdx.x, warp = tid >> 5, lane = tid & 31;
    int r = lane >> 2, cq = lane & 3;
    int g = warp & 3, half = warp >> 2;
    int m0 = g * 16;
    int q0 = blockIdx.x * 64, hh = blockIdx.y, b = blockIdx.z;

    for (int i = tid; i < 64 * 16; i += 256) {
        int tok = i >> 4, qd = (i & 15) * 4;
        float4 t = *(const float4*)(q + (size_t)(b * SEQ + q0 + tok) * DMODEL + hh * HD + qd);
        Qs[(qd + 0) * 68 + tok] = __float_as_uint(t.x);
        Qs[(qd + 1) * 68 + tok] = __float_as_uint(t.y);
        Qs[(qd + 2) * 68 + tok] = __float_as_uint(t.z);
        Qs[(qd + 3) * 68 + tok] = __float_as_uint(t.w);
    }
    for (int i = tid; i < 128 * 16; i += 256) {
        int key = i >> 4, qd = (i & 15) * 4;
        int kg = q0 - 64 + key;
        float4 tk = make_float4(0.f, 0.f, 0.f, 0.f);
        float4 tv = make_float4(0.f, 0.f, 0.f, 0.f);
        if (kg >= 0) {
            tk = *(const float4*)(k + (size_t)(b * SEQ + kg) * DMODEL + hh * HD + qd);
            tv = *(const float4*)(v + (size_t)(b * SEQ + kg) * DMODEL + hh * HD + qd);
        }
        Ks[(qd + 0) * 132 + key] = __float_as_uint(tk.x);
        Ks[(qd + 1) * 132 + key] = __float_as_uint(tk.y);
        Ks[(qd + 2) * 132 + key] = __float_as_uint(tk.z);
        Ks[(qd + 3) * 132 + key] = __float_as_uint(tk.w);
        *(uint4*)(Vs + key * 68 + qd) =
            make_uint4(__float_as_uint(tv.x), __float_as_uint(tv.y),
                       __float_as_uint(tv.z), __float_as_uint(tv.w));
    }
    __syncthreads();

    float acc[8][4];
    #pragma unroll
    for (int ni = 0; ni < 8; ni++)
        #pragma unroll
        for (int e = 0; e < 4; e++) acc[ni][e] = 0.f;
    for (int kk = 0; kk < 64; kk += 8) {
        uint32_t a0 = Qs[(kk + cq) * 68 + m0 + r];
        uint32_t a1 = Qs[(kk + cq) * 68 + m0 + r + 8];
        uint32_t a2 = Qs[(kk + cq + 4) * 68 + m0 + r];
        uint32_t a3 = Qs[(kk + cq + 4) * 68 + m0 + r + 8];
        #pragma unroll
        for (int ni = 0; ni < 8; ni++) {
            int gn = half * 8 + ni;
            uint32_t b0 = Ks[(kk + cq) * 132 + gn * 8 + r];
            uint32_t b1 = Ks[(kk + cq + 4) * 132 + gn * 8 + r];
            mma8(acc[ni], a0, a1, a2, a3, b0, b1);
        }
    }

    int rowlo = m0 + r, rowhi = rowlo + 8;
    float mlo = -1e30f, mhi = -1e30f;
    #pragma unroll
    for (int ni = 0; ni < 8; ni++) {
        int n = (half * 8 + ni) * 8 + 2 * cq;
        bool ok0l = (n     >= rowlo) && (n     <= rowlo + 64) && (q0 - 64 + n     >= 0);
        bool ok1l = (n + 1 >= rowlo) && (n + 1 <= rowlo + 64) && (q0 - 64 + n + 1 >= 0);
        bool ok0h = (n     >= rowhi) && (n     <= rowhi + 64) && (q0 - 64 + n     >= 0);
        bool ok1h = (n + 1 >= rowhi) && (n + 1 <= rowhi + 64) && (q0 - 64 + n + 1 >= 0);
        acc[ni][0] = ok0l ? acc[ni][0] * 0.125f : -1e30f;
        acc[ni][1] = ok1l ? acc[ni][1] * 0.125f : -1e30f;
        acc[ni][2] = ok0h ? acc[ni][2] * 0.125f : -1e30f;
        acc[ni][3] = ok1h ? acc[ni][3] * 0.125f : -1e30f;
        mlo = fmaxf(mlo, fmaxf(acc[ni][0], acc[ni][1]));
        mhi = fmaxf(mhi, fmaxf(acc[ni][2], acc[ni][3]));
    }
    mlo = fmaxf(mlo, __shfl_xor_sync(0xffffffffu, mlo, 1));
    mlo = fmaxf(mlo, __shfl_xor_sync(0xffffffffu, mlo, 2));
    mhi = fmaxf(mhi, __shfl_xor_sync(0xffffffffu, mhi, 1));
    mhi = fmaxf(mhi, __shfl_xor_sync(0xffffffffu, mhi, 2));
    if (cq == 0) {
        red[rowlo * 2 + half] = mlo;
        red[rowhi * 2 + half] = mhi;
    }
    __syncthreads();
    float Mlo = fmaxf(red[rowlo * 2], red[rowlo * 2 + 1]);
    float Mhi = fmaxf(red[rowhi * 2], red[rowhi * 2 + 1]);

    float slo = 0.f, shi = 0.f;
    #pragma unroll
    for (int ni = 0; ni < 8; ni++) {
        acc[ni][0] = __expf(acc[ni][0] - Mlo);
        acc[ni][1] = __expf(acc[ni][1] - Mlo);
        acc[ni][2] = __expf(acc[ni][2] - Mhi);
        acc[ni][3] = __expf(acc[ni][3] - Mhi);
        slo += acc[ni][0] + acc[ni][1];
        shi += acc[ni][2] + acc[ni][3];
    }
    slo += __shfl_xor_sync(0xffffffffu, slo, 1);
    slo += __shfl_xor_sync(0xffffffffu, slo, 2);
    shi += __shfl_xor_sync(0xffffffffu, shi, 1);
    shi += __shfl_xor_sync(0xffffffffu, shi, 2);
    if (cq == 0) {
        red[128 + rowlo * 2 + half] = slo;
        red[128 + rowhi * 2 + half] = shi;
    }

    #pragma unroll
    for (int ni = 0; ni < 8; ni++) {
        int n = (half * 8 + ni) * 8 + 2 * cq;
        Ps[n * 68 + rowlo]       = __float_as_uint(acc[ni][0]);
        Ps[(n + 1) * 68 + rowlo] = __float_as_uint(acc[ni][1]);
        Ps[n * 68 + rowhi]       = __float_as_uint(acc[ni][2]);
        Ps[(n + 1) * 68 + rowhi] = __float_as_uint(acc[ni][3]);
    }
    __syncthreads();
    float sumlo = red[128 + rowlo * 2] + red[128 + rowlo * 2 + 1];
    float sumhi = red[128 + rowhi * 2] + red[128 + rowhi * 2 + 1];

    float accO[8][4];
    #pragma unroll
    for (int ni = 0; ni < 8; ni++)
        #pragma unroll
        for (int e = 0; e < 4; e++) accO[ni][e] = 0.f;
    for (int ks = 0; ks < 64; ks += 8) {
        int kk = half * 64 + ks;
        uint32_t a0 = Ps[(kk + cq) * 68 + m0 + r];
        uint32_t a1 = Ps[(kk + cq) * 68 + m0 + r + 8];
        uint32_t a2 = Ps[(kk + cq + 4) * 68 + m0 + r];
        uint32_t a3 = Ps[(kk + cq + 4) * 68 + m0 + r + 8];
        #pragma unroll
        for (int ni = 0; ni < 8; ni++) {
            uint32_t b0 = Vs[(kk + cq) * 68 + ni * 8 + r];
            uint32_t b1 = Vs[(kk + cq + 4) * 68 + ni * 8 + r];
            mma8(accO[ni], a0, a1, a2, a3, b0, b1);
        }
    }
    if (half == 1) {
        #pragma unroll
        for (int ni = 0; ni < 8; ni++) {
            int n = ni * 8 + 2 * cq;
            Osm[rowlo * 68 + n]     = accO[ni][0];
            Osm[rowlo * 68 + n + 1] = accO[ni][1];
            Osm[rowhi * 68 + n]     = accO[ni][2];
            Osm[rowhi * 68 + n + 1] = accO[ni][3];
        }
    }
    __syncthreads();
    if (half == 0) {
        float izlo = 1.f / sumlo, izhi = 1.f / sumhi;
        #pragma unroll
        for (int ni = 0; ni < 8; ni++) {
            int n = ni * 8 + 2 * cq;
            int colg = DMODEL + hh * HD + n;
            *(uint32_t*)(catb + (size_t)(b * SEQ + q0 + rowlo) * (2 * DMODEL) + colg) =
                bf16pack((accO[ni][0] + Osm[rowlo * 68 + n]) * izlo,
                         (accO[ni][1] + Osm[rowlo * 68 + n + 1]) * izlo);
            *(uint32_t*)(catb + (size_t)(b * SEQ + q0 + rowhi) * (2 * DMODEL) + colg) =
                bf16pack((accO[ni][2] + Osm[rowhi * 68 + n]) * izhi,
                         (accO[ni][3] + Osm[rowhi * 68 + n + 1]) * izhi);
        }
    }
}

// ---------------------------------- launch -----------------------------------
extern "C" void kernel_launch(void* const* d_in, const int* in_sizes, int n_in,
                              void* d_out, int out_size) {
    const float* x      = (const float*)d_in[0];
    const float* norm_w = (const float*)d_in[1];
    const float* Wq     = (const float*)d_in[2];
    const float* Wk     = (const float*)d_in[3];
    const float* Wv     = (const float*)d_in[4];
    const float* Wqf    = (const float*)d_in[5];
    const float* Wkf    = (const float*)d_in[6];
    const float* Wout   = (const float*)d_in[7];
    float* out = (float*)d_out;

    __nv_bfloat16 *hb, *wqt, *wkt, *wvt, *woutt, *catb;
    float *q, *k, *v, *ckv2;
    uint32_t* ckvb;
    cudaGetSymbolAddress((void**)&hb,    g_hb);
    cudaGetSymbolAddress((void**)&wqt,   g_wqt);
    cudaGetSymbolAddress((void**)&wkt,   g_wkt);
    cudaGetSymbolAddress((void**)&wvt,   g_wvt);
    cudaGetSymbolAddress((void**)&woutt, g_woutt);
    cudaGetSymbolAddress((void**)&catb,  g_catb);
    cudaGetSymbolAddress((void**)&q,     g_q);
    cudaGetSymbolAddress((void**)&k,     g_k);
    cudaGetSymbolAddress((void**)&v,     g_v);
    cudaGetSymbolAddress((void**)&ckv2,  g_ckv2);
    cudaGetSymbolAddress((void**)&ckvb,  g_ckvb);

    const int smemG   = NSTAGEB * (ASB_ELE + BSB_ELE) * 4;              // 81920
    const int smemKV  = (160 * 36 + 72 * 36) * 4;                       // 33408
    const int smemLin = (80 * 132 * 2 + 80 * 88) * 4;                   // 112640
    const int smemSWA = (64 * 68 + 64 * 132 + 128 * 68 + 128 * 68) * 4 + 256 * 4;

    static cudaStream_t s2 = nullptr;
    static cudaEvent_t ev_root = nullptr, ev_w = nullptr, ev_fork = nullptr, ev_join = nullptr;
    static bool attrs_set = false;
    if (!attrs_set) {
        cudaFuncSetAttribute(gemmb,       cudaFuncAttributeMaxDynamicSharedMemorySize, smemG);
        cudaFuncSetAttribute(gemmb_qkv,   cudaFuncAttributeMaxDynamicSharedMemorySize, smemG);
        cudaFuncSetAttribute(chunk_kv_v6, cudaFuncAttributeMaxDynamicSharedMemorySize, smemKV);
        cudaFuncSetAttribute(lin_attn_v6, cudaFuncAttributeMaxDynamicSharedMemorySize, smemLin);
        cudaFuncSetAttribute(swa_v5,      cudaFuncAttributeMaxDynamicSharedMemorySize, smemSWA);
        cudaStreamCreateWithFlags(&s2, cudaStreamNonBlocking);
        cudaEventCreateWithFlags(&ev_root, cudaEventDisableTiming);
        cudaEventCreateWithFlags(&ev_w,    cudaEventDisableTiming);
        cudaEventCreateWithFlags(&ev_fork, cudaEventDisableTiming);
        cudaEventCreateWithFlags(&ev_join, cudaEventDisableTiming);
        attrs_set = true;
    }

    // fork s2 from the capture-origin stream BEFORE any s2 work
    cudaEventRecord(ev_root, 0);
    cudaStreamWaitEvent(s2, ev_root, 0);

    transpose_bf16<<<dim3(32, 32), 256, 0, s2>>>(Wq, wqt, DMODEL, DMODEL);
    transpose_bf16<<<dim3(32, 32), 256, 0, s2>>>(Wk, wkt, DMODEL, DMODEL);
    transpose_bf16<<<dim3(32, 32), 256, 0, s2>>>(Wv, wvt, DMODEL, DMODEL);
    transpose_bf16<<<dim3(32, 64), 256, 0, s2>>>(Wout, woutt, 2 * DMODEL, DMODEL);
    cudaEventRecord(ev_w, s2);

    rmsnorm_kernel<<<ROWS, 256>>>(x, norm_w, hb);
    cudaStreamWaitEvent(0, ev_w, 0);

    gemmb_qkv<<<dim3(DMODEL / 128, ROWS / 128, 3), 256, smemG>>>(hb, wqt, wkt, wvt, q, k, v);

    // fork: SWA runs concurrently with the linear-attention chain
    cudaEventRecord(ev_fork, 0);
    cudaStreamWaitEvent(s2, ev_fork, 0);
    swa_v5<<<dim3(SEQ / 64, NH, BATCH), 256, smemSWA, s2>>>(q, k, v, catb);
    cudaEventRecord(ev_join, s2);

    chunk_kv_v6<<<BATCH * NH * NCHUNK * 2, 320, smemKV>>>(k, v, Wkf, ckv2);
    prefix_kv_v4<<<(32 * FPH * 72 + 255) / 256, 256>>>(ckv2, ckvb);
    lin_attn_v6<<<BATCH * NH * NCHUNK, 256, smemLin>>>(q, k, v, Wqf, Wkf, ckvb, catb);

    cudaStreamWaitEvent(0, ev_join, 0);

    gemmb<<<dim3(DMODEL / 128, ROWS / 128), 256, smemG>>>(catb, woutt, out, x, 2 * DMODEL, DMODEL);
}

// round 16
// speedup vs baseline: 1.5216x; 1.0657x over previous
#include <cuda_runtime.h>
#include <cuda_bf16.h>
#include <cstdint>

#define BATCH 2
#define SEQ 2048
#define DMODEL 1024
#define NH 16
#define HD 64
#define FEAT 16
#define FDIM 153           // 1 + 16 + 136
#define FPAD 160
#define NCHUNK 16
#define CHUNKSZ 128
#define ROWS (BATCH*SEQ)          // 4096
#define HROWS (BATCH*SEQ*NH)      // 131072
#define FPH (FPAD/2)              // 80 feature pairs

// ------------------------- scratch (static device memory) -------------------
__device__ __nv_bfloat16 g_hb[ROWS*DMODEL];
__device__ __nv_bfloat16 g_wqt[DMODEL*DMODEL];
__device__ __nv_bfloat16 g_wkt[DMODEL*DMODEL];
__device__ __nv_bfloat16 g_wvt[DMODEL*DMODEL];
__device__ __nv_bfloat16 g_woutt[DMODEL*2*DMODEL];
__device__ __nv_bfloat16 g_catb[(size_t)ROWS*2*DMODEL];
__device__ __nv_bfloat16 g_qb[ROWS*DMODEL];
__device__ __nv_bfloat16 g_kb[ROWS*DMODEL];
__device__ __nv_bfloat16 g_vb[ROWS*DMODEL];
__device__ float g_ckv2[(size_t)BATCH*NH*NCHUNK*2*FPAD*72];
__device__ uint32_t g_ckvb[(size_t)BATCH*NH*NCHUNK*FPH*72];   // bf16x2 feature pairs

__device__ __forceinline__ void mma16bf(float acc[4], uint32_t a0, uint32_t a1,
                                        uint32_t a2, uint32_t a3,
                                        uint32_t b0, uint32_t b1) {
    asm volatile(
        "mma.sync.aligned.m16n8k16.row.col.f32.bf16.bf16.f32 "
        "{%0,%1,%2,%3}, {%4,%5,%6,%7}, {%8,%9}, {%0,%1,%2,%3};"
        : "+f"(acc[0]), "+f"(acc[1]), "+f"(acc[2]), "+f"(acc[3])
        : "r"(a0), "r"(a1), "r"(a2), "r"(a3), "r"(b0), "r"(b1));
}

__device__ __forceinline__ void mma8(float acc[4], uint32_t a0, uint32_t a1,
                                     uint32_t a2, uint32_t a3,
                                     uint32_t b0, uint32_t b1) {
    asm volatile(
        "mma.sync.aligned.m16n8k8.row.col.f32.tf32.tf32.f32 "
        "{%0,%1,%2,%3}, {%4,%5,%6,%7}, {%8,%9}, {%0,%1,%2,%3};"
        : "+f"(acc[0]), "+f"(acc[1]), "+f"(acc[2]), "+f"(acc[3])
        : "r"(a0), "r"(a1), "r"(a2), "r"(a3), "r"(b0), "r"(b1));
}

__device__ __forceinline__ void cp16(uint32_t sdst, const void* gsrc) {
    asm volatile("cp.async.cg.shared.global [%0], [%1], 16;" :: "r"(sdst), "l"(gsrc));
}

__device__ __forceinline__ uint32_t bf16pack(float lo, float hi) {
    uint32_t u;
    asm("cvt.rn.bf16x2.f32 %0, %1, %2;" : "=r"(u) : "f"(hi), "f"(lo));
    return u;
}

// load 4 consecutive bf16 -> 4 floats
__device__ __forceinline__ void ld4bf(const __nv_bfloat16* p, float* o) {
    uint2 u = *(const uint2*)p;
    float2 f0 = __bfloat1622float2(*(__nv_bfloat162*)&u.x);
    float2 f1 = __bfloat1622float2(*(__nv_bfloat162*)&u.y);
    o[0] = f0.x; o[1] = f0.y; o[2] = f1.x; o[3] = f1.y;
}

// phi expansion -> bf16x2-packed col-major (feature pairs): dst[(f>>1)*132 + tok]
__device__ __forceinline__ void write_phi_colmajor_bf(uint32_t* dst, int tok,
                                                      const float* xf) {
    float x[16];
    #pragma unroll
    for (int i = 0; i < 16; i++) x[i] = xf[i];
    const float inv = 0.70710678118654752440f;
    float pend = 0.f;
    #define PHI_EMIT(IDX, V) { if ((IDX) & 1) dst[((IDX) >> 1) * 132 + tok] = bf16pack(pend, (V)); else pend = (V); }
    PHI_EMIT(0, 1.f);
    #pragma unroll
    for (int i = 0; i < 16; i++) PHI_EMIT(1 + i, x[i]);
    int idx = 17;
    #pragma unroll
    for (int i = 0; i < 16; i++) {
        PHI_EMIT(idx, 0.5f * x[i] * x[i]); idx++;
        #pragma unroll
        for (int j = i + 1; j < 16; j++) { PHI_EMIT(idx, inv * x[i] * x[j]); idx++; }
    }
    #pragma unroll
    for (int f = FDIM; f < FPAD; f++) PHI_EMIT(f, 0.f);
    #undef PHI_EMIT
}

// phi expansion -> bf16 [feature][token] layout (stride 72 bf16), half-split
__device__ __forceinline__ void write_phi_ftok_half(__nv_bfloat16* dstb, int tok,
                                                    const float* xf, int h) {
    float x[16];
    #pragma unroll
    for (int i = 0; i < 16; i++) x[i] = xf[i];
    const float inv = 0.70710678118654752440f;
    #define EMITF(F, V) dstb[(F) * 72 + tok] = __float2bfloat16(V)
    if (h == 0) {
        EMITF(0, 1.f);
        #pragma unroll
        for (int i = 0; i < 16; i += 2) {
            int idx = 17 + i * 16 - (i * (i - 1)) / 2;
            EMITF(idx, 0.5f * x[i] * x[i]); idx++;
            #pragma unroll
            for (int j = i + 1; j < 16; j++) { EMITF(idx, inv * x[i] * x[j]); idx++; }
        }
        #pragma unroll
        for (int f = FDIM; f < FPAD; f++) EMITF(f, 0.f);
    } else {
        #pragma unroll
        for (int i = 0; i < 16; i++) EMITF(1 + i, x[i]);
        #pragma unroll
        for (int i = 1; i < 16; i += 2) {
            int idx = 17 + i * 16 - (i * (i - 1)) / 2;
            EMITF(idx, 0.5f * x[i] * x[i]); idx++;
            #pragma unroll
            for (int j = i + 1; j < 16; j++) { EMITF(idx, inv * x[i] * x[j]); idx++; }
        }
    }
    #undef EMITF
}

// ---------------- weight transpose + fp32->bf16 convert ----------------------
__global__ void transpose_bf16(const float* __restrict__ W, __nv_bfloat16* __restrict__ Wt,
                               int K, int N) {
    __shared__ float tile[32][33];
    int n0 = blockIdx.x * 32, k0 = blockIdx.y * 32;
    int tx = threadIdx.x & 31, ty = threadIdx.x >> 5;
    #pragma unroll
    for (int j = 0; j < 32; j += 8)
        tile[ty + j][tx] = W[(size_t)(k0 + ty + j) * N + n0 + tx];
    __syncthreads();
    #pragma unroll
    for (int j = 0; j < 32; j += 8)
        Wt[(size_t)(n0 + ty + j) * K + k0 + tx] = __float2bfloat16(tile[tx][ty + j]);
}

// ------------------------- RMSNorm (float4 in, bf16 out) ---------------------
__global__ void rmsnorm_kernel(const float* __restrict__ x,
                               const float* __restrict__ w,
                               __nv_bfloat16* __restrict__ hb) {
    int row = blockIdx.x;
    const float4* xr = (const float4*)(x + (size_t)row * DMODEL);
    float4 t = xr[threadIdx.x];
    float s = t.x * t.x + t.y * t.y + t.z * t.z + t.w * t.w;
    __shared__ float red[8];
    #pragma unroll
    for (int o = 16; o > 0; o >>= 1) s += __shfl_xor_sync(0xffffffffu, s, o);
    if ((threadIdx.x & 31) == 0) red[threadIdx.x >> 5] = s;
    __syncthreads();
    if (threadIdx.x < 8) {
        float v = red[threadIdx.x];
        #pragma unroll
        for (int o = 4; o > 0; o >>= 1) v += __shfl_xor_sync(0xffu, v, o);
        if (threadIdx.x == 0) red[0] = v;
    }
    __syncthreads();
    float rs = rsqrtf(red[0] / (float)DMODEL + 1e-6f);
    float4 wv = ((const float4*)w)[threadIdx.x];
    uint32_t p0 = bf16pack(t.x * rs * wv.x, t.y * rs * wv.y);
    uint32_t p1 = bf16pack(t.z * rs * wv.z, t.w * rs * wv.w);
    ((uint2*)(hb + (size_t)row * DMODEL))[threadIdx.x] = make_uint2(p0, p1);
}

// ---------------- BF16 GEMM: cp.async 4-stage, k-tile 32, m16n8k16 ------------
#define ASB_ELE (128*20)
#define BSB_ELE (128*20)
#define NSTAGEB 4

__device__ __forceinline__ void gemmb_issue(const __nv_bfloat16* A, const __nv_bfloat16* Bt,
        uint32_t* As, uint32_t* Bs, int bm, int bn, int k0, int K, int tid) {
    #pragma unroll
    for (int j = 0; j < 2; j++) {
        int c = tid + j * 256;
        int m = c >> 2, seg = c & 3;
        cp16((uint32_t)__cvta_generic_to_shared(As + m * 20 + seg * 4),
             A + (size_t)(bm + m) * K + k0 + seg * 8);
    }
    #pragma unroll
    for (int j = 0; j < 2; j++) {
        int c = tid + j * 256;
        int n = c >> 2, seg = c & 3;
        cp16((uint32_t)__cvta_generic_to_shared(Bs + n * 20 + seg * 4),
             Bt + (size_t)(bn + n) * K + k0 + seg * 8);
    }
}

template<bool BF16OUT>
__device__ __forceinline__ void gemmb_core(const __nv_bfloat16* A, const __nv_bfloat16* Bt,
        void* Cout, const float* residual, uint32_t* As, uint32_t* Bs,
        int bm, int bn, int K, int N, int tid) {
    int warp = tid >> 5, lane = tid & 31;
    int wm = (warp >> 2) * 64, wn = (warp & 3) * 32;
    int r = lane >> 2, cq = lane & 3;

    float acc[4][4][4];
    #pragma unroll
    for (int mi = 0; mi < 4; mi++)
        #pragma unroll
        for (int ni = 0; ni < 4; ni++)
            #pragma unroll
            for (int e = 0; e < 4; e++) acc[mi][ni][e] = 0.f;

    int nk = K / 32;
    gemmb_issue(A, Bt, As, Bs, bm, bn, 0, K, tid);
    asm volatile("cp.async.commit_group;");
    gemmb_issue(A, Bt, As + ASB_ELE, Bs + BSB_ELE, bm, bn, 32, K, tid);
    asm volatile("cp.async.commit_group;");
    gemmb_issue(A, Bt, As + 2 * ASB_ELE, Bs + 2 * BSB_ELE, bm, bn, 64, K, tid);
    asm volatile("cp.async.commit_group;");

    for (int kt = 0; kt < nk; kt++) {
        if (kt + 3 < nk) {
            int slot = (kt + 3) & 3;
            gemmb_issue(A, Bt, As + slot * ASB_ELE, Bs + slot * BSB_ELE,
                        bm, bn, (kt + 3) * 32, K, tid);
        }
        asm volatile("cp.async.commit_group;");
        asm volatile("cp.async.wait_group 3;");
        __syncthreads();
        const uint32_t* Au = As + (kt & 3) * ASB_ELE;
        const uint32_t* Bu = Bs + (kt & 3) * BSB_ELE;
        #pragma unroll
        for (int ks = 0; ks < 16; ks += 8) {
            uint32_t af[4][4], bf[4][2];
            #pragma unroll
            for (int mi = 0; mi < 4; mi++) {
                int m = wm + mi * 16 + r;
                af[mi][0] = Au[m * 20 + ks + cq];
                af[mi][1] = Au[(m + 8) * 20 + ks + cq];
                af[mi][2] = Au[m * 20 + ks + cq + 4];
                af[mi][3] = Au[(m + 8) * 20 + ks + cq + 4];
            }
            #pragma unroll
            for (int ni = 0; ni < 4; ni++) {
                int n = wn + ni * 8 + r;
                bf[ni][0] = Bu[n * 20 + ks + cq];
                bf[ni][1] = Bu[n * 20 + ks + cq + 4];
            }
            #pragma unroll
            for (int mi = 0; mi < 4; mi++)
                #pragma unroll
                for (int ni = 0; ni < 4; ni++)
                    mma16bf(acc[mi][ni], af[mi][0], af[mi][1], af[mi][2], af[mi][3],
                            bf[ni][0], bf[ni][1]);
        }
        __syncthreads();
    }

    #pragma unroll
    for (int mi = 0; mi < 4; mi++) {
        int row0 = bm + wm + mi * 16 + r;
        #pragma unroll
        for (int ni = 0; ni < 4; ni++) {
            int col = bn + wn + ni * 8 + 2 * cq;
            if (BF16OUT) {
                __nv_bfloat16* Cb = (__nv_bfloat16*)Cout;
                *(uint32_t*)(Cb + (size_t)row0 * N + col) =
                    bf16pack(acc[mi][ni][0], acc[mi][ni][1]);
                *(uint32_t*)(Cb + (size_t)(row0 + 8) * N + col) =
                    bf16pack(acc[mi][ni][2], acc[mi][ni][3]);
            } else {
                float* C = (float*)Cout;
                float2 lo = make_float2(acc[mi][ni][0], acc[mi][ni][1]);
                float2 hi = make_float2(acc[mi][ni][2], acc[mi][ni][3]);
                if (residual) {
                    float2 r0 = *(const float2*)(residual + (size_t)row0 * N + col);
                    float2 r1 = *(const float2*)(residual + (size_t)(row0 + 8) * N + col);
                    lo.x += r0.x; lo.y += r0.y; hi.x += r1.x; hi.y += r1.y;
                }
                *(float2*)(C + (size_t)row0 * N + col) = lo;
                *(float2*)(C + (size_t)(row0 + 8) * N + col) = hi;
            }
        }
    }
}

__global__ __launch_bounds__(256) void gemmb(
        const __nv_bfloat16* __restrict__ A, const __nv_bfloat16* __restrict__ Bt,
        float* __restrict__ C, const float* __restrict__ residual, int K, int N) {
    extern __shared__ uint32_t sgb[];
    gemmb_core<false>(A, Bt, C, residual, sgb, sgb + NSTAGEB * ASB_ELE,
                      blockIdx.y * 128, blockIdx.x * 128, K, N, threadIdx.x);
}

__global__ __launch_bounds__(256) void gemmb_qkv(
        const __nv_bfloat16* __restrict__ A,
        const __nv_bfloat16* __restrict__ Bq, const __nv_bfloat16* __restrict__ Bk,
        const __nv_bfloat16* __restrict__ Bv,
        __nv_bfloat16* __restrict__ Cq, __nv_bfloat16* __restrict__ Ck,
        __nv_bfloat16* __restrict__ Cv) {
    extern __shared__ uint32_t sgb[];
    const __nv_bfloat16* Bt = (blockIdx.z == 0) ? Bq : (blockIdx.z == 1) ? Bk : Bv;
    __nv_bfloat16* C = (blockIdx.z == 0) ? Cq : (blockIdx.z == 1) ? Ck : Cv;
    gemmb_core<true>(A, Bt, C, nullptr, sgb, sgb + NSTAGEB * ASB_ELE,
                     blockIdx.y * 128, blockIdx.x * 128, DMODEL, DMODEL, threadIdx.x);
}

// --------- pass A: half-chunk fused feat-proj + phi + partial KV' (bf16) ------
__global__ __launch_bounds__(320) void chunk_kv_v6(const __nv_bfloat16* __restrict__ kb_,
        const __nv_bfloat16* __restrict__ vb_, const float* __restrict__ Wkf,
        float* __restrict__ ckv2) {
    extern __shared__ uint32_t su[];
    uint32_t* Ks2 = su;             // [160][36] uints (bf16 [feat][tok72])
    uint32_t* Vs2 = su + 160 * 36;  // [72][36] uints
    float* Kf = (float*)Ks2;        // overlay: raw k tile [64][68] floats
    float* Sf = (float*)Vs2;        // overlay: W [1024] + kf [1024] floats
    int tid = threadIdx.x, warp = tid >> 5, lane = tid & 31;
    int r = lane >> 2, cq = lane & 3;
    int bid = blockIdx.x;
    int half = bid & 1, bhc = bid >> 1;
    int c = bhc & 15, bh = bhc >> 4, b = bh >> 4, hh = bh & 15;
    size_t row0 = (size_t)(b * SEQ + c * CHUNKSZ + half * 64) * DMODEL + hh * HD;

    for (int i = tid; i < 64 * 16; i += 320) {
        int tok = i >> 4, qd = (i & 15) * 4;
        ld4bf(kb_ + row0 + (size_t)tok * DMODEL + qd, Kf + tok * 68 + qd);
    }
    for (int i = tid; i < 1024; i += 320) Sf[i] = Wkf[i];
    __syncthreads();

    if (tid < 256) {                 // feat-proj: 4 threads/token, 4 cols each
        int tok = tid >> 2, qm = (tid & 3) * 4;
        float accf[4];
        #pragma unroll
        for (int cc = 0; cc < 4; cc++) accf[cc] = 0.f;
        for (int e = 0; e < 64; e++) {
            float rv = Kf[tok * 68 + e];
            #pragma unroll
            for (int cc = 0; cc < 4; cc++) accf[cc] += rv * Sf[e * 16 + qm + cc];
        }
        #pragma unroll
        for (int cc = 0; cc < 4; cc++) Sf[1024 + tok * 16 + qm + cc] = accf[cc];
    }
    __syncthreads();
    if (tid < 128) {
        int tok = tid >> 1, hm = tid & 1;
        write_phi_ftok_half((__nv_bfloat16*)Ks2, tok, Sf + 1024 + tok * 16, hm);
    }
    __syncthreads();

    // V' bf16 [d][tok]: transpose copy of bf16 v (+ ones col 64)
    {
        __nv_bfloat16* Vb = (__nv_bfloat16*)Vs2;
        const __nv_bfloat16 one = __float2bfloat16(1.f);
        const __nv_bfloat16 zero = __float2bfloat16(0.f);
        for (int i = tid; i < 64 * 18; i += 320) {
            int tok = i / 18, qd = (i % 18) * 4;
            if (qd < 64) {
                uint2 u = *(const uint2*)(vb_ + row0 + (size_t)tok * DMODEL + qd);
                const __nv_bfloat16* pv = (const __nv_bfloat16*)&u;
                #pragma unroll
                for (int e = 0; e < 4; e++) Vb[(qd + e) * 72 + tok] = pv[e];
            } else {
                #pragma unroll
                for (int e = 0; e < 4; e++)
                    Vb[(qd + e) * 72 + tok] = (qd + e == 64) ? one : zero;
            }
        }
    }
    __syncthreads();

    float acc[9][4];
    #pragma unroll
    for (int ni = 0; ni < 9; ni++)
        #pragma unroll
        for (int e = 0; e < 4; e++) acc[ni][e] = 0.f;
    int m0 = warp * 16;
    for (int kp = 0; kp < 32; kp += 8) {
        uint32_t a0 = Ks2[(m0 + r) * 36 + kp + cq];
        uint32_t a1 = Ks2[(m0 + r + 8) * 36 + kp + cq];
        uint32_t a2 = Ks2[(m0 + r) * 36 + kp + cq + 4];
        uint32_t a3 = Ks2[(m0 + r + 8) * 36 + kp + cq + 4];
        #pragma unroll
        for (int ni = 0; ni < 9; ni++) {
            uint32_t b0 = Vs2[(ni * 8 + r) * 36 + kp + cq];
            uint32_t b1 = Vs2[(ni * 8 + r) * 36 + kp + cq + 4];
            mma16bf(acc[ni], a0, a1, a2, a3, b0, b1);
        }
    }
    float* outb = ckv2 + (size_t)bid * FPAD * 72;
    #pragma unroll
    for (int ni = 0; ni < 9; ni++) {
        int n = ni * 8 + 2 * cq;
        *(float2*)(outb + (m0 + r) * 72 + n)     = make_float2(acc[ni][0], acc[ni][1]);
        *(float2*)(outb + (m0 + r + 8) * 72 + n) = make_float2(acc[ni][2], acc[ni][3]);
    }
}

// --------- pass B: exclusive prefix over chunks -> bf16x2 feature pairs -------
__global__ void prefix_kv_v4(const float* __restrict__ ckv2, uint32_t* __restrict__ ckvb) {
    const int FD = FPAD * 72;
    const int PD = FPH * 72;
    int idx = blockIdx.x * 256 + threadIdx.x;
    if (idx >= 32 * PD) return;
    int bh = idx / PD, e = idx % PD;
    int fp = e / 72, n = e % 72;
    size_t o0 = (size_t)(2 * fp) * 72 + n;
    size_t o1 = o0 + 72;
    float run0 = 0.f, run1 = 0.f;
    for (int c = 0; c < NCHUNK; c++) {
        size_t bc = (size_t)(bh * NCHUNK + c);
        ckvb[bc * PD + e] = bf16pack(run0, run1);
        run0 += ckv2[(bc * 2) * FD + o0] + ckv2[(bc * 2 + 1) * FD + o0];
        run1 += ckv2[(bc * 2) * FD + o1] + ckv2[(bc * 2 + 1) * FD + o1];
    }
}

// --------- pass C: fused feat-proj + phi + linear attention (bf16 mma) --------
__global__ __launch_bounds__(256) void lin_attn_v6(const __nv_bfloat16* __restrict__ qb_,
        const __nv_bfloat16* __restrict__ kb_, const __nv_bfloat16* __restrict__ vb_,
        const float* __restrict__ Wqf, const float* __restrict__ Wkf,
        const uint32_t* __restrict__ ckvb, __nv_bfloat16* __restrict__ catb) {
    extern __shared__ uint32_t su[];
    uint32_t* Qs  = su;                  // [kp 80][132]
    uint32_t* Ks  = su + 80 * 132;       // [kp 80][132]
    uint32_t* KVs = Ks + 80 * 132;       // [kp 80][88]
    uint32_t* Am  = Ks;                  // overlay [sp 64][132]
    uint32_t* Vs  = Ks + 64 * 132;       // overlay [sp 64][88]
    float* Qraw = (float*)Qs;
    float* Kraw = (float*)Ks;
    float* Scr  = (float*)KVs;
    int tid = threadIdx.x, warp = tid >> 5, lane = tid & 31;
    int r = lane >> 2, cq = lane & 3;
    int bhc = blockIdx.x, c = bhc & 15, bh = bhc >> 4, b = bh >> 4, hh = bh & 15;
    size_t row0 = (size_t)(b * SEQ + c * CHUNKSZ) * DMODEL + hh * HD;

    for (int i = tid; i < 128 * 16; i += 256) {
        int tok = i >> 4, qd = (i & 15) * 4;
        ld4bf(qb_ + row0 + (size_t)tok * DMODEL + qd, Qraw + tok * 68 + qd);
        ld4bf(kb_ + row0 + (size_t)tok * DMODEL + qd, Kraw + tok * 68 + qd);
    }
    for (int i = tid; i < 1024; i += 256) { Scr[i] = Wqf[i]; Scr[1024 + i] = Wkf[i]; }
    __syncthreads();

    {
        int tok = tid & 127, which = tid >> 7;
        const float* raw = which ? Kraw : Qraw;
        const float* W   = Scr + which * 1024;
        float* of        = Scr + 2048 + which * 2048;
        float accf[16];
        #pragma unroll
        for (int cc = 0; cc < 16; cc++) accf[cc] = 0.f;
        for (int e = 0; e < 64; e++) {
            float rv = raw[tok * 68 + e];
            #pragma unroll
            for (int cc = 0; cc < 16; cc++) accf[cc] += rv * W[e * 16 + cc];
        }
        #pragma unroll
        for (int cc = 0; cc < 16; cc++) of[tok * 16 + cc] = accf[cc];
    }
    __syncthreads();
    {
        int tok = tid & 127, which = tid >> 7;
        uint32_t* dst = which ? Ks : Qs;
        write_phi_colmajor_bf(dst, tok, Scr + 2048 + which * 2048 + tok * 16);
    }
    __syncthreads();

    const uint32_t* kvb = ckvb + (size_t)bhc * FPH * 72;
    for (int i = tid; i < 80 * 72; i += 256) {
        int kp = i / 72, n = i % 72;
        KVs[kp * 88 + n] = kvb[kp * 72 + n];
    }
    __syncthreads();

    float accy[9][4];
    #pragma unroll
    for (int ni = 0; ni < 9; ni++)
        #pragma unroll
        for (int e = 0; e < 4; e++) accy[ni][e] = 0.f;
    int m0 = warp * 16;
    for (int kp = 0; kp < 80; kp += 8) {
        uint32_t a0 = Qs[(kp + cq) * 132 + m0 + r];
        uint32_t a1 = Qs[(kp + cq) * 132 + m0 + r + 8];
        uint32_t a2 = Qs[(kp + cq + 4) * 132 + m0 + r];
        uint32_t a3 = Qs[(kp + cq + 4) * 132 + m0 + r + 8];
        #pragma unroll
        for (int ni = 0; ni < 9; ni++) {
            uint32_t b0 = KVs[(kp + cq) * 88 + ni * 8 + r];
            uint32_t b1 = KVs[(kp + cq + 4) * 88 + ni * 8 + r];
            mma16bf(accy[ni], a0, a1, a2, a3, b0, b1);
        }
    }

    float acc1[4][4][4];
    #pragma unroll
    for (int mi = 0; mi < 4; mi++)
        #pragma unroll
        for (int ni = 0; ni < 4; ni++)
            #pragma unroll
            for (int e = 0; e < 4; e++) acc1[mi][ni][e] = 0.f;
    int wm = (warp >> 2) * 64, wn = (warp & 3) * 32;
    for (int kp = 0; kp < 80; kp += 8) {
        uint32_t af[4][4];
        #pragma unroll
        for (int mi = 0; mi < 4; mi++) {
            int m = wm + mi * 16;
            af[mi][0] = Qs[(kp + cq) * 132 + m + r];
            af[mi][1] = Qs[(kp + cq) * 132 + m + r + 8];
            af[mi][2] = Qs[(kp + cq + 4) * 132 + m + r];
            af[mi][3] = Qs[(kp + cq + 4) * 132 + m + r + 8];
        }
        #pragma unroll
        for (int ni = 0; ni < 4; ni++) {
            uint32_t b0 = Ks[(kp + cq) * 132 + wn + ni * 8 + r];
            uint32_t b1 = Ks[(kp + cq + 4) * 132 + wn + ni * 8 + r];
            #pragma unroll
            for (int mi = 0; mi < 4; mi++)
                mma16bf(acc1[mi][ni], af[mi][0], af[mi][1], af[mi][2], af[mi][3], b0, b1);
        }
    }
    __syncthreads();

    #pragma unroll
    for (int mi = 0; mi < 4; mi++) {
        int row = wm + mi * 16 + r;
        #pragma unroll
        for (int ni = 0; ni < 4; ni++) {
            int col = wn + ni * 8 + 2 * cq;
            float v0 = (col     <= row)     ? acc1[mi][ni][0] : 0.f;
            float v1 = (col + 1 <= row)     ? acc1[mi][ni][1] : 0.f;
            float v2 = (col     <= row + 8) ? acc1[mi][ni][2] : 0.f;
            float v3 = (col + 1 <= row + 8) ? acc1[mi][ni][3] : 0.f;
            Am[(col >> 1) * 132 + row]     = bf16pack(v0, v1);
            Am[(col >> 1) * 132 + row + 8] = bf16pack(v2, v3);
        }
    }
    {
        __nv_bfloat16* Vb = (__nv_bfloat16*)Vs;
        const __nv_bfloat16 one = __float2bfloat16(1.f);
        const __nv_bfloat16 zero = __float2bfloat16(0.f);
        for (int i = tid; i < 128 * 18; i += 256) {
            int tok = i / 18, qd = (i % 18) * 4;
            if (qd < 64) {
                uint2 u = *(const uint2*)(vb_ + row0 + (size_t)tok * DMODEL + qd);
                const __nv_bfloat16* pv = (const __nv_bfloat16*)&u;
                #pragma unroll
                for (int e = 0; e < 4; e++)
                    Vb[((size_t)(tok >> 1) * 88 + qd + e) * 2 + (tok & 1)] = pv[e];
            } else {
                #pragma unroll
                for (int e = 0; e < 4; e++)
                    Vb[((size_t)(tok >> 1) * 88 + qd + e) * 2 + (tok & 1)] =
                        (qd + e == 64) ? one : zero;
            }
        }
    }
    __syncthreads();

    for (int sp = 0; sp < 64; sp += 8) {
        uint32_t a0 = Am[(sp + cq) * 132 + m0 + r];
        uint32_t a1 = Am[(sp + cq) * 132 + m0 + r + 8];
        uint32_t a2 = Am[(sp + cq + 4) * 132 + m0 + r];
        uint32_t a3 = Am[(sp + cq + 4) * 132 + m0 + r + 8];
        #pragma unroll
        for (int ni = 0; ni < 9; ni++) {
            uint32_t b0 = Vs[(sp + cq) * 88 + ni * 8 + r];
            uint32_t b1 = Vs[(sp + cq + 4) * 88 + ni * 8 + r];
            mma16bf(accy[ni], a0, a1, a2, a3, b0, b1);
        }
    }

    float zlo = __shfl_sync(0xffffffffu, accy[8][0], lane & 28) + 1e-6f;
    float zhi = __shfl_sync(0xffffffffu, accy[8][2], lane & 28) + 1e-6f;
    float izlo = 1.f / zlo, izhi = 1.f / zhi;
    size_t rowg = (size_t)(b * SEQ + c * CHUNKSZ + m0 + r);
    #pragma unroll
    for (int ni = 0; ni < 8; ni++) {
        int colg = hh * HD + ni * 8 + 2 * cq;
        *(uint32_t*)(catb + rowg * (2 * DMODEL) + colg) =
            bf16pack(accy[ni][0] * izlo, accy[ni][1] * izlo);
        *(uint32_t*)(catb + (rowg + 8) * (2 * DMODEL) + colg) =
            bf16pack(accy[ni][2] * izhi, accy[ni][3] * izhi);
    }
}

// ---------------- sliding-window attention (256 thr, warp-pair) --------------
__global__ __launch_bounds__(256) void swa_v5(const __nv_bfloat16* __restrict__ qb_,
        const __nv_bfloat16* __restrict__ kb_, const __nv_bfloat16* __restrict__ vb_,
        __nv_bfloat16* __restrict__ catb) {
    extern __shared__ uint32_t su[];
    uint32_t* Qs = su;
    uint32_t* Ks = Qs + 64 * 68;
    uint32_t* Ps = Ks + 64 * 132;
    uint32_t* Vs = Ps + 128 * 68;
    float* red   = (float*)(Vs + 128 * 68);
    float* Osm   = (float*)Qs;
    int tid = threadIdx.x, warp = tid >> 5, lane = tid & 31;
    int r = lane >> 2, cq = lane & 3;
    int g = warp & 3, half = warp >> 2;
    int m0 = g * 16;
    int q0 = blockIdx.x * 64, hh = blockIdx.y, b = blockIdx.z;

    for (int i = tid; i < 64 * 16; i += 256) {
        int tok = i >> 4, qd = (i & 15) * 4;
        float f[4];
        ld4bf(qb_ + (size_t)(b * SEQ + q0 + tok) * DMODEL + hh * HD + qd, f);
        #pragma unroll
        for (int e = 0; e < 4; e++) Qs[(qd + e) * 68 + tok] = __float_as_uint(f[e]);
    }
    for (int i = tid; i < 128 * 16; i += 256) {
        int key = i >> 4, qd = (i & 15) * 4;
        int kg = q0 - 64 + key;
        float fk[4] = {0.f, 0.f, 0.f, 0.f};
        float fv[4] = {0.f, 0.f, 0.f, 0.f};
        if (kg >= 0) {
            ld4bf(kb_ + (size_t)(b * SEQ + kg) * DMODEL + hh * HD + qd, fk);
            ld4bf(vb_ + (size_t)(b * SEQ + kg) * DMODEL + hh * HD + qd, fv);
        }
        #pragma unroll
        for (int e = 0; e < 4; e++) Ks[(qd + e) * 132 + key] = __float_as_uint(fk[e]);
        *(uint4*)(Vs + key * 68 + qd) =
            make_uint4(__float_as_uint(fv[0]), __float_as_uint(fv[1]),
                       __float_as_uint(fv[2]), __float_as_uint(fv[3]));
    }
    __syncthreads();

    float acc[8][4];
    #pragma unroll
    for (int ni = 0; ni < 8; ni++)
        #pragma unroll
        for (int e = 0; e < 4; e++) acc[ni][e] = 0.f;
    for (int kk = 0; kk < 64; kk += 8) {
        uint32_t a0 = Qs[(kk + cq) * 68 + m0 + r];
        uint32_t a1 = Qs[(kk + cq) * 68 + m0 + r + 8];
        uint32_t a2 = Qs[(kk + cq + 4) * 68 + m0 + r];
        uint32_t a3 = Qs[(kk + cq + 4) * 68 + m0 + r + 8];
        #pragma unroll
        for (int ni = 0; ni < 8; ni++) {
            int gn = half * 8 + ni;
            uint32_t b0 = Ks[(kk + cq) * 132 + gn * 8 + r];
            uint32_t b1 = Ks[(kk + cq + 4) * 132 + gn * 8 + r];
            mma8(acc[ni], a0, a1, a2, a3, b0, b1);
        }
    }

    int rowlo = m0 + r, rowhi = rowlo + 8;
    float mlo = -1e30f, mhi = -1e30f;
    #pragma unroll
    for (int ni = 0; ni < 8; ni++) {
        int n = (half * 8 + ni) * 8 + 2 * cq;
        bool ok0l = (n     >= rowlo) && (n     <= rowlo + 64) && (q0 - 64 + n     >= 0);
        bool ok1l = (n + 1 >= rowlo) && (n + 1 <= rowlo + 64) && (q0 - 64 + n + 1 >= 0);
        bool ok0h = (n     >= rowhi) && (n     <= rowhi + 64) && (q0 - 64 + n     >= 0);
        bool ok1h = (n + 1 >= rowhi) && (n + 1 <= rowhi + 64) && (q0 - 64 + n + 1 >= 0);
        acc[ni][0] = ok0l ? acc[ni][0] * 0.125f : -1e30f;
        acc[ni][1] = ok1l ? acc[ni][1] * 0.125f : -1e30f;
        acc[ni][2] = ok0h ? acc[ni][2] * 0.125f : -1e30f;
        acc[ni][3] = ok1h ? acc[ni][3] * 0.125f : -1e30f;
        mlo = fmaxf(mlo, fmaxf(acc[ni][0], acc[ni][1]));
        mhi = fmaxf(mhi, fmaxf(acc[ni][2], acc[ni][3]));
    }
    mlo = fmaxf(mlo, __shfl_xor_sync(0xffffffffu, mlo, 1));
    mlo = fmaxf(mlo, __shfl_xor_sync(0xffffffffu, mlo, 2));
    mhi = fmaxf(mhi, __shfl_xor_sync(0xffffffffu, mhi, 1));
    mhi = fmaxf(mhi, __shfl_xor_sync(0xffffffffu, mhi, 2));
    if (cq == 0) {
        red[rowlo * 2 + half] = mlo;
        red[rowhi * 2 + half] = mhi;
    }
    __syncthreads();
    float Mlo = fmaxf(red[rowlo * 2], red[rowlo * 2 + 1]);
    float Mhi = fmaxf(red[rowhi * 2], red[rowhi * 2 + 1]);

    float slo = 0.f, shi = 0.f;
    #pragma unroll
    for (int ni = 0; ni < 8; ni++) {
        acc[ni][0] = __expf(acc[ni][0] - Mlo);
        acc[ni][1] = __expf(acc[ni][1] - Mlo);
        acc[ni][2] = __expf(acc[ni][2] - Mhi);
        acc[ni][3] = __expf(acc[ni][3] - Mhi);
        slo += acc[ni][0] + acc[ni][1];
        shi += acc[ni][2] + acc[ni][3];
    }
    slo += __shfl_xor_sync(0xffffffffu, slo, 1);
    slo += __shfl_xor_sync(0xffffffffu, slo, 2);
    shi += __shfl_xor_sync(0xffffffffu, shi, 1);
    shi += __shfl_xor_sync(0xffffffffu, shi, 2);
    if (cq == 0) {
        red[128 + rowlo * 2 + half] = slo;
        red[128 + rowhi * 2 + half] = shi;
    }

    #pragma unroll
    for (int ni = 0; ni < 8; ni++) {
        int n = (half * 8 + ni) * 8 + 2 * cq;
        Ps[n * 68 + rowlo]       = __float_as_uint(acc[ni][0]);
        Ps[(n + 1) * 68 + rowlo] = __float_as_uint(acc[ni][1]);
        Ps[n * 68 + rowhi]       = __float_as_uint(acc[ni][2]);
        Ps[(n + 1) * 68 + rowhi] = __float_as_uint(acc[ni][3]);
    }
    __syncthreads();
    float sumlo = red[128 + rowlo * 2] + red[128 + rowlo * 2 + 1];
    float sumhi = red[128 + rowhi * 2] + red[128 + rowhi * 2 + 1];

    float accO[8][4];
    #pragma unroll
    for (int ni = 0; ni < 8; ni++)
        #pragma unroll
        for (int e = 0; e < 4; e++) accO[ni][e] = 0.f;
    for (int ks = 0; ks < 64; ks += 8) {
        int kk = half * 64 + ks;
        uint32_t a0 = Ps[(kk + cq) * 68 + m0 + r];
        uint32_t a1 = Ps[(kk + cq) * 68 + m0 + r + 8];
        uint32_t a2 = Ps[(kk + cq + 4) * 68 + m0 + r];
        uint32_t a3 = Ps[(kk + cq + 4) * 68 + m0 + r + 8];
        #pragma unroll
        for (int ni = 0; ni < 8; ni++) {
            uint32_t b0 = Vs[(kk + cq) * 68 + ni * 8 + r];
            uint32_t b1 = Vs[(kk + cq + 4) * 68 + ni * 8 + r];
            mma8(accO[ni], a0, a1, a2, a3, b0, b1);
        }
    }
    if (half == 1) {
        #pragma unroll
        for (int ni = 0; ni < 8; ni++) {
            int n = ni * 8 + 2 * cq;
            Osm[rowlo * 68 + n]     = accO[ni][0];
            Osm[rowlo * 68 + n + 1] = accO[ni][1];
            Osm[rowhi * 68 + n]     = accO[ni][2];
            Osm[rowhi * 68 + n + 1] = accO[ni][3];
        }
    }
    __syncthreads();
    if (half == 0) {
        float izlo = 1.f / sumlo, izhi = 1.f / sumhi;
        #pragma unroll
        for (int ni = 0; ni < 8; ni++) {
            int n = ni * 8 + 2 * cq;
            int colg = DMODEL + hh * HD + n;
            *(uint32_t*)(catb + (size_t)(b * SEQ + q0 + rowlo) * (2 * DMODEL) + colg) =
                bf16pack((accO[ni][0] + Osm[rowlo * 68 + n]) * izlo,
                         (accO[ni][1] + Osm[rowlo * 68 + n + 1]) * izlo);
            *(uint32_t*)(catb + (size_t)(b * SEQ + q0 + rowhi) * (2 * DMODEL) + colg) =
                bf16pack((accO[ni][2] + Osm[rowhi * 68 + n]) * izhi,
                         (accO[ni][3] + Osm[rowhi * 68 + n + 1]) * izhi);
        }
    }
}

// ---------------------------------- launch -----------------------------------
extern "C" void kernel_launch(void* const* d_in, const int* in_sizes, int n_in,
                              void* d_out, int out_size) {
    const float* x      = (const float*)d_in[0];
    const float* norm_w = (const float*)d_in[1];
    const float* Wq     = (const float*)d_in[2];
    const float* Wk     = (const float*)d_in[3];
    const float* Wv     = (const float*)d_in[4];
    const float* Wqf    = (const float*)d_in[5];
    const float* Wkf    = (const float*)d_in[6];
    const float* Wout   = (const float*)d_in[7];
    float* out = (float*)d_out;

    __nv_bfloat16 *hb, *wqt, *wkt, *wvt, *woutt, *catb, *qb, *kb, *vb;
    float *ckv2;
    uint32_t* ckvb;
    cudaGetSymbolAddress((void**)&hb,    g_hb);
    cudaGetSymbolAddress((void**)&wqt,   g_wqt);
    cudaGetSymbolAddress((void**)&wkt,   g_wkt);
    cudaGetSymbolAddress((void**)&wvt,   g_wvt);
    cudaGetSymbolAddress((void**)&woutt, g_woutt);
    cudaGetSymbolAddress((void**)&catb,  g_catb);
    cudaGetSymbolAddress((void**)&qb,    g_qb);
    cudaGetSymbolAddress((void**)&kb,    g_kb);
    cudaGetSymbolAddress((void**)&vb,    g_vb);
    cudaGetSymbolAddress((void**)&ckv2,  g_ckv2);
    cudaGetSymbolAddress((void**)&ckvb,  g_ckvb);

    const int smemG   = NSTAGEB * (ASB_ELE + BSB_ELE) * 4;              // 81920
    const int smemKV  = (160 * 36 + 72 * 36) * 4;                       // 33408
    const int smemLin = (80 * 132 * 2 + 80 * 88) * 4;                   // 112640
    const int smemSWA = (64 * 68 + 64 * 132 + 128 * 68 + 128 * 68) * 4 + 256 * 4;

    static cudaStream_t s2 = nullptr;
    static cudaEvent_t ev_root = nullptr, ev_w3 = nullptr, ev_fork = nullptr, ev_join = nullptr;
    static bool attrs_set = false;
    if (!attrs_set) {
        cudaFuncSetAttribute(gemmb,       cudaFuncAttributeMaxDynamicSharedMemorySize, smemG);
        cudaFuncSetAttribute(gemmb_qkv,   cudaFuncAttributeMaxDynamicSharedMemorySize, smemG);
        cudaFuncSetAttribute(chunk_kv_v6, cudaFuncAttributeMaxDynamicSharedMemorySize, smemKV);
        cudaFuncSetAttribute(lin_attn_v6, cudaFuncAttributeMaxDynamicSharedMemorySize, smemLin);
        cudaFuncSetAttribute(swa_v5,      cudaFuncAttributeMaxDynamicSharedMemorySize, smemSWA);
        cudaStreamCreateWithFlags(&s2, cudaStreamNonBlocking);
        cudaEventCreateWithFlags(&ev_root, cudaEventDisableTiming);
        cudaEventCreateWithFlags(&ev_w3,   cudaEventDisableTiming);
        cudaEventCreateWithFlags(&ev_fork, cudaEventDisableTiming);
        cudaEventCreateWithFlags(&ev_join, cudaEventDisableTiming);
        attrs_set = true;
    }

    // fork s2 from the capture-origin stream BEFORE any s2 work
    cudaEventRecord(ev_root, 0);
    cudaStreamWaitEvent(s2, ev_root, 0);

    // QKV weight transposes gate the QKV GEMM; Wout transpose deferred
    transpose_bf16<<<dim3(32, 32), 256, 0, s2>>>(Wq, wqt, DMODEL, DMODEL);
    transpose_bf16<<<dim3(32, 32), 256, 0, s2>>>(Wk, wkt, DMODEL, DMODEL);
    transpose_bf16<<<dim3(32, 32), 256, 0, s2>>>(Wv, wvt, DMODEL, DMODEL);
    cudaEventRecord(ev_w3, s2);
    // Wout transpose overlaps the QKV GEMM (still ordered before ev_join on s2)
    transpose_bf16<<<dim3(32, 64), 256, 0, s2>>>(Wout, woutt, 2 * DMODEL, DMODEL);

    rmsnorm_kernel<<<ROWS, 256>>>(x, norm_w, hb);
    cudaStreamWaitEvent(0, ev_w3, 0);

    gemmb_qkv<<<dim3(DMODEL / 128, ROWS / 128, 3), 256, smemG>>>(hb, wqt, wkt, wvt, qb, kb, vb);

    // fork: SWA runs concurrently with the linear-attention chain
    cudaEventRecord(ev_fork, 0);
    cudaStreamWaitEvent(s2, ev_fork, 0);
    swa_v5<<<dim3(SEQ / 64, NH, BATCH), 256, smemSWA, s2>>>(qb, kb, vb, catb);
    cudaEventRecord(ev_join, s2);

    chunk_kv_v6<<<BATCH * NH * NCHUNK * 2, 320, smemKV>>>(kb, vb, Wkf, ckv2);
    prefix_kv_v4<<<(32 * FPH * 72 + 255) / 256, 256>>>(ckv2, ckvb);
    lin_attn_v6<<<BATCH * NH * NCHUNK, 256, smemLin>>>(qb, kb, vb, Wqf, Wkf, ckvb, catb);

    cudaStreamWaitEvent(0, ev_join, 0);

    gemmb<<<dim3(DMODEL / 128, ROWS / 128), 256, smemG>>>(catb, woutt, out, x, 2 * DMODEL, DMODEL);
}

// round 17
// speedup vs baseline: 1.5260x; 1.0029x over previous
#include <cuda_runtime.h>
#include <cuda_bf16.h>
#include <cstdint>

#define BATCH 2
#define SEQ 2048
#define DMODEL 1024
#define NH 16
#define HD 64
#define FEAT 16
#define FDIM 153           // 1 + 16 + 136
#define FPAD 160
#define NCHUNK 16
#define CHUNKSZ 128
#define ROWS (BATCH*SEQ)          // 4096
#define HROWS (BATCH*SEQ*NH)      // 131072
#define FPH (FPAD/2)              // 80 feature pairs

// ------------------------- scratch (static device memory) -------------------
__device__ __nv_bfloat16 g_hb[ROWS*DMODEL];
__device__ __nv_bfloat16 g_wqt[DMODEL*DMODEL];
__device__ __nv_bfloat16 g_wkt[DMODEL*DMODEL];
__device__ __nv_bfloat16 g_wvt[DMODEL*DMODEL];
__device__ __nv_bfloat16 g_woutt[DMODEL*2*DMODEL];
__device__ __nv_bfloat16 g_catb[(size_t)ROWS*2*DMODEL];
__device__ __nv_bfloat16 g_qb[ROWS*DMODEL];
__device__ __nv_bfloat16 g_kb[ROWS*DMODEL];
__device__ __nv_bfloat16 g_vb[ROWS*DMODEL];
__device__ float g_ckv2[(size_t)BATCH*NH*NCHUNK*2*FPAD*72];
__device__ uint32_t g_ckvb[(size_t)BATCH*NH*NCHUNK*FPH*72];   // bf16x2 feature pairs

__device__ __forceinline__ void mma16bf(float acc[4], uint32_t a0, uint32_t a1,
                                        uint32_t a2, uint32_t a3,
                                        uint32_t b0, uint32_t b1) {
    asm volatile(
        "mma.sync.aligned.m16n8k16.row.col.f32.bf16.bf16.f32 "
        "{%0,%1,%2,%3}, {%4,%5,%6,%7}, {%8,%9}, {%0,%1,%2,%3};"
        : "+f"(acc[0]), "+f"(acc[1]), "+f"(acc[2]), "+f"(acc[3])
        : "r"(a0), "r"(a1), "r"(a2), "r"(a3), "r"(b0), "r"(b1));
}

__device__ __forceinline__ void mma8(float acc[4], uint32_t a0, uint32_t a1,
                                     uint32_t a2, uint32_t a3,
                                     uint32_t b0, uint32_t b1) {
    asm volatile(
        "mma.sync.aligned.m16n8k8.row.col.f32.tf32.tf32.f32 "
        "{%0,%1,%2,%3}, {%4,%5,%6,%7}, {%8,%9}, {%0,%1,%2,%3};"
        : "+f"(acc[0]), "+f"(acc[1]), "+f"(acc[2]), "+f"(acc[3])
        : "r"(a0), "r"(a1), "r"(a2), "r"(a3), "r"(b0), "r"(b1));
}

__device__ __forceinline__ void cp16(uint32_t sdst, const void* gsrc) {
    asm volatile("cp.async.cg.shared.global [%0], [%1], 16;" :: "r"(sdst), "l"(gsrc));
}

__device__ __forceinline__ uint32_t bf16pack(float lo, float hi) {
    uint32_t u;
    asm("cvt.rn.bf16x2.f32 %0, %1, %2;" : "=r"(u) : "f"(hi), "f"(lo));
    return u;
}

// load 4 consecutive bf16 -> 4 floats
__device__ __forceinline__ void ld4bf(const __nv_bfloat16* p, float* o) {
    uint2 u = *(const uint2*)p;
    float2 f0 = __bfloat1622float2(*(__nv_bfloat162*)&u.x);
    float2 f1 = __bfloat1622float2(*(__nv_bfloat162*)&u.y);
    o[0] = f0.x; o[1] = f0.y; o[2] = f1.x; o[3] = f1.y;
}

// phi expansion -> bf16x2-packed col-major (feature pairs): dst[(f>>1)*132 + tok]
__device__ __forceinline__ void write_phi_colmajor_bf(uint32_t* dst, int tok,
                                                      const float* xf) {
    float x[16];
    #pragma unroll
    for (int i = 0; i < 16; i++) x[i] = xf[i];
    const float inv = 0.70710678118654752440f;
    float pend = 0.f;
    #define PHI_EMIT(IDX, V) { if ((IDX) & 1) dst[((IDX) >> 1) * 132 + tok] = bf16pack(pend, (V)); else pend = (V); }
    PHI_EMIT(0, 1.f);
    #pragma unroll
    for (int i = 0; i < 16; i++) PHI_EMIT(1 + i, x[i]);
    int idx = 17;
    #pragma unroll
    for (int i = 0; i < 16; i++) {
        PHI_EMIT(idx, 0.5f * x[i] * x[i]); idx++;
        #pragma unroll
        for (int j = i + 1; j < 16; j++) { PHI_EMIT(idx, inv * x[i] * x[j]); idx++; }
    }
    #pragma unroll
    for (int f = FDIM; f < FPAD; f++) PHI_EMIT(f, 0.f);
    #undef PHI_EMIT
}

// phi expansion -> bf16 [feature][token] layout (stride 72 bf16), half-split
__device__ __forceinline__ void write_phi_ftok_half(__nv_bfloat16* dstb, int tok,
                                                    const float* xf, int h) {
    float x[16];
    #pragma unroll
    for (int i = 0; i < 16; i++) x[i] = xf[i];
    const float inv = 0.70710678118654752440f;
    #define EMITF(F, V) dstb[(F) * 72 + tok] = __float2bfloat16(V)
    if (h == 0) {
        EMITF(0, 1.f);
        #pragma unroll
        for (int i = 0; i < 16; i += 2) {
            int idx = 17 + i * 16 - (i * (i - 1)) / 2;
            EMITF(idx, 0.5f * x[i] * x[i]); idx++;
            #pragma unroll
            for (int j = i + 1; j < 16; j++) { EMITF(idx, inv * x[i] * x[j]); idx++; }
        }
        #pragma unroll
        for (int f = FDIM; f < FPAD; f++) EMITF(f, 0.f);
    } else {
        #pragma unroll
        for (int i = 0; i < 16; i++) EMITF(1 + i, x[i]);
        #pragma unroll
        for (int i = 1; i < 16; i += 2) {
            int idx = 17 + i * 16 - (i * (i - 1)) / 2;
            EMITF(idx, 0.5f * x[i] * x[i]); idx++;
            #pragma unroll
            for (int j = i + 1; j < 16; j++) { EMITF(idx, inv * x[i] * x[j]); idx++; }
        }
    }
    #undef EMITF
}

// ---------------- weight transpose + fp32->bf16 convert ----------------------
__global__ void transpose_bf16(const float* __restrict__ W, __nv_bfloat16* __restrict__ Wt,
                               int K, int N) {
    __shared__ float tile[32][33];
    int n0 = blockIdx.x * 32, k0 = blockIdx.y * 32;
    int tx = threadIdx.x & 31, ty = threadIdx.x >> 5;
    #pragma unroll
    for (int j = 0; j < 32; j += 8)
        tile[ty + j][tx] = W[(size_t)(k0 + ty + j) * N + n0 + tx];
    __syncthreads();
    #pragma unroll
    for (int j = 0; j < 32; j += 8)
        Wt[(size_t)(n0 + ty + j) * K + k0 + tx] = __float2bfloat16(tile[tx][ty + j]);
}

// ------------------------- RMSNorm (float4 in, bf16 out) ---------------------
__global__ void rmsnorm_kernel(const float* __restrict__ x,
                               const float* __restrict__ w,
                               __nv_bfloat16* __restrict__ hb) {
    int row = blockIdx.x;
    const float4* xr = (const float4*)(x + (size_t)row * DMODEL);
    float4 t = xr[threadIdx.x];
    float s = t.x * t.x + t.y * t.y + t.z * t.z + t.w * t.w;
    __shared__ float red[8];
    #pragma unroll
    for (int o = 16; o > 0; o >>= 1) s += __shfl_xor_sync(0xffffffffu, s, o);
    if ((threadIdx.x & 31) == 0) red[threadIdx.x >> 5] = s;
    __syncthreads();
    if (threadIdx.x < 8) {
        float v = red[threadIdx.x];
        #pragma unroll
        for (int o = 4; o > 0; o >>= 1) v += __shfl_xor_sync(0xffu, v, o);
        if (threadIdx.x == 0) red[0] = v;
    }
    __syncthreads();
    float rs = rsqrtf(red[0] / (float)DMODEL + 1e-6f);
    float4 wv = ((const float4*)w)[threadIdx.x];
    uint32_t p0 = bf16pack(t.x * rs * wv.x, t.y * rs * wv.y);
    uint32_t p1 = bf16pack(t.z * rs * wv.z, t.w * rs * wv.w);
    ((uint2*)(hb + (size_t)row * DMODEL))[threadIdx.x] = make_uint2(p0, p1);
}

// ---------------- BF16 GEMM: cp.async 4-stage, k-tile 32, m16n8k16 ------------
#define ASB_ELE (128*20)
#define BSB_ELE (128*20)
#define NSTAGEB 4

__device__ __forceinline__ void gemmb_issue(const __nv_bfloat16* A, const __nv_bfloat16* Bt,
        uint32_t* As, uint32_t* Bs, int bm, int bn, int k0, int lda, int ldb, int tid) {
    #pragma unroll
    for (int j = 0; j < 2; j++) {
        int c = tid + j * 256;
        int m = c >> 2, seg = c & 3;
        cp16((uint32_t)__cvta_generic_to_shared(As + m * 20 + seg * 4),
             A + (size_t)(bm + m) * lda + k0 + seg * 8);
    }
    #pragma unroll
    for (int j = 0; j < 2; j++) {
        int c = tid + j * 256;
        int n = c >> 2, seg = c & 3;
        cp16((uint32_t)__cvta_generic_to_shared(Bs + n * 20 + seg * 4),
             Bt + (size_t)(bn + n) * ldb + k0 + seg * 8);
    }
}

template<bool BF16OUT>
__device__ __forceinline__ void gemmb_core(const __nv_bfloat16* A, const __nv_bfloat16* Bt,
        void* Cout, const float* residual, uint32_t* As, uint32_t* Bs,
        int bm, int bn, int K, int N, int lda, int ldb, int tid) {
    int warp = tid >> 5, lane = tid & 31;
    int wm = (warp >> 2) * 64, wn = (warp & 3) * 32;
    int r = lane >> 2, cq = lane & 3;

    float acc[4][4][4];
    #pragma unroll
    for (int mi = 0; mi < 4; mi++)
        #pragma unroll
        for (int ni = 0; ni < 4; ni++)
            #pragma unroll
            for (int e = 0; e < 4; e++) acc[mi][ni][e] = 0.f;

    int nk = K / 32;
    gemmb_issue(A, Bt, As, Bs, bm, bn, 0, lda, ldb, tid);
    asm volatile("cp.async.commit_group;");
    gemmb_issue(A, Bt, As + ASB_ELE, Bs + BSB_ELE, bm, bn, 32, lda, ldb, tid);
    asm volatile("cp.async.commit_group;");
    gemmb_issue(A, Bt, As + 2 * ASB_ELE, Bs + 2 * BSB_ELE, bm, bn, 64, lda, ldb, tid);
    asm volatile("cp.async.commit_group;");

    for (int kt = 0; kt < nk; kt++) {
        if (kt + 3 < nk) {
            int slot = (kt + 3) & 3;
            gemmb_issue(A, Bt, As + slot * ASB_ELE, Bs + slot * BSB_ELE,
                        bm, bn, (kt + 3) * 32, lda, ldb, tid);
        }
        asm volatile("cp.async.commit_group;");
        asm volatile("cp.async.wait_group 3;");
        __syncthreads();
        const uint32_t* Au = As + (kt & 3) * ASB_ELE;
        const uint32_t* Bu = Bs + (kt & 3) * BSB_ELE;
        #pragma unroll
        for (int ks = 0; ks < 16; ks += 8) {
            uint32_t af[4][4], bf[4][2];
            #pragma unroll
            for (int mi = 0; mi < 4; mi++) {
                int m = wm + mi * 16 + r;
                af[mi][0] = Au[m * 20 + ks + cq];
                af[mi][1] = Au[(m + 8) * 20 + ks + cq];
                af[mi][2] = Au[m * 20 + ks + cq + 4];
                af[mi][3] = Au[(m + 8) * 20 + ks + cq + 4];
            }
            #pragma unroll
            for (int ni = 0; ni < 4; ni++) {
                int n = wn + ni * 8 + r;
                bf[ni][0] = Bu[n * 20 + ks + cq];
                bf[ni][1] = Bu[n * 20 + ks + cq + 4];
            }
            #pragma unroll
            for (int mi = 0; mi < 4; mi++)
                #pragma unroll
                for (int ni = 0; ni < 4; ni++)
                    mma16bf(acc[mi][ni], af[mi][0], af[mi][1], af[mi][2], af[mi][3],
                            bf[ni][0], bf[ni][1]);
        }
        __syncthreads();
    }

    #pragma unroll
    for (int mi = 0; mi < 4; mi++) {
        int row0 = bm + wm + mi * 16 + r;
        #pragma unroll
        for (int ni = 0; ni < 4; ni++) {
            int col = bn + wn + ni * 8 + 2 * cq;
            if (BF16OUT) {
                __nv_bfloat16* Cb = (__nv_bfloat16*)Cout;
                *(uint32_t*)(Cb + (size_t)row0 * N + col) =
                    bf16pack(acc[mi][ni][0], acc[mi][ni][1]);
                *(uint32_t*)(Cb + (size_t)(row0 + 8) * N + col) =
                    bf16pack(acc[mi][ni][2], acc[mi][ni][3]);
            } else {
                float* C = (float*)Cout;
                float2 lo = make_float2(acc[mi][ni][0], acc[mi][ni][1]);
                float2 hi = make_float2(acc[mi][ni][2], acc[mi][ni][3]);
                if (residual) {
                    float2 r0 = *(const float2*)(residual + (size_t)row0 * N + col);
                    float2 r1 = *(const float2*)(residual + (size_t)(row0 + 8) * N + col);
                    lo.x += r0.x; lo.y += r0.y; hi.x += r1.x; hi.y += r1.y;
                }
                *(float2*)(C + (size_t)row0 * N + col) = lo;
                *(float2*)(C + (size_t)(row0 + 8) * N + col) = hi;
            }
        }
    }
}

__global__ __launch_bounds__(256) void gemmb(
        const __nv_bfloat16* __restrict__ A, const __nv_bfloat16* __restrict__ Bt,
        float* __restrict__ C, const float* __restrict__ residual,
        int K, int N, int lda, int ldb) {
    extern __shared__ uint32_t sgb[];
    gemmb_core<false>(A, Bt, C, residual, sgb, sgb + NSTAGEB * ASB_ELE,
                      blockIdx.y * 128, blockIdx.x * 128, K, N, lda, ldb, threadIdx.x);
}

__global__ __launch_bounds__(256) void gemmb_qkv(
        const __nv_bfloat16* __restrict__ A,
        const __nv_bfloat16* __restrict__ Bq, const __nv_bfloat16* __restrict__ Bk,
        const __nv_bfloat16* __restrict__ Bv,
        __nv_bfloat16* __restrict__ Cq, __nv_bfloat16* __restrict__ Ck,
        __nv_bfloat16* __restrict__ Cv) {
    extern __shared__ uint32_t sgb[];
    const __nv_bfloat16* Bt = (blockIdx.z == 0) ? Bq : (blockIdx.z == 1) ? Bk : Bv;
    __nv_bfloat16* C = (blockIdx.z == 0) ? Cq : (blockIdx.z == 1) ? Ck : Cv;
    gemmb_core<true>(A, Bt, C, nullptr, sgb, sgb + NSTAGEB * ASB_ELE,
                     blockIdx.y * 128, blockIdx.x * 128, DMODEL, DMODEL,
                     DMODEL, DMODEL, threadIdx.x);
}

// --------- pass A: half-chunk fused feat-proj + phi + partial KV' (bf16) ------
__global__ __launch_bounds__(320) void chunk_kv_v6(const __nv_bfloat16* __restrict__ kb_,
        const __nv_bfloat16* __restrict__ vb_, const float* __restrict__ Wkf,
        float* __restrict__ ckv2) {
    extern __shared__ uint32_t su[];
    uint32_t* Ks2 = su;             // [160][36] uints (bf16 [feat][tok72])
    uint32_t* Vs2 = su + 160 * 36;  // [72][36] uints
    float* Kf = (float*)Ks2;
    float* Sf = (float*)Vs2;
    int tid = threadIdx.x, warp = tid >> 5, lane = tid & 31;
    int r = lane >> 2, cq = lane & 3;
    int bid = blockIdx.x;
    int half = bid & 1, bhc = bid >> 1;
    int c = bhc & 15, bh = bhc >> 4, b = bh >> 4, hh = bh & 15;
    size_t row0 = (size_t)(b * SEQ + c * CHUNKSZ + half * 64) * DMODEL + hh * HD;

    for (int i = tid; i < 64 * 16; i += 320) {
        int tok = i >> 4, qd = (i & 15) * 4;
        ld4bf(kb_ + row0 + (size_t)tok * DMODEL + qd, Kf + tok * 68 + qd);
    }
    for (int i = tid; i < 1024; i += 320) Sf[i] = Wkf[i];
    __syncthreads();

    if (tid < 256) {
        int tok = tid >> 2, qm = (tid & 3) * 4;
        float accf[4];
        #pragma unroll
        for (int cc = 0; cc < 4; cc++) accf[cc] = 0.f;
        for (int e = 0; e < 64; e++) {
            float rv = Kf[tok * 68 + e];
            #pragma unroll
            for (int cc = 0; cc < 4; cc++) accf[cc] += rv * Sf[e * 16 + qm + cc];
        }
        #pragma unroll
        for (int cc = 0; cc < 4; cc++) Sf[1024 + tok * 16 + qm + cc] = accf[cc];
    }
    __syncthreads();
    if (tid < 128) {
        int tok = tid >> 1, hm = tid & 1;
        write_phi_ftok_half((__nv_bfloat16*)Ks2, tok, Sf + 1024 + tok * 16, hm);
    }
    __syncthreads();

    {
        __nv_bfloat16* Vb = (__nv_bfloat16*)Vs2;
        const __nv_bfloat16 one = __float2bfloat16(1.f);
        const __nv_bfloat16 zero = __float2bfloat16(0.f);
        for (int i = tid; i < 64 * 18; i += 320) {
            int tok = i / 18, qd = (i % 18) * 4;
            if (qd < 64) {
                uint2 u = *(const uint2*)(vb_ + row0 + (size_t)tok * DMODEL + qd);
                const __nv_bfloat16* pv = (const __nv_bfloat16*)&u;
                #pragma unroll
                for (int e = 0; e < 4; e++) Vb[(qd + e) * 72 + tok] = pv[e];
            } else {
                #pragma unroll
                for (int e = 0; e < 4; e++)
                    Vb[(qd + e) * 72 + tok] = (qd + e == 64) ? one : zero;
            }
        }
    }
    __syncthreads();

    float acc[9][4];
    #pragma unroll
    for (int ni = 0; ni < 9; ni++)
        #pragma unroll
        for (int e = 0; e < 4; e++) acc[ni][e] = 0.f;
    int m0 = warp * 16;
    for (int kp = 0; kp < 32; kp += 8) {
        uint32_t a0 = Ks2[(m0 + r) * 36 + kp + cq];
        uint32_t a1 = Ks2[(m0 + r + 8) * 36 + kp + cq];
        uint32_t a2 = Ks2[(m0 + r) * 36 + kp + cq + 4];
        uint32_t a3 = Ks2[(m0 + r + 8) * 36 + kp + cq + 4];
        #pragma unroll
        for (int ni = 0; ni < 9; ni++) {
            uint32_t b0 = Vs2[(ni * 8 + r) * 36 + kp + cq];
            uint32_t b1 = Vs2[(ni * 8 + r) * 36 + kp + cq + 4];
            mma16bf(acc[ni], a0, a1, a2, a3, b0, b1);
        }
    }
    float* outb = ckv2 + (size_t)bid * FPAD * 72;
    #pragma unroll
    for (int ni = 0; ni < 9; ni++) {
        int n = ni * 8 + 2 * cq;
        *(float2*)(outb + (m0 + r) * 72 + n)     = make_float2(acc[ni][0], acc[ni][1]);
        *(float2*)(outb + (m0 + r + 8) * 72 + n) = make_float2(acc[ni][2], acc[ni][3]);
    }
}

// --------- pass B: exclusive prefix over chunks -> bf16x2 feature pairs -------
__global__ void prefix_kv_v4(const float* __restrict__ ckv2, uint32_t* __restrict__ ckvb) {
    const int FD = FPAD * 72;
    const int PD = FPH * 72;
    int idx = blockIdx.x * 256 + threadIdx.x;
    if (idx >= 32 * PD) return;
    int bh = idx / PD, e = idx % PD;
    int fp = e / 72, n = e % 72;
    size_t o0 = (size_t)(2 * fp) * 72 + n;
    size_t o1 = o0 + 72;
    float run0 = 0.f, run1 = 0.f;
    for (int c = 0; c < NCHUNK; c++) {
        size_t bc = (size_t)(bh * NCHUNK + c);
        ckvb[bc * PD + e] = bf16pack(run0, run1);
        run0 += ckv2[(bc * 2) * FD + o0] + ckv2[(bc * 2 + 1) * FD + o0];
        run1 += ckv2[(bc * 2) * FD + o1] + ckv2[(bc * 2 + 1) * FD + o1];
    }
}

// --------- pass C: fused feat-proj + phi + linear attention (bf16 mma) --------
__global__ __launch_bounds__(256) void lin_attn_v6(const __nv_bfloat16* __restrict__ qb_,
        const __nv_bfloat16* __restrict__ kb_, const __nv_bfloat16* __restrict__ vb_,
        const float* __restrict__ Wqf, const float* __restrict__ Wkf,
        const uint32_t* __restrict__ ckvb, __nv_bfloat16* __restrict__ catb) {
    extern __shared__ uint32_t su[];
    uint32_t* Qs  = su;                  // [kp 80][132]
    uint32_t* Ks  = su + 80 * 132;       // [kp 80][132]
    uint32_t* KVs = Ks + 80 * 132;       // [kp 80][88]
    uint32_t* Am  = Ks;                  // overlay [sp 64][132]
    uint32_t* Vs  = Ks + 64 * 132;       // overlay [sp 64][88]
    float* Qraw = (float*)Qs;
    float* Kraw = (float*)Ks;
    float* Scr  = (float*)KVs;
    int tid = threadIdx.x, warp = tid >> 5, lane = tid & 31;
    int r = lane >> 2, cq = lane & 3;
    int bhc = blockIdx.x, c = bhc & 15, bh = bhc >> 4, b = bh >> 4, hh = bh & 15;
    size_t row0 = (size_t)(b * SEQ + c * CHUNKSZ) * DMODEL + hh * HD;

    for (int i = tid; i < 128 * 16; i += 256) {
        int tok = i >> 4, qd = (i & 15) * 4;
        ld4bf(qb_ + row0 + (size_t)tok * DMODEL + qd, Qraw + tok * 68 + qd);
        ld4bf(kb_ + row0 + (size_t)tok * DMODEL + qd, Kraw + tok * 68 + qd);
    }
    for (int i = tid; i < 1024; i += 256) { Scr[i] = Wqf[i]; Scr[1024 + i] = Wkf[i]; }
    __syncthreads();

    {
        int tok = tid & 127, which = tid >> 7;
        const float* raw = which ? Kraw : Qraw;
        const float* W   = Scr + which * 1024;
        float* of        = Scr + 2048 + which * 2048;
        float accf[16];
        #pragma unroll
        for (int cc = 0; cc < 16; cc++) accf[cc] = 0.f;
        for (int e = 0; e < 64; e++) {
            float rv = raw[tok * 68 + e];
            #pragma unroll
            for (int cc = 0; cc < 16; cc++) accf[cc] += rv * W[e * 16 + cc];
        }
        #pragma unroll
        for (int cc = 0; cc < 16; cc++) of[tok * 16 + cc] = accf[cc];
    }
    __syncthreads();
    {
        int tok = tid & 127, which = tid >> 7;
        uint32_t* dst = which ? Ks : Qs;
        write_phi_colmajor_bf(dst, tok, Scr + 2048 + which * 2048 + tok * 16);
    }
    __syncthreads();

    const uint32_t* kvb = ckvb + (size_t)bhc * FPH * 72;
    for (int i = tid; i < 80 * 72; i += 256) {
        int kp = i / 72, n = i % 72;
        KVs[kp * 88 + n] = kvb[kp * 72 + n];
    }
    __syncthreads();

    float accy[9][4];
    #pragma unroll
    for (int ni = 0; ni < 9; ni++)
        #pragma unroll
        for (int e = 0; e < 4; e++) accy[ni][e] = 0.f;
    int m0 = warp * 16;
    for (int kp = 0; kp < 80; kp += 8) {
        uint32_t a0 = Qs[(kp + cq) * 132 + m0 + r];
        uint32_t a1 = Qs[(kp + cq) * 132 + m0 + r + 8];
        uint32_t a2 = Qs[(kp + cq + 4) * 132 + m0 + r];
        uint32_t a3 = Qs[(kp + cq + 4) * 132 + m0 + r + 8];
        #pragma unroll
        for (int ni = 0; ni < 9; ni++) {
            uint32_t b0 = KVs[(kp + cq) * 88 + ni * 8 + r];
            uint32_t b1 = KVs[(kp + cq + 4) * 88 + ni * 8 + r];
            mma16bf(accy[ni], a0, a1, a2, a3, b0, b1);
        }
    }

    float acc1[4][4][4];
    #pragma unroll
    for (int mi = 0; mi < 4; mi++)
        #pragma unroll
        for (int ni = 0; ni < 4; ni++)
            #pragma unroll
            for (int e = 0; e < 4; e++) acc1[mi][ni][e] = 0.f;
    int wm = (warp >> 2) * 64, wn = (warp & 3) * 32;
    for (int kp = 0; kp < 80; kp += 8) {
        uint32_t af[4][4];
        #pragma unroll
        for (int mi = 0; mi < 4; mi++) {
            int m = wm + mi * 16;
            af[mi][0] = Qs[(kp + cq) * 132 + m + r];
            af[mi][1] = Qs[(kp + cq) * 132 + m + r + 8];
            af[mi][2] = Qs[(kp + cq + 4) * 132 + m + r];
            af[mi][3] = Qs[(kp + cq + 4) * 132 + m + r + 8];
        }
        #pragma unroll
        for (int ni = 0; ni < 4; ni++) {
            uint32_t b0 = Ks[(kp + cq) * 132 + wn + ni * 8 + r];
            uint32_t b1 = Ks[(kp + cq + 4) * 132 + wn + ni * 8 + r];
            #pragma unroll
            for (int mi = 0; mi < 4; mi++)
                mma16bf(acc1[mi][ni], af[mi][0], af[mi][1], af[mi][2], af[mi][3], b0, b1);
        }
    }
    __syncthreads();

    #pragma unroll
    for (int mi = 0; mi < 4; mi++) {
        int row = wm + mi * 16 + r;
        #pragma unroll
        for (int ni = 0; ni < 4; ni++) {
            int col = wn + ni * 8 + 2 * cq;
            float v0 = (col     <= row)     ? acc1[mi][ni][0] : 0.f;
            float v1 = (col + 1 <= row)     ? acc1[mi][ni][1] : 0.f;
            float v2 = (col     <= row + 8) ? acc1[mi][ni][2] : 0.f;
            float v3 = (col + 1 <= row + 8) ? acc1[mi][ni][3] : 0.f;
            Am[(col >> 1) * 132 + row]     = bf16pack(v0, v1);
            Am[(col >> 1) * 132 + row + 8] = bf16pack(v2, v3);
        }
    }
    {
        __nv_bfloat16* Vb = (__nv_bfloat16*)Vs;
        const __nv_bfloat16 one = __float2bfloat16(1.f);
        const __nv_bfloat16 zero = __float2bfloat16(0.f);
        for (int i = tid; i < 128 * 18; i += 256) {
            int tok = i / 18, qd = (i % 18) * 4;
            if (qd < 64) {
                uint2 u = *(const uint2*)(vb_ + row0 + (size_t)tok * DMODEL + qd);
                const __nv_bfloat16* pv = (const __nv_bfloat16*)&u;
                #pragma unroll
                for (int e = 0; e < 4; e++)
                    Vb[((size_t)(tok >> 1) * 88 + qd + e) * 2 + (tok & 1)] = pv[e];
            } else {
                #pragma unroll
                for (int e = 0; e < 4; e++)
                    Vb[((size_t)(tok >> 1) * 88 + qd + e) * 2 + (tok & 1)] =
                        (qd + e == 64) ? one : zero;
            }
        }
    }
    __syncthreads();

    for (int sp = 0; sp < 64; sp += 8) {
        uint32_t a0 = Am[(sp + cq) * 132 + m0 + r];
        uint32_t a1 = Am[(sp + cq) * 132 + m0 + r + 8];
        uint32_t a2 = Am[(sp + cq + 4) * 132 + m0 + r];
        uint32_t a3 = Am[(sp + cq + 4) * 132 + m0 + r + 8];
        #pragma unroll
        for (int ni = 0; ni < 9; ni++) {
            uint32_t b0 = Vs[(sp + cq) * 88 + ni * 8 + r];
            uint32_t b1 = Vs[(sp + cq + 4) * 88 + ni * 8 + r];
            mma16bf(accy[ni], a0, a1, a2, a3, b0, b1);
        }
    }

    float zlo = __shfl_sync(0xffffffffu, accy[8][0], lane & 28) + 1e-6f;
    float zhi = __shfl_sync(0xffffffffu, accy[8][2], lane & 28) + 1e-6f;
    float izlo = 1.f / zlo, izhi = 1.f / zhi;
    size_t rowg = (size_t)(b * SEQ + c * CHUNKSZ + m0 + r);
    #pragma unroll
    for (int ni = 0; ni < 8; ni++) {
        int colg = hh * HD + ni * 8 + 2 * cq;
        *(uint32_t*)(catb + rowg * (2 * DMODEL) + colg) =
            bf16pack(accy[ni][0] * izlo, accy[ni][1] * izlo);
        *(uint32_t*)(catb + (rowg + 8) * (2 * DMODEL) + colg) =
            bf16pack(accy[ni][2] * izhi, accy[ni][3] * izhi);
    }
}

// ---------------- sliding-window attention (256 thr, warp-pair) --------------
__global__ __launch_bounds__(256) void swa_v5(const __nv_bfloat16* __restrict__ qb_,
        const __nv_bfloat16* __restrict__ kb_, const __nv_bfloat16* __restrict__ vb_,
        __nv_bfloat16* __restrict__ catb) {
    extern __shared__ uint32_t su[];
    uint32_t* Qs = su;
    uint32_t* Ks = Qs + 64 * 68;
    uint32_t* Ps = Ks + 64 * 132;
    uint32_t* Vs = Ps + 128 * 68;
    float* red   = (float*)(Vs + 128 * 68);
    float* Osm   = (float*)Qs;
    int tid = threadIdx.x, warp = tid >> 5, lane = tid & 31;
    int r = lane >> 2, cq = lane & 3;
    int g = warp & 3, half = warp >> 2;
    int m0 = g * 16;
    int q0 = blockIdx.x * 64, hh = blockIdx.y, b = blockIdx.z;

    for (int i = tid; i < 64 * 16; i += 256) {
        int tok = i >> 4, qd = (i & 15) * 4;
        float f[4];
        ld4bf(qb_ + (size_t)(b * SEQ + q0 + tok) * DMODEL + hh * HD + qd, f);
        #pragma unroll
        for (int e = 0; e < 4; e++) Qs[(qd + e) * 68 + tok] = __float_as_uint(f[e]);
    }
    for (int i = tid; i < 128 * 16; i += 256) {
        int key = i >> 4, qd = (i & 15) * 4;
        int kg = q0 - 64 + key;
        float fk[4] = {0.f, 0.f, 0.f, 0.f};
        float fv[4] = {0.f, 0.f, 0.f, 0.f};
        if (kg >= 0) {
            ld4bf(kb_ + (size_t)(b * SEQ + kg) * DMODEL + hh * HD + qd, fk);
            ld4bf(vb_ + (size_t)(b * SEQ + kg) * DMODEL + hh * HD + qd, fv);
        }
        #pragma unroll
        for (int e = 0; e < 4; e++) Ks[(qd + e) * 132 + key] = __float_as_uint(fk[e]);
        *(uint4*)(Vs + key * 68 + qd) =
            make_uint4(__float_as_uint(fv[0]), __float_as_uint(fv[1]),
                       __float_as_uint(fv[2]), __float_as_uint(fv[3]));
    }
    __syncthreads();

    float acc[8][4];
    #pragma unroll
    for (int ni = 0; ni < 8; ni++)
        #pragma unroll
        for (int e = 0; e < 4; e++) acc[ni][e] = 0.f;
    for (int kk = 0; kk < 64; kk += 8) {
        uint32_t a0 = Qs[(kk + cq) * 68 + m0 + r];
        uint32_t a1 = Qs[(kk + cq) * 68 + m0 + r + 8];
        uint32_t a2 = Qs[(kk + cq + 4) * 68 + m0 + r];
        uint32_t a3 = Qs[(kk + cq + 4) * 68 + m0 + r + 8];
        #pragma unroll
        for (int ni = 0; ni < 8; ni++) {
            int gn = half * 8 + ni;
            uint32_t b0 = Ks[(kk + cq) * 132 + gn * 8 + r];
            uint32_t b1 = Ks[(kk + cq + 4) * 132 + gn * 8 + r];
            mma8(acc[ni], a0, a1, a2, a3, b0, b1);
        }
    }

    int rowlo = m0 + r, rowhi = rowlo + 8;
    float mlo = -1e30f, mhi = -1e30f;
    #pragma unroll
    for (int ni = 0; ni < 8; ni++) {
        int n = (half * 8 + ni) * 8 + 2 * cq;
        bool ok0l = (n     >= rowlo) && (n     <= rowlo + 64) && (q0 - 64 + n     >= 0);
        bool ok1l = (n + 1 >= rowlo) && (n + 1 <= rowlo + 64) && (q0 - 64 + n + 1 >= 0);
        bool ok0h = (n     >= rowhi) && (n     <= rowhi + 64) && (q0 - 64 + n     >= 0);
        bool ok1h = (n + 1 >= rowhi) && (n + 1 <= rowhi + 64) && (q0 - 64 + n + 1 >= 0);
        acc[ni][0] = ok0l ? acc[ni][0] * 0.125f : -1e30f;
        acc[ni][1] = ok1l ? acc[ni][1] * 0.125f : -1e30f;
        acc[ni][2] = ok0h ? acc[ni][2] * 0.125f : -1e30f;
        acc[ni][3] = ok1h ? acc[ni][3] * 0.125f : -1e30f;
        mlo = fmaxf(mlo, fmaxf(acc[ni][0], acc[ni][1]));
        mhi = fmaxf(mhi, fmaxf(acc[ni][2], acc[ni][3]));
    }
    mlo = fmaxf(mlo, __shfl_xor_sync(0xffffffffu, mlo, 1));
    mlo = fmaxf(mlo, __shfl_xor_sync(0xffffffffu, mlo, 2));
    mhi = fmaxf(mhi, __shfl_xor_sync(0xffffffffu, mhi, 1));
    mhi = fmaxf(mhi, __shfl_xor_sync(0xffffffffu, mhi, 2));
    if (cq == 0) {
        red[rowlo * 2 + half] = mlo;
        red[rowhi * 2 + half] = mhi;
    }
    __syncthreads();
    float Mlo = fmaxf(red[rowlo * 2], red[rowlo * 2 + 1]);
    float Mhi = fmaxf(red[rowhi * 2], red[rowhi * 2 + 1]);

    float slo = 0.f, shi = 0.f;
    #pragma unroll
    for (int ni = 0; ni < 8; ni++) {
        acc[ni][0] = __expf(acc[ni][0] - Mlo);
        acc[ni][1] = __expf(acc[ni][1] - Mlo);
        acc[ni][2] = __expf(acc[ni][2] - Mhi);
        acc[ni][3] = __expf(acc[ni][3] - Mhi);
        slo += acc[ni][0] + acc[ni][1];
        shi += acc[ni][2] + acc[ni][3];
    }
    slo += __shfl_xor_sync(0xffffffffu, slo, 1);
    slo += __shfl_xor_sync(0xffffffffu, slo, 2);
    shi += __shfl_xor_sync(0xffffffffu, shi, 1);
    shi += __shfl_xor_sync(0xffffffffu, shi, 2);
    if (cq == 0) {
        red[128 + rowlo * 2 + half] = slo;
        red[128 + rowhi * 2 + half] = shi;
    }

    #pragma unroll
    for (int ni = 0; ni < 8; ni++) {
        int n = (half * 8 + ni) * 8 + 2 * cq;
        Ps[n * 68 + rowlo]       = __float_as_uint(acc[ni][0]);
        Ps[(n + 1) * 68 + rowlo] = __float_as_uint(acc[ni][1]);
        Ps[n * 68 + rowhi]       = __float_as_uint(acc[ni][2]);
        Ps[(n + 1) * 68 + rowhi] = __float_as_uint(acc[ni][3]);
    }
    __syncthreads();
    float sumlo = red[128 + rowlo * 2] + red[128 + rowlo * 2 + 1];
    float sumhi = red[128 + rowhi * 2] + red[128 + rowhi * 2 + 1];

    float accO[8][4];
    #pragma unroll
    for (int ni = 0; ni < 8; ni++)
        #pragma unroll
        for (int e = 0; e < 4; e++) accO[ni][e] = 0.f;
    for (int ks = 0; ks < 64; ks += 8) {
        int kk = half * 64 + ks;
        uint32_t a0 = Ps[(kk + cq) * 68 + m0 + r];
        uint32_t a1 = Ps[(kk + cq) * 68 + m0 + r + 8];
        uint32_t a2 = Ps[(kk + cq + 4) * 68 + m0 + r];
        uint32_t a3 = Ps[(kk + cq + 4) * 68 + m0 + r + 8];
        #pragma unroll
        for (int ni = 0; ni < 8; ni++) {
            uint32_t b0 = Vs[(kk + cq) * 68 + ni * 8 + r];
            uint32_t b1 = Vs[(kk + cq + 4) * 68 + ni * 8 + r];
            mma8(accO[ni], a0, a1, a2, a3, b0, b1);
        }
    }
    if (half == 1) {
        #pragma unroll
        for (int ni = 0; ni < 8; ni++) {
            int n = ni * 8 + 2 * cq;
            Osm[rowlo * 68 + n]     = accO[ni][0];
            Osm[rowlo * 68 + n + 1] = accO[ni][1];
            Osm[rowhi * 68 + n]     = accO[ni][2];
            Osm[rowhi * 68 + n + 1] = accO[ni][3];
        }
    }
    __syncthreads();
    if (half == 0) {
        float izlo = 1.f / sumlo, izhi = 1.f / sumhi;
        #pragma unroll
        for (int ni = 0; ni < 8; ni++) {
            int n = ni * 8 + 2 * cq;
            int colg = DMODEL + hh * HD + n;
            *(uint32_t*)(catb + (size_t)(b * SEQ + q0 + rowlo) * (2 * DMODEL) + colg) =
                bf16pack((accO[ni][0] + Osm[rowlo * 68 + n]) * izlo,
                         (accO[ni][1] + Osm[rowlo * 68 + n + 1]) * izlo);
            *(uint32_t*)(catb + (size_t)(b * SEQ + q0 + rowhi) * (2 * DMODEL) + colg) =
                bf16pack((accO[ni][2] + Osm[rowhi * 68 + n]) * izhi,
                         (accO[ni][3] + Osm[rowhi * 68 + n + 1]) * izhi);
        }
    }
}

// ---------------------------------- launch -----------------------------------
extern "C" void kernel_launch(void* const* d_in, const int* in_sizes, int n_in,
                              void* d_out, int out_size) {
    const float* x      = (const float*)d_in[0];
    const float* norm_w = (const float*)d_in[1];
    const float* Wq     = (const float*)d_in[2];
    const float* Wk     = (const float*)d_in[3];
    const float* Wv     = (const float*)d_in[4];
    const float* Wqf    = (const float*)d_in[5];
    const float* Wkf    = (const float*)d_in[6];
    const float* Wout   = (const float*)d_in[7];
    float* out = (float*)d_out;

    __nv_bfloat16 *hb, *wqt, *wkt, *wvt, *woutt, *catb, *qb, *kb, *vb;
    float *ckv2;
    uint32_t* ckvb;
    cudaGetSymbolAddress((void**)&hb,    g_hb);
    cudaGetSymbolAddress((void**)&wqt,   g_wqt);
    cudaGetSymbolAddress((void**)&wkt,   g_wkt);
    cudaGetSymbolAddress((void**)&wvt,   g_wvt);
    cudaGetSymbolAddress((void**)&woutt, g_woutt);
    cudaGetSymbolAddress((void**)&catb,  g_catb);
    cudaGetSymbolAddress((void**)&qb,    g_qb);
    cudaGetSymbolAddress((void**)&kb,    g_kb);
    cudaGetSymbolAddress((void**)&vb,    g_vb);
    cudaGetSymbolAddress((void**)&ckv2,  g_ckv2);
    cudaGetSymbolAddress((void**)&ckvb,  g_ckvb);

    const int smemG   = NSTAGEB * (ASB_ELE + BSB_ELE) * 4;              // 81920
    const int smemKV  = (160 * 36 + 72 * 36) * 4;                       // 33408
    const int smemLin = (80 * 132 * 2 + 80 * 88) * 4;                   // 112640
    const int smemSWA = (64 * 68 + 64 * 132 + 128 * 68 + 128 * 68) * 4 + 256 * 4;

    static cudaStream_t s2 = nullptr;
    static cudaEvent_t ev_root = nullptr, ev_w3 = nullptr, ev_fork = nullptr, ev_join = nullptr;
    static bool attrs_set = false;
    if (!attrs_set) {
        cudaFuncSetAttribute(gemmb,       cudaFuncAttributeMaxDynamicSharedMemorySize, smemG);
        cudaFuncSetAttribute(gemmb_qkv,   cudaFuncAttributeMaxDynamicSharedMemorySize, smemG);
        cudaFuncSetAttribute(chunk_kv_v6, cudaFuncAttributeMaxDynamicSharedMemorySize, smemKV);
        cudaFuncSetAttribute(lin_attn_v6, cudaFuncAttributeMaxDynamicSharedMemorySize, smemLin);
        cudaFuncSetAttribute(swa_v5,      cudaFuncAttributeMaxDynamicSharedMemorySize, smemSWA);
        cudaStreamCreateWithFlags(&s2, cudaStreamNonBlocking);
        cudaEventCreateWithFlags(&ev_root, cudaEventDisableTiming);
        cudaEventCreateWithFlags(&ev_w3,   cudaEventDisableTiming);
        cudaEventCreateWithFlags(&ev_fork, cudaEventDisableTiming);
        cudaEventCreateWithFlags(&ev_join, cudaEventDisableTiming);
        attrs_set = true;
    }

    // fork s2 from the capture-origin stream BEFORE any s2 work
    cudaEventRecord(ev_root, 0);
    cudaStreamWaitEvent(s2, ev_root, 0);

    // QKV weight transposes gate the QKV GEMM; Wout transpose deferred
    transpose_bf16<<<dim3(32, 32), 256, 0, s2>>>(Wq, wqt, DMODEL, DMODEL);
    transpose_bf16<<<dim3(32, 32), 256, 0, s2>>>(Wk, wkt, DMODEL, DMODEL);
    transpose_bf16<<<dim3(32, 32), 256, 0, s2>>>(Wv, wvt, DMODEL, DMODEL);
    cudaEventRecord(ev_w3, s2);
    // Wout transpose overlaps the QKV GEMM (ordered before gemm_win on s2)
    transpose_bf16<<<dim3(32, 64), 256, 0, s2>>>(Wout, woutt, 2 * DMODEL, DMODEL);

    rmsnorm_kernel<<<ROWS, 256>>>(x, norm_w, hb);
    cudaStreamWaitEvent(0, ev_w3, 0);

    gemmb_qkv<<<dim3(DMODEL / 128, ROWS / 128, 3), 256, smemG>>>(hb, wqt, wkt, wvt, qb, kb, vb);

    // fork: SWA + win-half output GEMM run concurrently with the lin-attn chain
    cudaEventRecord(ev_fork, 0);
    cudaStreamWaitEvent(s2, ev_fork, 0);
    swa_v5<<<dim3(SEQ / 64, NH, BATCH), 256, smemSWA, s2>>>(qb, kb, vb, catb);
    // out = x + win @ Wout_bot  (A = cat win half, lda 2048; Bt = woutt k-offset 1024)
    gemmb<<<dim3(DMODEL / 128, ROWS / 128), 256, smemG, s2>>>(
        catb + DMODEL, woutt + DMODEL, out, x, DMODEL, DMODEL, 2 * DMODEL, 2 * DMODEL);
    cudaEventRecord(ev_join, s2);

    chunk_kv_v6<<<BATCH * NH * NCHUNK * 2, 320, smemKV>>>(kb, vb, Wkf, ckv2);
    prefix_kv_v4<<<(32 * FPH * 72 + 255) / 256, 256>>>(ckv2, ckvb);
    lin_attn_v6<<<BATCH * NH * NCHUNK, 256, smemLin>>>(qb, kb, vb, Wqf, Wkf, ckvb, catb);

    cudaStreamWaitEvent(0, ev_join, 0);

    // out += lin @ Wout_top  (residual = out, per-thread read-own-then-write)
    gemmb<<<dim3(DMODEL / 128, ROWS / 128), 256, smemG>>>(
        catb, woutt, out, out, DMODEL, DMODEL, 2 * DMODEL, 2 * DMODEL);
}